// round 1
// baseline (speedup 1.0000x reference)
#include <cuda_runtime.h>
#include <cstdint>

#define B_ 8
#define L_ 1024
#define C_ 512
#define H_ 8
#define D_ 64

// ---------------- scratch (static device allocations; no cudaMalloc) --------
__device__ float g_q[B_*H_*L_*D_];     // 16MB, [B][H][L][D], pre-scaled by 1/sqrt(D)
__device__ float g_k[B_*H_*L_*D_];     // 16MB
__device__ float g_v[B_*H_*L_*D_];     // 16MB
__device__ float g_ao[B_*L_*C_];       // 16MB attention output [B][L][H*D]
__device__ unsigned g_adjbits[B_*L_*(L_/32)];   // 1MB row bitmasks of adj_local
__device__ unsigned g_distbits[B_*L_*(L_/32)];  // 1MB row bitmasks of distance>0
__device__ unsigned char g_mask[(size_t)B_*L_*L_]; // 8MB 5-bit masks

// ---------------- 1. bit-pack adj_local and distance>0 ----------------------
__global__ void pack_kernel(const float* __restrict__ adj,
                            const float* __restrict__ dist) {
    unsigned e = blockIdx.x * 256u + threadIdx.x;   // element index in [0, B*L*L)
    unsigned j = e & (L_ - 1u);
    unsigned i = (e >> 10) & (L_ - 1u);
    bool ab = (adj[e] != 0.0f) && (i != 0u) && (j != 0u);  // has_cls zeroing
    unsigned aw = __ballot_sync(0xffffffffu, ab);
    bool db = dist[e] > 0.0f;
    unsigned dw = __ballot_sync(0xffffffffu, db);
    if ((threadIdx.x & 31u) == 0u) {
        g_adjbits[e >> 5]  = aw;
        g_distbits[e >> 5] = dw;
    }
}

// ---------------- 2. build 5-bit mask per (b,i,j) ---------------------------
// bit0 fwd, bit1 bwd, bit2 dist_fwd, bit3 dist_bwd, bit4 struct
__global__ void mask_kernel() {
    const int b  = blockIdx.z;
    const int i0 = blockIdx.y * 32;
    const int j0 = blockIdx.x * 32;
    __shared__ unsigned Ai[32][33];
    __shared__ unsigned Aj[32][33];
    const int t = threadIdx.x;  // 256 threads
#pragma unroll
    for (int k = 0; k < 4; k++) {
        int pos = t + k * 256;
        int r = pos >> 5, w = pos & 31;
        Ai[r][w] = g_adjbits[((b << 10) + i0 + r) * 32 + w];
        Aj[r][w] = g_adjbits[((b << 10) + j0 + r) * 32 + w];
    }
    __syncthreads();
    const int il = t >> 3;          // 0..31 (i within tile)
    const int jb = (t & 7) << 2;    // 0,4,...,28 (j group of 4)
    const int ig = i0 + il;
    const unsigned di = g_distbits[((b << 10) + ig) * 32 + (j0 >> 5)];
    unsigned sbits = 0u;
    for (int w = 0; w < 32; w++) {
        unsigned ai = Ai[il][w];
#pragma unroll
        for (int jj = 0; jj < 4; jj++)
            if (ai & Aj[jb + jj][w]) sbits |= (1u << jj);
        if (sbits == 0xFu) break;   // early exit (dense adj hits this fast)
    }
    unsigned word = 0u;
#pragma unroll
    for (int jj = 0; jj < 4; jj++) {
        int jl = jb + jj;
        unsigned fwd = (Ai[il][j0 >> 5] >> jl) & 1u;
        unsigned bwd = (Aj[jl][i0 >> 5] >> il) & 1u;
        unsigned dfw = (di >> jl) & 1u;
        unsigned dbw = (g_distbits[((b << 10) + j0 + jl) * 32 + (i0 >> 5)] >> il) & 1u;
        unsigned st  = (sbits >> jj) & 1u;
        unsigned mb  = fwd | (bwd << 1) | (dfw << 2) | (dbw << 3) | (st << 4);
        word |= mb << (8 * jj);
    }
    *reinterpret_cast<unsigned*>(g_mask + (((size_t)((b << 10) + ig)) << 10) + j0 + jb) = word;
}

// ---------------- 3. qkv GEMM: x[8192,512] @ w_qkv[512,1536] ----------------
// 128x64 block tile, 256 threads, 8x4 micro-tile, scatter epilogue to q/k/v.
__global__ void qkv_gemm(const float* __restrict__ A, const float* __restrict__ Bm) {
    const int n0 = blockIdx.x * 64;
    const int m0 = blockIdx.y * 128;
    __shared__ float As[16][128];
    __shared__ float Bs[16][64];
    const int t  = threadIdx.x;
    const int tx = t & 15, ty = t >> 4;
    float acc[8][4];
#pragma unroll
    for (int r = 0; r < 8; r++)
#pragma unroll
        for (int c = 0; c < 4; c++) acc[r][c] = 0.0f;

    for (int k0 = 0; k0 < 512; k0 += 16) {
#pragma unroll
        for (int i = 0; i < 2; i++) {
            int pos = t + i * 256;
            int row = pos >> 2, k4 = (pos & 3) << 2;
            float4 a = *reinterpret_cast<const float4*>(A + (size_t)(m0 + row) * 512 + k0 + k4);
            As[k4 + 0][row] = a.x; As[k4 + 1][row] = a.y;
            As[k4 + 2][row] = a.z; As[k4 + 3][row] = a.w;
        }
        {
            int krow = t >> 4, n4 = (t & 15) << 2;
            *reinterpret_cast<float4*>(&Bs[krow][n4]) =
                *reinterpret_cast<const float4*>(Bm + (size_t)(k0 + krow) * 1536 + n0 + n4);
        }
        __syncthreads();
#pragma unroll
        for (int kk = 0; kk < 16; kk++) {
            float av[8], bv[4];
#pragma unroll
            for (int r = 0; r < 8; r++) av[r] = As[kk][ty * 8 + r];
            float4 b4 = *reinterpret_cast<const float4*>(&Bs[kk][tx * 4]);
            bv[0] = b4.x; bv[1] = b4.y; bv[2] = b4.z; bv[3] = b4.w;
#pragma unroll
            for (int r = 0; r < 8; r++)
#pragma unroll
                for (int c = 0; c < 4; c++) acc[r][c] = fmaf(av[r], bv[c], acc[r][c]);
        }
        __syncthreads();
    }
    // epilogue: n0 block spans a single (part, head)
    const int part = n0 >> 9;
    const int h    = (n0 & 511) >> 6;
    float* base = (part == 0) ? g_q : (part == 1) ? g_k : g_v;
    const float scale = (part == 0) ? 0.125f : 1.0f;   // q /= sqrt(64)
#pragma unroll
    for (int r = 0; r < 8; r++) {
        int row = m0 + ty * 8 + r;
        int bb = row >> 10, ll = row & 1023;
        float4 o;
        o.x = acc[r][0] * scale; o.y = acc[r][1] * scale;
        o.z = acc[r][2] * scale; o.w = acc[r][3] * scale;
        *reinterpret_cast<float4*>(base + ((size_t)((bb * H_ + h) * L_ + ll)) * 64 + tx * 4) = o;
    }
}

// ---------------- 4. flash attention (fp32) ---------------------------------
// block = (b, h, 64 q-rows), 128 threads (16x8), tiles of 64 kv-rows.
__global__ void __launch_bounds__(128) attn_kernel(const float* __restrict__ gamma) {
    const int b  = blockIdx.z;
    const int h  = blockIdx.y;
    const int i0 = blockIdx.x * 64;
    const int t  = threadIdx.x;
    const int tx = t & 15, ty = t >> 4;
    const int lane = t & 31;

    __shared__ float Qs[64 * 64];  // Q^T swizzled: [d][row^ (d&28)]
    __shared__ float KP[64 * 64];  // K^T swizzled, then P (row-major)
    __shared__ float Vs[64 * 64];  // [j][d]

    // per-lane bias table entry: table[m] = sum_k gamma[h][k]*bit_k(m), m = lane
    float tv = 0.0f;
#pragma unroll
    for (int kk = 0; kk < 5; kk++)
        if ((lane >> kk) & 1) tv += gamma[h * 5 + kk];

    const float* qbase = g_q + ((size_t)(b * H_ + h) * L_ + i0) * 64;
    const float* kbase = g_k + ((size_t)(b * H_ + h) * L_) * 64;
    const float* vbase = g_v + ((size_t)(b * H_ + h) * L_) * 64;
    const unsigned char* mbase = g_mask + (size_t)b * L_ * L_;

    // load Q tile transposed + swizzled
#pragma unroll
    for (int i = 0; i < 8; i++) {
        int pos = t + i * 128;
        int row = pos >> 4, c4 = (pos & 15) * 4;
        float4 v = *reinterpret_cast<const float4*>(qbase + row * 64 + c4);
        Qs[(c4 + 0) * 64 + (row ^ ((c4 + 0) & 28))] = v.x;
        Qs[(c4 + 1) * 64 + (row ^ ((c4 + 1) & 28))] = v.y;
        Qs[(c4 + 2) * 64 + (row ^ ((c4 + 2) & 28))] = v.z;
        Qs[(c4 + 3) * 64 + (row ^ ((c4 + 3) & 28))] = v.w;
    }

    float m[8], l[8], O[8][4];
#pragma unroll
    for (int r = 0; r < 8; r++) {
        m[r] = -1e30f; l[r] = 0.0f;
#pragma unroll
        for (int c = 0; c < 4; c++) O[r][c] = 0.0f;
    }

    for (int j0 = 0; j0 < L_; j0 += 64) {
        // load K^T (swizzled) and V
#pragma unroll
        for (int i = 0; i < 8; i++) {
            int pos = t + i * 128;
            int row = pos >> 4, c4 = (pos & 15) * 4;
            float4 kv = *reinterpret_cast<const float4*>(kbase + (size_t)(j0 + row) * 64 + c4);
            KP[(c4 + 0) * 64 + (row ^ ((c4 + 0) & 28))] = kv.x;
            KP[(c4 + 1) * 64 + (row ^ ((c4 + 1) & 28))] = kv.y;
            KP[(c4 + 2) * 64 + (row ^ ((c4 + 2) & 28))] = kv.z;
            KP[(c4 + 3) * 64 + (row ^ ((c4 + 3) & 28))] = kv.w;
            float4 vv = *reinterpret_cast<const float4*>(vbase + (size_t)(j0 + row) * 64 + c4);
            *reinterpret_cast<float4*>(Vs + row * 64 + c4) = vv;
        }
        __syncthreads();

        // S = Q K^T
        float S[8][4];
#pragma unroll
        for (int r = 0; r < 8; r++)
#pragma unroll
            for (int c = 0; c < 4; c++) S[r][c] = 0.0f;
#pragma unroll 4
        for (int d = 0; d < 64; d++) {
            int sw = d & 28;
            float qr[8];
#pragma unroll
            for (int r = 0; r < 8; r++) qr[r] = Qs[d * 64 + ((ty * 8 + r) ^ sw)];
            float4 k4 = *reinterpret_cast<const float4*>(&KP[d * 64 + ((tx * 4) ^ sw)]);
            float kc[4] = {k4.x, k4.y, k4.z, k4.w};
#pragma unroll
            for (int r = 0; r < 8; r++)
#pragma unroll
                for (int c = 0; c < 4; c++) S[r][c] = fmaf(qr[r], kc[c], S[r][c]);
        }
        __syncthreads();   // all K reads done before P overwrites KP

        // bias + online softmax
#pragma unroll
        for (int r = 0; r < 8; r++) {
            int ig = i0 + ty * 8 + r;
            unsigned mm = *reinterpret_cast<const unsigned*>(
                mbase + (size_t)ig * L_ + j0 + tx * 4);
#pragma unroll
            for (int c = 0; c < 4; c++)
                S[r][c] += __shfl_sync(0xffffffffu, tv, (mm >> (8 * c)) & 31u);

            float mx = fmaxf(fmaxf(S[r][0], S[r][1]), fmaxf(S[r][2], S[r][3]));
#pragma unroll
            for (int o = 1; o < 16; o <<= 1)
                mx = fmaxf(mx, __shfl_xor_sync(0xffffffffu, mx, o));
            float mn  = fmaxf(m[r], mx);
            float fac = __expf(m[r] - mn);
            m[r] = mn;
            float rs = 0.0f;
#pragma unroll
            for (int c = 0; c < 4; c++) { S[r][c] = __expf(S[r][c] - mn); rs += S[r][c]; }
#pragma unroll
            for (int o = 1; o < 16; o <<= 1)
                rs += __shfl_xor_sync(0xffffffffu, rs, o);
            l[r] = l[r] * fac + rs;
#pragma unroll
            for (int c = 0; c < 4; c++) O[r][c] *= fac;
            // store P row chunk (row-major, vectorized)
            float4 p4; p4.x = S[r][0]; p4.y = S[r][1]; p4.z = S[r][2]; p4.w = S[r][3];
            *reinterpret_cast<float4*>(&KP[(ty * 8 + r) * 64 + tx * 4]) = p4;
        }
        __syncthreads();

        // O += P V
#pragma unroll 4
        for (int j = 0; j < 64; j++) {
            float4 v4 = *reinterpret_cast<const float4*>(&Vs[j * 64 + tx * 4]);
            float vv[4] = {v4.x, v4.y, v4.z, v4.w};
#pragma unroll
            for (int r = 0; r < 8; r++) {
                float p = KP[(ty * 8 + r) * 64 + j];
#pragma unroll
                for (int c = 0; c < 4; c++) O[r][c] = fmaf(p, vv[c], O[r][c]);
            }
        }
        __syncthreads();   // before next tile's K/V overwrite
    }

    // epilogue: normalize and store to [B][L][H*D]
#pragma unroll
    for (int r = 0; r < 8; r++) {
        float inv = 1.0f / l[r];
        int row = i0 + ty * 8 + r;
        float4 o;
        o.x = O[r][0] * inv; o.y = O[r][1] * inv;
        o.z = O[r][2] * inv; o.w = O[r][3] * inv;
        *reinterpret_cast<float4*>(g_ao + ((size_t)(b * L_) + row) * C_ + h * 64 + tx * 4) = o;
    }
}

// ---------------- 5. proj GEMM: ao[8192,512] @ w_proj[512,512] -> out -------
__global__ void proj_gemm(const float* __restrict__ Bm, float* __restrict__ out) {
    const int n0 = blockIdx.x * 64;
    const int m0 = blockIdx.y * 128;
    __shared__ float As[16][128];
    __shared__ float Bs[16][64];
    const int t  = threadIdx.x;
    const int tx = t & 15, ty = t >> 4;
    float acc[8][4];
#pragma unroll
    for (int r = 0; r < 8; r++)
#pragma unroll
        for (int c = 0; c < 4; c++) acc[r][c] = 0.0f;

    for (int k0 = 0; k0 < 512; k0 += 16) {
#pragma unroll
        for (int i = 0; i < 2; i++) {
            int pos = t + i * 256;
            int row = pos >> 2, k4 = (pos & 3) << 2;
            float4 a = *reinterpret_cast<const float4*>(g_ao + (size_t)(m0 + row) * 512 + k0 + k4);
            As[k4 + 0][row] = a.x; As[k4 + 1][row] = a.y;
            As[k4 + 2][row] = a.z; As[k4 + 3][row] = a.w;
        }
        {
            int krow = t >> 4, n4 = (t & 15) << 2;
            *reinterpret_cast<float4*>(&Bs[krow][n4]) =
                *reinterpret_cast<const float4*>(Bm + (size_t)(k0 + krow) * 512 + n0 + n4);
        }
        __syncthreads();
#pragma unroll
        for (int kk = 0; kk < 16; kk++) {
            float av[8], bv[4];
#pragma unroll
            for (int r = 0; r < 8; r++) av[r] = As[kk][ty * 8 + r];
            float4 b4 = *reinterpret_cast<const float4*>(&Bs[kk][tx * 4]);
            bv[0] = b4.x; bv[1] = b4.y; bv[2] = b4.z; bv[3] = b4.w;
#pragma unroll
            for (int r = 0; r < 8; r++)
#pragma unroll
                for (int c = 0; c < 4; c++) acc[r][c] = fmaf(av[r], bv[c], acc[r][c]);
        }
        __syncthreads();
    }
#pragma unroll
    for (int r = 0; r < 8; r++) {
        int row = m0 + ty * 8 + r;
        float4 o; o.x = acc[r][0]; o.y = acc[r][1]; o.z = acc[r][2]; o.w = acc[r][3];
        *reinterpret_cast<float4*>(out + (size_t)row * 512 + n0 + tx * 4) = o;
    }
}

// ---------------- launch ----------------------------------------------------
extern "C" void kernel_launch(void* const* d_in, const int* in_sizes, int n_in,
                              void* d_out, int out_size) {
    const float* x      = (const float*)d_in[0];
    const float* adj    = (const float*)d_in[1];
    const float* dist   = (const float*)d_in[2];
    const float* w_qkv  = (const float*)d_in[3];
    const float* w_proj = (const float*)d_in[4];
    const float* gamma  = (const float*)d_in[5];
    float* out = (float*)d_out;

    pack_kernel<<<(B_ * L_ * L_) / 256, 256>>>(adj, dist);
    mask_kernel<<<dim3(L_ / 32, L_ / 32, B_), 256>>>();
    qkv_gemm<<<dim3(24, 64), 256>>>(x, w_qkv);
    attn_kernel<<<dim3(L_ / 64, H_, B_), 128>>>(gamma);
    proj_gemm<<<dim3(8, 64), 256>>>(w_proj, out);
}

// round 2
// speedup vs baseline: 1.0010x; 1.0010x over previous
#include <cuda_runtime.h>
#include <cstdint>

#define B_ 8
#define L_ 1024
#define C_ 512
#define H_ 8
#define D_ 64

// ---------------- scratch (static device allocations; no cudaMalloc) --------
__device__ float g_q[B_*H_*L_*D_];     // 16MB, [B][H][L][D], pre-scaled by 1/sqrt(D)
__device__ float g_k[B_*H_*L_*D_];     // 16MB
__device__ float g_v[B_*H_*L_*D_];     // 16MB
__device__ float g_ao[B_*L_*C_];       // 16MB attention output [B][L][H*D]
__device__ unsigned g_adjbits[B_*L_*(L_/32)];   // 1MB row bitmasks of adj_local
__device__ unsigned g_distbits[B_*L_*(L_/32)];  // 1MB row bitmasks of distance>0
__device__ unsigned char g_mask[(size_t)B_*L_*L_]; // 8MB 5-bit masks

// ---------------- 1. bit-pack adj_local and distance>0 ----------------------
__global__ void pack_kernel(const float* __restrict__ adj,
                            const float* __restrict__ dist) {
    unsigned e = blockIdx.x * 256u + threadIdx.x;   // element index in [0, B*L*L)
    unsigned j = e & (L_ - 1u);
    unsigned i = (e >> 10) & (L_ - 1u);
    bool ab = (adj[e] != 0.0f) && (i != 0u) && (j != 0u);  // has_cls zeroing
    unsigned aw = __ballot_sync(0xffffffffu, ab);
    bool db = dist[e] > 0.0f;
    unsigned dw = __ballot_sync(0xffffffffu, db);
    if ((threadIdx.x & 31u) == 0u) {
        g_adjbits[e >> 5]  = aw;
        g_distbits[e >> 5] = dw;
    }
}

// ---------------- 2. build 5-bit mask per (b,i,j) ---------------------------
// bit0 fwd, bit1 bwd, bit2 dist_fwd, bit3 dist_bwd, bit4 struct
__global__ void mask_kernel() {
    const int b  = blockIdx.z;
    const int i0 = blockIdx.y * 32;
    const int j0 = blockIdx.x * 32;
    __shared__ unsigned Ai[32][33];
    __shared__ unsigned Aj[32][33];
    const int t = threadIdx.x;  // 256 threads
#pragma unroll
    for (int k = 0; k < 4; k++) {
        int pos = t + k * 256;
        int r = pos >> 5, w = pos & 31;
        Ai[r][w] = g_adjbits[((b << 10) + i0 + r) * 32 + w];
        Aj[r][w] = g_adjbits[((b << 10) + j0 + r) * 32 + w];
    }
    __syncthreads();
    const int il = t >> 3;          // 0..31 (i within tile)
    const int jb = (t & 7) << 2;    // 0,4,...,28 (j group of 4)
    const int ig = i0 + il;
    const unsigned di = g_distbits[((b << 10) + ig) * 32 + (j0 >> 5)];
    unsigned sbits = 0u;
    for (int w = 0; w < 32; w++) {
        unsigned ai = Ai[il][w];
#pragma unroll
        for (int jj = 0; jj < 4; jj++)
            if (ai & Aj[jb + jj][w]) sbits |= (1u << jj);
        if (sbits == 0xFu) break;   // early exit (dense adj hits this fast)
    }
    unsigned word = 0u;
#pragma unroll
    for (int jj = 0; jj < 4; jj++) {
        int jl = jb + jj;
        unsigned fwd = (Ai[il][j0 >> 5] >> jl) & 1u;
        unsigned bwd = (Aj[jl][i0 >> 5] >> il) & 1u;
        unsigned dfw = (di >> jl) & 1u;
        unsigned dbw = (g_distbits[((b << 10) + j0 + jl) * 32 + (i0 >> 5)] >> il) & 1u;
        unsigned st  = (sbits >> jj) & 1u;
        unsigned mb  = fwd | (bwd << 1) | (dfw << 2) | (dbw << 3) | (st << 4);
        word |= mb << (8 * jj);
    }
    *reinterpret_cast<unsigned*>(g_mask + (((size_t)((b << 10) + ig)) << 10) + j0 + jb) = word;
}

// ---------------- 3. qkv GEMM: x[8192,512] @ w_qkv[512,1536] ----------------
// 128x64 block tile, 256 threads, 8x4 micro-tile, scatter epilogue to q/k/v.
__global__ void qkv_gemm(const float* __restrict__ A, const float* __restrict__ Bm) {
    const int n0 = blockIdx.x * 64;
    const int m0 = blockIdx.y * 128;
    __shared__ float As[16][128];
    __shared__ float Bs[16][64];
    const int t  = threadIdx.x;
    const int tx = t & 15, ty = t >> 4;
    float acc[8][4];
#pragma unroll
    for (int r = 0; r < 8; r++)
#pragma unroll
        for (int c = 0; c < 4; c++) acc[r][c] = 0.0f;

    for (int k0 = 0; k0 < 512; k0 += 16) {
#pragma unroll
        for (int i = 0; i < 2; i++) {
            int pos = t + i * 256;
            int row = pos >> 2, k4 = (pos & 3) << 2;
            float4 a = *reinterpret_cast<const float4*>(A + (size_t)(m0 + row) * 512 + k0 + k4);
            As[k4 + 0][row] = a.x; As[k4 + 1][row] = a.y;
            As[k4 + 2][row] = a.z; As[k4 + 3][row] = a.w;
        }
        {
            int krow = t >> 4, n4 = (t & 15) << 2;
            *reinterpret_cast<float4*>(&Bs[krow][n4]) =
                *reinterpret_cast<const float4*>(Bm + (size_t)(k0 + krow) * 1536 + n0 + n4);
        }
        __syncthreads();
#pragma unroll
        for (int kk = 0; kk < 16; kk++) {
            float av[8], bv[4];
#pragma unroll
            for (int r = 0; r < 8; r++) av[r] = As[kk][ty * 8 + r];
            float4 b4 = *reinterpret_cast<const float4*>(&Bs[kk][tx * 4]);
            bv[0] = b4.x; bv[1] = b4.y; bv[2] = b4.z; bv[3] = b4.w;
#pragma unroll
            for (int r = 0; r < 8; r++)
#pragma unroll
                for (int c = 0; c < 4; c++) acc[r][c] = fmaf(av[r], bv[c], acc[r][c]);
        }
        __syncthreads();
    }
    // epilogue: n0 block spans a single (part, head)
    const int part = n0 >> 9;
    const int h    = (n0 & 511) >> 6;
    float* base = (part == 0) ? g_q : (part == 1) ? g_k : g_v;
    const float scale = (part == 0) ? 0.125f : 1.0f;   // q /= sqrt(64)
#pragma unroll
    for (int r = 0; r < 8; r++) {
        int row = m0 + ty * 8 + r;
        int bb = row >> 10, ll = row & 1023;
        float4 o;
        o.x = acc[r][0] * scale; o.y = acc[r][1] * scale;
        o.z = acc[r][2] * scale; o.w = acc[r][3] * scale;
        *reinterpret_cast<float4*>(base + ((size_t)((bb * H_ + h) * L_ + ll)) * 64 + tx * 4) = o;
    }
}

// ---------------- 4. flash attention (fp32) ---------------------------------
// block = (b, h, 64 q-rows), 128 threads (16x8), tiles of 64 kv-rows.
__global__ void __launch_bounds__(128) attn_kernel(const float* __restrict__ gamma) {
    const int b  = blockIdx.z;
    const int h  = blockIdx.y;
    const int i0 = blockIdx.x * 64;
    const int t  = threadIdx.x;
    const int tx = t & 15, ty = t >> 4;
    const int lane = t & 31;

    __shared__ float Qs[64 * 64];  // Q^T swizzled: [d][row^ (d&28)]
    __shared__ float KP[64 * 64];  // K^T swizzled, then P (row-major)
    __shared__ float Vs[64 * 64];  // [j][d]

    // per-lane bias table entry: table[m] = sum_k gamma[h][k]*bit_k(m), m = lane
    float tv = 0.0f;
#pragma unroll
    for (int kk = 0; kk < 5; kk++)
        if ((lane >> kk) & 1) tv += gamma[h * 5 + kk];

    const float* qbase = g_q + ((size_t)(b * H_ + h) * L_ + i0) * 64;
    const float* kbase = g_k + ((size_t)(b * H_ + h) * L_) * 64;
    const float* vbase = g_v + ((size_t)(b * H_ + h) * L_) * 64;
    const unsigned char* mbase = g_mask + (size_t)b * L_ * L_;

    // load Q tile transposed + swizzled
#pragma unroll
    for (int i = 0; i < 8; i++) {
        int pos = t + i * 128;
        int row = pos >> 4, c4 = (pos & 15) * 4;
        float4 v = *reinterpret_cast<const float4*>(qbase + row * 64 + c4);
        Qs[(c4 + 0) * 64 + (row ^ ((c4 + 0) & 28))] = v.x;
        Qs[(c4 + 1) * 64 + (row ^ ((c4 + 1) & 28))] = v.y;
        Qs[(c4 + 2) * 64 + (row ^ ((c4 + 2) & 28))] = v.z;
        Qs[(c4 + 3) * 64 + (row ^ ((c4 + 3) & 28))] = v.w;
    }

    float m[8], l[8], O[8][4];
#pragma unroll
    for (int r = 0; r < 8; r++) {
        m[r] = -1e30f; l[r] = 0.0f;
#pragma unroll
        for (int c = 0; c < 4; c++) O[r][c] = 0.0f;
    }

    for (int j0 = 0; j0 < L_; j0 += 64) {
        // load K^T (swizzled) and V
#pragma unroll
        for (int i = 0; i < 8; i++) {
            int pos = t + i * 128;
            int row = pos >> 4, c4 = (pos & 15) * 4;
            float4 kv = *reinterpret_cast<const float4*>(kbase + (size_t)(j0 + row) * 64 + c4);
            KP[(c4 + 0) * 64 + (row ^ ((c4 + 0) & 28))] = kv.x;
            KP[(c4 + 1) * 64 + (row ^ ((c4 + 1) & 28))] = kv.y;
            KP[(c4 + 2) * 64 + (row ^ ((c4 + 2) & 28))] = kv.z;
            KP[(c4 + 3) * 64 + (row ^ ((c4 + 3) & 28))] = kv.w;
            float4 vv = *reinterpret_cast<const float4*>(vbase + (size_t)(j0 + row) * 64 + c4);
            *reinterpret_cast<float4*>(Vs + row * 64 + c4) = vv;
        }
        __syncthreads();

        // S = Q K^T
        float S[8][4];
#pragma unroll
        for (int r = 0; r < 8; r++)
#pragma unroll
            for (int c = 0; c < 4; c++) S[r][c] = 0.0f;
#pragma unroll 4
        for (int d = 0; d < 64; d++) {
            int sw = d & 28;
            float qr[8];
#pragma unroll
            for (int r = 0; r < 8; r++) qr[r] = Qs[d * 64 + ((ty * 8 + r) ^ sw)];
            float4 k4 = *reinterpret_cast<const float4*>(&KP[d * 64 + ((tx * 4) ^ sw)]);
            float kc[4] = {k4.x, k4.y, k4.z, k4.w};
#pragma unroll
            for (int r = 0; r < 8; r++)
#pragma unroll
                for (int c = 0; c < 4; c++) S[r][c] = fmaf(qr[r], kc[c], S[r][c]);
        }
        __syncthreads();   // all K reads done before P overwrites KP

        // bias + online softmax
#pragma unroll
        for (int r = 0; r < 8; r++) {
            int ig = i0 + ty * 8 + r;
            unsigned mm = *reinterpret_cast<const unsigned*>(
                mbase + (size_t)ig * L_ + j0 + tx * 4);
#pragma unroll
            for (int c = 0; c < 4; c++)
                S[r][c] += __shfl_sync(0xffffffffu, tv, (mm >> (8 * c)) & 31u);

            float mx = fmaxf(fmaxf(S[r][0], S[r][1]), fmaxf(S[r][2], S[r][3]));
#pragma unroll
            for (int o = 1; o < 16; o <<= 1)
                mx = fmaxf(mx, __shfl_xor_sync(0xffffffffu, mx, o));
            float mn  = fmaxf(m[r], mx);
            float fac = __expf(m[r] - mn);
            m[r] = mn;
            float rs = 0.0f;
#pragma unroll
            for (int c = 0; c < 4; c++) { S[r][c] = __expf(S[r][c] - mn); rs += S[r][c]; }
#pragma unroll
            for (int o = 1; o < 16; o <<= 1)
                rs += __shfl_xor_sync(0xffffffffu, rs, o);
            l[r] = l[r] * fac + rs;
#pragma unroll
            for (int c = 0; c < 4; c++) O[r][c] *= fac;
            // store P row chunk (row-major, vectorized)
            float4 p4; p4.x = S[r][0]; p4.y = S[r][1]; p4.z = S[r][2]; p4.w = S[r][3];
            *reinterpret_cast<float4*>(&KP[(ty * 8 + r) * 64 + tx * 4]) = p4;
        }
        __syncthreads();

        // O += P V
#pragma unroll 4
        for (int j = 0; j < 64; j++) {
            float4 v4 = *reinterpret_cast<const float4*>(&Vs[j * 64 + tx * 4]);
            float vv[4] = {v4.x, v4.y, v4.z, v4.w};
#pragma unroll
            for (int r = 0; r < 8; r++) {
                float p = KP[(ty * 8 + r) * 64 + j];
#pragma unroll
                for (int c = 0; c < 4; c++) O[r][c] = fmaf(p, vv[c], O[r][c]);
            }
        }
        __syncthreads();   // before next tile's K/V overwrite
    }

    // epilogue: normalize and store to [B][L][H*D]
#pragma unroll
    for (int r = 0; r < 8; r++) {
        float inv = 1.0f / l[r];
        int row = i0 + ty * 8 + r;
        float4 o;
        o.x = O[r][0] * inv; o.y = O[r][1] * inv;
        o.z = O[r][2] * inv; o.w = O[r][3] * inv;
        *reinterpret_cast<float4*>(g_ao + ((size_t)(b * L_) + row) * C_ + h * 64 + tx * 4) = o;
    }
}

// ---------------- 5. proj GEMM: ao[8192,512] @ w_proj[512,512] -> out -------
__global__ void proj_gemm(const float* __restrict__ Bm, float* __restrict__ out) {
    const int n0 = blockIdx.x * 64;
    const int m0 = blockIdx.y * 128;
    __shared__ float As[16][128];
    __shared__ float Bs[16][64];
    const int t  = threadIdx.x;
    const int tx = t & 15, ty = t >> 4;
    float acc[8][4];
#pragma unroll
    for (int r = 0; r < 8; r++)
#pragma unroll
        for (int c = 0; c < 4; c++) acc[r][c] = 0.0f;

    for (int k0 = 0; k0 < 512; k0 += 16) {
#pragma unroll
        for (int i = 0; i < 2; i++) {
            int pos = t + i * 256;
            int row = pos >> 2, k4 = (pos & 3) << 2;
            float4 a = *reinterpret_cast<const float4*>(g_ao + (size_t)(m0 + row) * 512 + k0 + k4);
            As[k4 + 0][row] = a.x; As[k4 + 1][row] = a.y;
            As[k4 + 2][row] = a.z; As[k4 + 3][row] = a.w;
        }
        {
            int krow = t >> 4, n4 = (t & 15) << 2;
            *reinterpret_cast<float4*>(&Bs[krow][n4]) =
                *reinterpret_cast<const float4*>(Bm + (size_t)(k0 + krow) * 512 + n0 + n4);
        }
        __syncthreads();
#pragma unroll
        for (int kk = 0; kk < 16; kk++) {
            float av[8], bv[4];
#pragma unroll
            for (int r = 0; r < 8; r++) av[r] = As[kk][ty * 8 + r];
            float4 b4 = *reinterpret_cast<const float4*>(&Bs[kk][tx * 4]);
            bv[0] = b4.x; bv[1] = b4.y; bv[2] = b4.z; bv[3] = b4.w;
#pragma unroll
            for (int r = 0; r < 8; r++)
#pragma unroll
                for (int c = 0; c < 4; c++) acc[r][c] = fmaf(av[r], bv[c], acc[r][c]);
        }
        __syncthreads();
    }
#pragma unroll
    for (int r = 0; r < 8; r++) {
        int row = m0 + ty * 8 + r;
        float4 o; o.x = acc[r][0]; o.y = acc[r][1]; o.z = acc[r][2]; o.w = acc[r][3];
        *reinterpret_cast<float4*>(out + (size_t)row * 512 + n0 + tx * 4) = o;
    }
}

// ---------------- launch ----------------------------------------------------
extern "C" void kernel_launch(void* const* d_in, const int* in_sizes, int n_in,
                              void* d_out, int out_size) {
    const float* x      = (const float*)d_in[0];
    const float* adj    = (const float*)d_in[1];
    const float* dist   = (const float*)d_in[2];
    const float* w_qkv  = (const float*)d_in[3];
    const float* w_proj = (const float*)d_in[4];
    const float* gamma  = (const float*)d_in[5];
    float* out = (float*)d_out;

    pack_kernel<<<(B_ * L_ * L_) / 256, 256>>>(adj, dist);
    mask_kernel<<<dim3(L_ / 32, L_ / 32, B_), 256>>>();
    qkv_gemm<<<dim3(24, 64), 256>>>(x, w_qkv);
    attn_kernel<<<dim3(L_ / 64, H_, B_), 128>>>(gamma);
    proj_gemm<<<dim3(8, 64), 256>>>(w_proj, out);
}

// round 4
// speedup vs baseline: 2.3484x; 2.3462x over previous
#include <cuda_runtime.h>
#include <cuda_bf16.h>
#include <cstdint>

#define B_ 8
#define L_ 1024
#define C_ 512
#define H_ 8
#define D_ 64
#define M_TOT (B_*L_)

// ---------------- static device scratch -------------------------------------
__device__ unsigned g_adjbits[B_*L_*(L_/32)];
__device__ unsigned g_distbits[B_*L_*(L_/32)];
__device__ unsigned char g_mask[(size_t)B_*L_*L_];

__device__ __nv_bfloat16 g_xhi[M_TOT*C_],   g_xlo[M_TOT*C_];
__device__ __nv_bfloat16 g_wqT_hi[3*C_*C_], g_wqT_lo[3*C_*C_];  // [1536][512]
__device__ __nv_bfloat16 g_wpT_hi[C_*C_],   g_wpT_lo[C_*C_];    // [512][512]
__device__ __nv_bfloat16 g_qhi[B_*H_*L_*D_], g_qlo[B_*H_*L_*D_]; // q pre-scaled 1/8
__device__ __nv_bfloat16 g_khi[B_*H_*L_*D_], g_klo[B_*H_*L_*D_];
__device__ __nv_bfloat16 g_vhi[B_*H_*L_*D_], g_vlo[B_*H_*L_*D_];
__device__ __nv_bfloat16 g_aohi[M_TOT*C_],  g_aolo[M_TOT*C_];

// ---------------- helpers -----------------------------------------------------
__device__ __forceinline__ uint32_t smem_u32(const void* p) {
    uint32_t a;
    asm("{ .reg .u64 t; cvta.to.shared.u64 t, %1; cvt.u32.u64 %0, t; }" : "=r"(a) : "l"(p));
    return a;
}
#define SW128(o) ((o) ^ (((o) >> 3) & 0x70))

__device__ __forceinline__ void mma_bf16(float* c, const unsigned* a, const unsigned* b) {
    asm volatile("mma.sync.aligned.m16n8k16.row.col.f32.bf16.bf16.f32 "
        "{%0,%1,%2,%3}, {%4,%5,%6,%7}, {%8,%9}, {%0,%1,%2,%3};"
        : "+f"(c[0]), "+f"(c[1]), "+f"(c[2]), "+f"(c[3])
        : "r"(a[0]), "r"(a[1]), "r"(a[2]), "r"(a[3]), "r"(b[0]), "r"(b[1]));
}
__device__ __forceinline__ void ldm4(unsigned* r, uint32_t a) {
    asm volatile("ldmatrix.sync.aligned.m8n8.x4.shared.b16 {%0,%1,%2,%3}, [%4];"
        : "=r"(r[0]), "=r"(r[1]), "=r"(r[2]), "=r"(r[3]) : "r"(a));
}
__device__ __forceinline__ void ldm4t(unsigned* r, uint32_t a) {
    asm volatile("ldmatrix.sync.aligned.m8n8.x4.trans.shared.b16 {%0,%1,%2,%3}, [%4];"
        : "=r"(r[0]), "=r"(r[1]), "=r"(r[2]), "=r"(r[3]) : "r"(a));
}
// pack (a -> low, b -> high) with residuals
__device__ __forceinline__ void split2(float a, float b, unsigned& h, unsigned& l) {
    __nv_bfloat162 hv = __floats2bfloat162_rn(a, b);
    __nv_bfloat162 lv = __floats2bfloat162_rn(a - __bfloat162float(hv.x),
                                              b - __bfloat162float(hv.y));
    h = *(unsigned*)&hv; l = *(unsigned*)&lv;
}

// ---------------- pack / mask (unchanged, passing) ---------------------------
__global__ void pack_kernel(const float* __restrict__ adj, const float* __restrict__ dist) {
    unsigned e = blockIdx.x * 256u + threadIdx.x;
    unsigned j = e & (L_ - 1u), i = (e >> 10) & (L_ - 1u);
    bool ab = (adj[e] != 0.0f) && (i != 0u) && (j != 0u);
    unsigned aw = __ballot_sync(0xffffffffu, ab);
    unsigned dw = __ballot_sync(0xffffffffu, dist[e] > 0.0f);
    if ((threadIdx.x & 31u) == 0u) { g_adjbits[e >> 5] = aw; g_distbits[e >> 5] = dw; }
}

__global__ void mask_kernel() {
    const int b = blockIdx.z, i0 = blockIdx.y * 32, j0 = blockIdx.x * 32;
    __shared__ unsigned Ai[32][33], Aj[32][33];
    const int t = threadIdx.x;
#pragma unroll
    for (int k = 0; k < 4; k++) {
        int pos = t + k * 256, r = pos >> 5, w = pos & 31;
        Ai[r][w] = g_adjbits[((b << 10) + i0 + r) * 32 + w];
        Aj[r][w] = g_adjbits[((b << 10) + j0 + r) * 32 + w];
    }
    __syncthreads();
    const int il = t >> 3, jb = (t & 7) << 2, ig = i0 + il;
    const unsigned di = g_distbits[((b << 10) + ig) * 32 + (j0 >> 5)];
    unsigned sbits = 0u;
    for (int w = 0; w < 32; w++) {
        unsigned ai = Ai[il][w];
#pragma unroll
        for (int jj = 0; jj < 4; jj++)
            if (ai & Aj[jb + jj][w]) sbits |= (1u << jj);
        if (sbits == 0xFu) break;
    }
    unsigned word = 0u;
#pragma unroll
    for (int jj = 0; jj < 4; jj++) {
        int jl = jb + jj;
        unsigned fwd = (Ai[il][j0 >> 5] >> jl) & 1u;
        unsigned bwd = (Aj[jl][i0 >> 5] >> il) & 1u;
        unsigned dfw = (di >> jl) & 1u;
        unsigned dbw = (g_distbits[((b << 10) + j0 + jl) * 32 + (i0 >> 5)] >> il) & 1u;
        unsigned st = (sbits >> jj) & 1u;
        word |= (fwd | (bwd << 1) | (dfw << 2) | (dbw << 3) | (st << 4)) << (8 * jj);
    }
    *reinterpret_cast<unsigned*>(g_mask + (((size_t)((b << 10) + ig)) << 10) + j0 + jb) = word;
}

// ---------------- splits -------------------------------------------------------
__global__ void split_x(const float* __restrict__ x) {
    int i = blockIdx.x * 256 + threadIdx.x;
    float v = x[i];
    __nv_bfloat16 h = __float2bfloat16(v);
    g_xhi[i] = h; g_xlo[i] = __float2bfloat16(v - __bfloat162float(h));
}
__global__ void split_w(const float* __restrict__ wq, const float* __restrict__ wp) {
    int i = blockIdx.x * 256 + threadIdx.x;
    if (i < 786432) {
        int k = i / 1536, n = i % 1536;
        float v = wq[i];
        __nv_bfloat16 h = __float2bfloat16(v);
        g_wqT_hi[n * 512 + k] = h;
        g_wqT_lo[n * 512 + k] = __float2bfloat16(v - __bfloat162float(h));
    } else {
        int j = i - 786432, k = j / 512, n = j % 512;
        float v = wp[j];
        __nv_bfloat16 h = __float2bfloat16(v);
        g_wpT_hi[n * 512 + k] = h;
        g_wpT_lo[n * 512 + k] = __float2bfloat16(v - __bfloat162float(h));
    }
}

// ---------------- mma.sync GEMM: 128x128 CTA tile, K=512 ----------------------
// smem: Ahi 0, Alo 16K, Bhi 32K, Blo 48K (each 128 rows x 64 bf16, SW128)
#define GDYN (65536 + 1024)
__global__ void __launch_bounds__(256) mm_kernel(int mode, float* __restrict__ out) {
    extern __shared__ char raw[];
    uint32_t rb = smem_u32(raw);
    char* sm = raw + ((1024u - (rb & 1023u)) & 1023u);
    const uint32_t sb = smem_u32(sm);
    const int t = threadIdx.x, lane = t & 31, wid = t >> 5;
    const int wm = wid & 3, wn = wid >> 2;
    const int n0 = blockIdx.x * 128, m0 = blockIdx.y * 128;

    const __nv_bfloat16 *Ahi, *Alo, *Bhi, *Blo;
    if (mode == 0) { Ahi = g_xhi;  Alo = g_xlo;  Bhi = g_wqT_hi; Blo = g_wqT_lo; }
    else           { Ahi = g_aohi; Alo = g_aolo; Bhi = g_wpT_hi; Blo = g_wpT_lo; }

    float C[2][8][4];
#pragma unroll
    for (int m = 0; m < 2; m++)
#pragma unroll
        for (int f = 0; f < 8; f++)
#pragma unroll
            for (int c = 0; c < 4; c++) C[m][f][c] = 0.0f;

    const int a_row = wm * 32 + (lane & 15);
    const int a_k   = (lane >> 4) * 8;
    const int b_row = wn * 64 + ((lane >> 4) << 3) + (lane & 7);
    const int b_k   = ((lane >> 3) & 1) * 8;

    for (int kc = 0; kc < 8; kc++) {
#pragma unroll
        for (int i = 0; i < 4; i++) {
            int pos = t + i * 256, row = pos >> 3, cs = pos & 7;
            unsigned off = SW128((unsigned)(row * 128 + cs * 16));
            size_t ga = (size_t)(m0 + row) * 512 + kc * 64 + cs * 8;
            size_t gb = (size_t)(n0 + row) * 512 + kc * 64 + cs * 8;
            *(uint4*)(sm + off)         = *(const uint4*)(Ahi + ga);
            *(uint4*)(sm + 16384 + off) = *(const uint4*)(Alo + ga);
            *(uint4*)(sm + 32768 + off) = *(const uint4*)(Bhi + gb);
            *(uint4*)(sm + 49152 + off) = *(const uint4*)(Blo + gb);
        }
        __syncthreads();
#pragma unroll
        for (int ks = 0; ks < 4; ks++) {
            unsigned ah[2][4], al[2][4];
#pragma unroll
            for (int mf = 0; mf < 2; mf++) {
                unsigned off = SW128((unsigned)((a_row + mf * 16) * 128 + (a_k + ks * 16) * 2));
                ldm4(ah[mf], sb + off);
                ldm4(al[mf], sb + 16384 + off);
            }
#pragma unroll
            for (int nf4 = 0; nf4 < 4; nf4++) {
                unsigned off = SW128((unsigned)((b_row + nf4 * 16) * 128 + (b_k + ks * 16) * 2));
                unsigned bh[4], bl[4];
                ldm4(bh, sb + 32768 + off);
                ldm4(bl, sb + 49152 + off);
#pragma unroll
                for (int mf = 0; mf < 2; mf++) {
                    mma_bf16(C[mf][2 * nf4], ah[mf], bh);
                    mma_bf16(C[mf][2 * nf4], ah[mf], bl);
                    mma_bf16(C[mf][2 * nf4], al[mf], bh);
                    mma_bf16(C[mf][2 * nf4 + 1], ah[mf], bh + 2);
                    mma_bf16(C[mf][2 * nf4 + 1], ah[mf], bl + 2);
                    mma_bf16(C[mf][2 * nf4 + 1], al[mf], bh + 2);
                }
            }
        }
        __syncthreads();
    }

    const int rq = lane >> 2, q2 = 2 * (lane & 3);
    if (mode == 1) {
#pragma unroll
        for (int mf = 0; mf < 2; mf++)
#pragma unroll
            for (int f = 0; f < 8; f++) {
                int row = m0 + wm * 32 + mf * 16 + rq;
                int col = n0 + wn * 64 + f * 8 + q2;
                float2 v0; v0.x = C[mf][f][0]; v0.y = C[mf][f][1];
                float2 v1; v1.x = C[mf][f][2]; v1.y = C[mf][f][3];
                *(float2*)(out + (size_t)row * 512 + col) = v0;
                *(float2*)(out + (size_t)(row + 8) * 512 + col) = v1;
            }
    } else {
        int part = n0 >> 9;
        int h = ((n0 + wn * 64) >> 6) & 7;
        __nv_bfloat16 *dh = (part == 0) ? g_qhi : (part == 1) ? g_khi : g_vhi;
        __nv_bfloat16 *dl = (part == 0) ? g_qlo : (part == 1) ? g_klo : g_vlo;
        float sc = (part == 0) ? 0.125f : 1.0f;
        int bb = m0 >> 10, lbase = (m0 & 1023) + wm * 32;
#pragma unroll
        for (int mf = 0; mf < 2; mf++)
#pragma unroll
            for (int f = 0; f < 8; f++) {
                int ll = lbase + mf * 16 + rq;
                size_t base = ((size_t)(bb * 8 + h) * 1024 + ll) * 64 + f * 8 + q2;
                unsigned hh, lw;
                split2(C[mf][f][0] * sc, C[mf][f][1] * sc, hh, lw);
                *(unsigned*)(dh + base) = hh; *(unsigned*)(dl + base) = lw;
                split2(C[mf][f][2] * sc, C[mf][f][3] * sc, hh, lw);
                *(unsigned*)(dh + base + 8 * 64) = hh; *(unsigned*)(dl + base + 8 * 64) = lw;
            }
    }
}

// ---------------- attention: mma.sync flash, 64 q-rows/CTA --------------------
// static smem: Khi 0, Klo 8K, Vhi 16K, Vlo 24K (each 64x64 bf16, SW128)
__global__ void __launch_bounds__(128) attn_mma(const float* __restrict__ gamma) {
    __shared__ __align__(1024) unsigned char smA[32768];
    const uint32_t sb = smem_u32(smA);
    const int t = threadIdx.x, lane = t & 31, wid = t >> 5;
    const int b = blockIdx.z, h = blockIdx.y, i0 = blockIdx.x * 64;
    const int bh = b * H_ + h;
    const int rq = lane >> 2, q2 = 2 * (lane & 3);

    float tv = 0.0f;
#pragma unroll
    for (int kk = 0; kk < 5; kk++)
        if ((lane >> kk) & 1) tv += gamma[h * 5 + kk];

    // stage Q tile (64x64 hi/lo) into K region, build A-fragments in registers
    {
#pragma unroll
        for (int i = 0; i < 4; i++) {
            int pos = t + i * 128, row = pos >> 3, cs = pos & 7;
            unsigned off = SW128((unsigned)(row * 128 + cs * 16));
            size_t g = ((size_t)bh * L_ + i0 + row) * 64 + cs * 8;
            *(uint4*)(smA + off)        = *(const uint4*)(g_qhi + g);
            *(uint4*)(smA + 8192 + off) = *(const uint4*)(g_qlo + g);
        }
    }
    __syncthreads();
    unsigned qh[4][4], ql[4][4];
    {
        int arow = wid * 16 + (lane & 15);
        int ak = (lane >> 4) * 8;
#pragma unroll
        for (int ks = 0; ks < 4; ks++) {
            unsigned off = SW128((unsigned)(arow * 128 + (ak + ks * 16) * 2));
            ldm4(qh[ks], sb + off);
            ldm4(ql[ks], sb + 8192 + off);
        }
    }
    __syncthreads();

    float O[8][4];
#pragma unroll
    for (int f = 0; f < 8; f++)
#pragma unroll
        for (int c = 0; c < 4; c++) O[f][c] = 0.0f;
    float m0r = -1e30f, m1r = -1e30f, l0r = 0.0f, l1r = 0.0f;

    const int ig0 = i0 + wid * 16 + rq;
    const unsigned char* mr0 = g_mask + ((size_t)b << 20) + (size_t)ig0 * 1024;
    const unsigned char* mr1 = mr0 + 8 * 1024;

    // ldmatrix address components
    const int kb_row = ((lane >> 4) << 3) + (lane & 7);   // + nf4*16 (K, non-trans)
    const int kb_k   = ((lane >> 3) & 1) * 8;             // + ks*16
    const int vb_j   = ((lane >> 3) & 1) * 8 + (lane & 7);// + ks*16 (V, trans)
    const int vb_d   = (lane >> 4) * 8;                   // + nf4*16

    for (int j0 = 0; j0 < L_; j0 += 64) {
        // load K/V tiles hi/lo
#pragma unroll
        for (int i = 0; i < 4; i++) {
            int pos = t + i * 128, row = pos >> 3, cs = pos & 7;
            unsigned off = SW128((unsigned)(row * 128 + cs * 16));
            size_t g = ((size_t)bh * L_ + j0 + row) * 64 + cs * 8;
            *(uint4*)(smA + off)         = *(const uint4*)(g_khi + g);
            *(uint4*)(smA + 8192 + off)  = *(const uint4*)(g_klo + g);
            *(uint4*)(smA + 16384 + off) = *(const uint4*)(g_vhi + g);
            *(uint4*)(smA + 24576 + off) = *(const uint4*)(g_vlo + g);
        }
        __syncthreads();

        // S = Q K^T (16 x 64 per warp)
        float S[8][4];
#pragma unroll
        for (int f = 0; f < 8; f++)
#pragma unroll
            for (int c = 0; c < 4; c++) S[f][c] = 0.0f;
#pragma unroll
        for (int ks = 0; ks < 4; ks++) {
#pragma unroll
            for (int nf4 = 0; nf4 < 4; nf4++) {
                unsigned off = SW128((unsigned)((kb_row + nf4 * 16) * 128 + (kb_k + ks * 16) * 2));
                unsigned bhf[4], blf[4];
                ldm4(bhf, sb + off);
                ldm4(blf, sb + 8192 + off);
                mma_bf16(S[2 * nf4], qh[ks], bhf);
                mma_bf16(S[2 * nf4], qh[ks], blf);
                mma_bf16(S[2 * nf4], ql[ks], bhf);
                mma_bf16(S[2 * nf4 + 1], qh[ks], bhf + 2);
                mma_bf16(S[2 * nf4 + 1], qh[ks], blf + 2);
                mma_bf16(S[2 * nf4 + 1], ql[ks], bhf + 2);
            }
        }

        // bias + online softmax (rows rq, rq+8)
        float mx0 = -1e30f, mx1 = -1e30f;
#pragma unroll
        for (int f = 0; f < 8; f++) {
            int cb = j0 + f * 8 + q2;
            unsigned short w0 = *(const unsigned short*)(mr0 + cb);
            unsigned short w1 = *(const unsigned short*)(mr1 + cb);
            S[f][0] += __shfl_sync(0xffffffffu, tv, w0 & 31u);
            S[f][1] += __shfl_sync(0xffffffffu, tv, (w0 >> 8) & 31u);
            S[f][2] += __shfl_sync(0xffffffffu, tv, w1 & 31u);
            S[f][3] += __shfl_sync(0xffffffffu, tv, (w1 >> 8) & 31u);
            mx0 = fmaxf(mx0, fmaxf(S[f][0], S[f][1]));
            mx1 = fmaxf(mx1, fmaxf(S[f][2], S[f][3]));
        }
        mx0 = fmaxf(mx0, __shfl_xor_sync(0xffffffffu, mx0, 1));
        mx0 = fmaxf(mx0, __shfl_xor_sync(0xffffffffu, mx0, 2));
        mx1 = fmaxf(mx1, __shfl_xor_sync(0xffffffffu, mx1, 1));
        mx1 = fmaxf(mx1, __shfl_xor_sync(0xffffffffu, mx1, 2));
        float nm0 = fmaxf(m0r, mx0), nm1 = fmaxf(m1r, mx1);
        float fac0 = __expf(m0r - nm0), fac1 = __expf(m1r - nm1);
        m0r = nm0; m1r = nm1;
        float rs0 = 0.0f, rs1 = 0.0f;
        unsigned ph01[8], ph23[8], pl01[8], pl23[8];
#pragma unroll
        for (int f = 0; f < 8; f++) {
            S[f][0] = __expf(S[f][0] - nm0); S[f][1] = __expf(S[f][1] - nm0);
            S[f][2] = __expf(S[f][2] - nm1); S[f][3] = __expf(S[f][3] - nm1);
            rs0 += S[f][0] + S[f][1];
            rs1 += S[f][2] + S[f][3];
            split2(S[f][0], S[f][1], ph01[f], pl01[f]);
            split2(S[f][2], S[f][3], ph23[f], pl23[f]);
            O[f][0] *= fac0; O[f][1] *= fac0;
            O[f][2] *= fac1; O[f][3] *= fac1;
        }
        rs0 += __shfl_xor_sync(0xffffffffu, rs0, 1);
        rs0 += __shfl_xor_sync(0xffffffffu, rs0, 2);
        rs1 += __shfl_xor_sync(0xffffffffu, rs1, 1);
        rs1 += __shfl_xor_sync(0xffffffffu, rs1, 2);
        l0r = l0r * fac0 + rs0;
        l1r = l1r * fac1 + rs1;

        // O += P V
#pragma unroll
        for (int ks = 0; ks < 4; ks++) {
            unsigned ah[4] = { ph01[2 * ks], ph23[2 * ks], ph01[2 * ks + 1], ph23[2 * ks + 1] };
            unsigned al[4] = { pl01[2 * ks], pl23[2 * ks], pl01[2 * ks + 1], pl23[2 * ks + 1] };
#pragma unroll
            for (int nf4 = 0; nf4 < 4; nf4++) {
                unsigned off = SW128((unsigned)((vb_j + ks * 16) * 128 + (vb_d + nf4 * 16) * 2));
                unsigned bvh[4], bvl[4];
                ldm4t(bvh, sb + 16384 + off);
                ldm4t(bvl, sb + 24576 + off);
                mma_bf16(O[2 * nf4], ah, bvh);
                mma_bf16(O[2 * nf4], ah, bvl);
                mma_bf16(O[2 * nf4], al, bvh);
                mma_bf16(O[2 * nf4 + 1], ah, bvh + 2);
                mma_bf16(O[2 * nf4 + 1], ah, bvl + 2);
                mma_bf16(O[2 * nf4 + 1], al, bvh + 2);
            }
        }
        __syncthreads();
    }

    // epilogue: normalize and store split to g_ao
    float inv0 = 1.0f / l0r, inv1 = 1.0f / l1r;
    size_t base0 = ((size_t)(b << 10) + ig0) * 512 + h * 64;
    size_t base1 = base0 + 8 * 512;
#pragma unroll
    for (int f = 0; f < 8; f++) {
        unsigned hh, lw;
        split2(O[f][0] * inv0, O[f][1] * inv0, hh, lw);
        *(unsigned*)(g_aohi + base0 + f * 8 + q2) = hh;
        *(unsigned*)(g_aolo + base0 + f * 8 + q2) = lw;
        split2(O[f][2] * inv1, O[f][3] * inv1, hh, lw);
        *(unsigned*)(g_aohi + base1 + f * 8 + q2) = hh;
        *(unsigned*)(g_aolo + base1 + f * 8 + q2) = lw;
    }
}

// ---------------- launch --------------------------------------------------------
extern "C" void kernel_launch(void* const* d_in, const int* in_sizes, int n_in,
                              void* d_out, int out_size) {
    const float* x      = (const float*)d_in[0];
    const float* adj    = (const float*)d_in[1];
    const float* dist   = (const float*)d_in[2];
    const float* w_qkv  = (const float*)d_in[3];
    const float* w_proj = (const float*)d_in[4];
    const float* gamma  = (const float*)d_in[5];
    float* out = (float*)d_out;

    cudaFuncSetAttribute(mm_kernel, cudaFuncAttributeMaxDynamicSharedMemorySize, GDYN);

    pack_kernel<<<(B_ * L_ * L_) / 256, 256>>>(adj, dist);
    mask_kernel<<<dim3(L_ / 32, L_ / 32, B_), 256>>>();
    split_x<<<(M_TOT * C_) / 256, 256>>>(x);
    split_w<<<(786432 + 262144) / 256, 256>>>(w_qkv, w_proj);
    mm_kernel<<<dim3(12, 64), 256, GDYN>>>(0, nullptr);   // qkv
    attn_mma<<<dim3(L_ / 64, H_, B_), 128>>>(gamma);
    mm_kernel<<<dim3(4, 64), 256, GDYN>>>(1, out);        // proj
}

// round 6
// speedup vs baseline: 2.7724x; 1.1805x over previous
#include <cuda_runtime.h>
#include <cuda_bf16.h>
#include <cstdint>

#define B_ 8
#define L_ 1024
#define C_ 512
#define H_ 8
#define D_ 64
#define M_TOT (B_*L_)

// ---------------- static device scratch -------------------------------------
__device__ unsigned g_adjbits[B_*L_*(L_/32)];
__device__ unsigned g_distbits[B_*L_*(L_/32)];
__device__ unsigned char g_mask[(size_t)B_*L_*L_];

__device__ __nv_bfloat16 g_xhi[M_TOT*C_],   g_xlo[M_TOT*C_];
__device__ __nv_bfloat16 g_wqT_hi[3*C_*C_], g_wqT_lo[3*C_*C_];  // [1536][512]
__device__ __nv_bfloat16 g_wpT_hi[C_*C_],   g_wpT_lo[C_*C_];    // [512][512]
__device__ __nv_bfloat16 g_qhi[B_*H_*L_*D_], g_qlo[B_*H_*L_*D_]; // q pre-scaled 1/8
__device__ __nv_bfloat16 g_khi[B_*H_*L_*D_], g_klo[B_*H_*L_*D_];
__device__ __nv_bfloat16 g_vhi[B_*H_*L_*D_], g_vlo[B_*H_*L_*D_];
__device__ __nv_bfloat16 g_aohi[M_TOT*C_],  g_aolo[M_TOT*C_];

// ---------------- helpers -----------------------------------------------------
__device__ __forceinline__ uint32_t smem_u32(const void* p) {
    uint32_t a;
    asm("{ .reg .u64 t; cvta.to.shared.u64 t, %1; cvt.u32.u64 %0, t; }" : "=r"(a) : "l"(p));
    return a;
}
#define SW128(o) ((o) ^ (((o) >> 3) & 0x70))

#define CPA(dst, src) asm volatile("cp.async.cg.shared.global [%0], [%1], 16;" :: "r"(dst), "l"(src))
#define CPC()  asm volatile("cp.async.commit_group;")
#define CPW(n) asm volatile("cp.async.wait_group %0;" :: "n"(n))

__device__ __forceinline__ void mma_bf16(float* c, const unsigned* a, const unsigned* b) {
    asm volatile("mma.sync.aligned.m16n8k16.row.col.f32.bf16.bf16.f32 "
        "{%0,%1,%2,%3}, {%4,%5,%6,%7}, {%8,%9}, {%0,%1,%2,%3};"
        : "+f"(c[0]), "+f"(c[1]), "+f"(c[2]), "+f"(c[3])
        : "r"(a[0]), "r"(a[1]), "r"(a[2]), "r"(a[3]), "r"(b[0]), "r"(b[1]));
}
__device__ __forceinline__ void ldm4(unsigned* r, uint32_t a) {
    asm volatile("ldmatrix.sync.aligned.m8n8.x4.shared.b16 {%0,%1,%2,%3}, [%4];"
        : "=r"(r[0]), "=r"(r[1]), "=r"(r[2]), "=r"(r[3]) : "r"(a));
}
__device__ __forceinline__ void ldm4t(unsigned* r, uint32_t a) {
    asm volatile("ldmatrix.sync.aligned.m8n8.x4.trans.shared.b16 {%0,%1,%2,%3}, [%4];"
        : "=r"(r[0]), "=r"(r[1]), "=r"(r[2]), "=r"(r[3]) : "r"(a));
}
__device__ __forceinline__ void split2(float a, float b, unsigned& h, unsigned& l) {
    __nv_bfloat162 hv = __floats2bfloat162_rn(a, b);
    __nv_bfloat162 lv = __floats2bfloat162_rn(a - __bfloat162float(hv.x),
                                              b - __bfloat162float(hv.y));
    h = *(unsigned*)&hv; l = *(unsigned*)&lv;
}

// ---------------- pack / mask (unchanged, passing) ---------------------------
__global__ void pack_kernel(const float* __restrict__ adj, const float* __restrict__ dist) {
    unsigned e = blockIdx.x * 256u + threadIdx.x;
    unsigned j = e & (L_ - 1u), i = (e >> 10) & (L_ - 1u);
    bool ab = (adj[e] != 0.0f) && (i != 0u) && (j != 0u);
    unsigned aw = __ballot_sync(0xffffffffu, ab);
    unsigned dw = __ballot_sync(0xffffffffu, dist[e] > 0.0f);
    if ((threadIdx.x & 31u) == 0u) { g_adjbits[e >> 5] = aw; g_distbits[e >> 5] = dw; }
}

__global__ void mask_kernel() {
    const int b = blockIdx.z, i0 = blockIdx.y * 32, j0 = blockIdx.x * 32;
    __shared__ unsigned Ai[32][33], Aj[32][33];
    const int t = threadIdx.x;
#pragma unroll
    for (int k = 0; k < 4; k++) {
        int pos = t + k * 256, r = pos >> 5, w = pos & 31;
        Ai[r][w] = g_adjbits[((b << 10) + i0 + r) * 32 + w];
        Aj[r][w] = g_adjbits[((b << 10) + j0 + r) * 32 + w];
    }
    __syncthreads();
    const int il = t >> 3, jb = (t & 7) << 2, ig = i0 + il;
    const unsigned di = g_distbits[((b << 10) + ig) * 32 + (j0 >> 5)];
    unsigned sbits = 0u;
    for (int w = 0; w < 32; w++) {
        unsigned ai = Ai[il][w];
#pragma unroll
        for (int jj = 0; jj < 4; jj++)
            if (ai & Aj[jb + jj][w]) sbits |= (1u << jj);
        if (sbits == 0xFu) break;
    }
    unsigned word = 0u;
#pragma unroll
    for (int jj = 0; jj < 4; jj++) {
        int jl = jb + jj;
        unsigned fwd = (Ai[il][j0 >> 5] >> jl) & 1u;
        unsigned bwd = (Aj[jl][i0 >> 5] >> il) & 1u;
        unsigned dfw = (di >> jl) & 1u;
        unsigned dbw = (g_distbits[((b << 10) + j0 + jl) * 32 + (i0 >> 5)] >> il) & 1u;
        unsigned st = (sbits >> jj) & 1u;
        word |= (fwd | (bwd << 1) | (dfw << 2) | (dbw << 3) | (st << 4)) << (8 * jj);
    }
    *reinterpret_cast<unsigned*>(g_mask + (((size_t)((b << 10) + ig)) << 10) + j0 + jb) = word;
}

// ---------------- splits -------------------------------------------------------
__global__ void split_x(const float* __restrict__ x) {
    int i = blockIdx.x * 256 + threadIdx.x;
    float v = x[i];
    __nv_bfloat16 h = __float2bfloat16(v);
    g_xhi[i] = h; g_xlo[i] = __float2bfloat16(v - __bfloat162float(h));
}
__global__ void split_w(const float* __restrict__ wq, const float* __restrict__ wp) {
    int i = blockIdx.x * 256 + threadIdx.x;
    if (i < 786432) {
        int k = i / 1536, n = i % 1536;
        float v = wq[i];
        __nv_bfloat16 h = __float2bfloat16(v);
        g_wqT_hi[n * 512 + k] = h;
        g_wqT_lo[n * 512 + k] = __float2bfloat16(v - __bfloat162float(h));
    } else {
        int j = i - 786432, k = j / 512, n = j % 512;
        float v = wp[j];
        __nv_bfloat16 h = __float2bfloat16(v);
        g_wpT_hi[n * 512 + k] = h;
        g_wpT_lo[n * 512 + k] = __float2bfloat16(v - __bfloat162float(h));
    }
}

// ---------------- mma.sync GEMM: 128x128 CTA tile, K=512, 2-stage cp.async ----
// stage s at s*65536: Ahi 0, Alo 16K, Bhi 32K, Blo 48K (each 128x64 bf16, SW128)
#define GDYN (131072 + 1024)
__global__ void __launch_bounds__(256) mm_kernel(int mode, float* __restrict__ out) {
    extern __shared__ char raw[];
    uint32_t rb = smem_u32(raw);
    char* sm = raw + ((1024u - (rb & 1023u)) & 1023u);
    const uint32_t sb = smem_u32(sm);
    const int t = threadIdx.x, lane = t & 31, wid = t >> 5;
    const int wm = wid & 3, wn = wid >> 2;
    const int n0 = blockIdx.x * 128, m0 = blockIdx.y * 128;

    const __nv_bfloat16 *Ahi, *Alo, *Bhi, *Blo;
    if (mode == 0) { Ahi = g_xhi;  Alo = g_xlo;  Bhi = g_wqT_hi; Blo = g_wqT_lo; }
    else           { Ahi = g_aohi; Alo = g_aolo; Bhi = g_wpT_hi; Blo = g_wpT_lo; }

    float C[2][8][4];
#pragma unroll
    for (int m = 0; m < 2; m++)
#pragma unroll
        for (int f = 0; f < 8; f++)
#pragma unroll
            for (int c = 0; c < 4; c++) C[m][f][c] = 0.0f;

    const int a_row = wm * 32 + (lane & 15);
    const int a_k   = (lane >> 4) * 8;
    const int b_row = wn * 64 + ((lane >> 4) << 3) + (lane & 7);
    const int b_k   = ((lane >> 3) & 1) * 8;

    auto pf = [&](int kc, uint32_t stb) {
#pragma unroll
        for (int i = 0; i < 4; i++) {
            int pos = t + i * 256, row = pos >> 3, cs = pos & 7;
            unsigned off = SW128((unsigned)(row * 128 + cs * 16));
            size_t ga = (size_t)(m0 + row) * 512 + kc * 64 + cs * 8;
            size_t gb = (size_t)(n0 + row) * 512 + kc * 64 + cs * 8;
            CPA(stb + off,         Ahi + ga);
            CPA(stb + 16384 + off, Alo + ga);
            CPA(stb + 32768 + off, Bhi + gb);
            CPA(stb + 49152 + off, Blo + gb);
        }
    };
    pf(0, sb);
    CPC();

    for (int kc = 0; kc < 8; kc++) {
        if (kc < 7) { pf(kc + 1, sb + (unsigned)((kc + 1) & 1) * 65536u); CPC(); CPW(1); }
        else CPW(0);
        __syncthreads();
        const uint32_t base = sb + (unsigned)(kc & 1) * 65536u;
#pragma unroll
        for (int ks = 0; ks < 4; ks++) {
            unsigned ah[2][4], al[2][4];
#pragma unroll
            for (int mf = 0; mf < 2; mf++) {
                unsigned off = SW128((unsigned)((a_row + mf * 16) * 128 + (a_k + ks * 16) * 2));
                ldm4(ah[mf], base + off);
                ldm4(al[mf], base + 16384 + off);
            }
#pragma unroll
            for (int nf4 = 0; nf4 < 4; nf4++) {
                unsigned off = SW128((unsigned)((b_row + nf4 * 16) * 128 + (b_k + ks * 16) * 2));
                unsigned bh[4], bl[4];
                ldm4(bh, base + 32768 + off);
                ldm4(bl, base + 49152 + off);
#pragma unroll
                for (int mf = 0; mf < 2; mf++) {
                    mma_bf16(C[mf][2 * nf4], ah[mf], bh);
                    mma_bf16(C[mf][2 * nf4], ah[mf], bl);
                    mma_bf16(C[mf][2 * nf4], al[mf], bh);
                    mma_bf16(C[mf][2 * nf4 + 1], ah[mf], bh + 2);
                    mma_bf16(C[mf][2 * nf4 + 1], ah[mf], bl + 2);
                    mma_bf16(C[mf][2 * nf4 + 1], al[mf], bh + 2);
                }
            }
        }
        __syncthreads();
    }

    const int rq = lane >> 2, q2 = 2 * (lane & 3);
    if (mode == 1) {
#pragma unroll
        for (int mf = 0; mf < 2; mf++)
#pragma unroll
            for (int f = 0; f < 8; f++) {
                int row = m0 + wm * 32 + mf * 16 + rq;
                int col = n0 + wn * 64 + f * 8 + q2;
                float2 v0; v0.x = C[mf][f][0]; v0.y = C[mf][f][1];
                float2 v1; v1.x = C[mf][f][2]; v1.y = C[mf][f][3];
                *(float2*)(out + (size_t)row * 512 + col) = v0;
                *(float2*)(out + (size_t)(row + 8) * 512 + col) = v1;
            }
    } else {
        int part = n0 >> 9;
        int h = ((n0 + wn * 64) >> 6) & 7;
        __nv_bfloat16 *dh = (part == 0) ? g_qhi : (part == 1) ? g_khi : g_vhi;
        __nv_bfloat16 *dl = (part == 0) ? g_qlo : (part == 1) ? g_klo : g_vlo;
        float sc = (part == 0) ? 0.125f : 1.0f;
        int bb = m0 >> 10, lbase = (m0 & 1023) + wm * 32;
#pragma unroll
        for (int mf = 0; mf < 2; mf++)
#pragma unroll
            for (int f = 0; f < 8; f++) {
                int ll = lbase + mf * 16 + rq;
                size_t base = ((size_t)(bb * 8 + h) * 1024 + ll) * 64 + f * 8 + q2;
                unsigned hh, lw;
                split2(C[mf][f][0] * sc, C[mf][f][1] * sc, hh, lw);
                *(unsigned*)(dh + base) = hh; *(unsigned*)(dl + base) = lw;
                split2(C[mf][f][2] * sc, C[mf][f][3] * sc, hh, lw);
                *(unsigned*)(dh + base + 8 * 64) = hh; *(unsigned*)(dl + base + 8 * 64) = lw;
            }
    }
}

// ---------------- attention: mma.sync flash, 2-stage cp.async, PV 3-pass ------
// stage s at s*32768: Khi 0, Klo 8K, Vhi 16K, Vlo 24K (each 64x64 bf16, SW128)
#define ADYN (65536 + 1024)
__global__ void __launch_bounds__(128) attn_mma(const float* __restrict__ gamma) {
    extern __shared__ char raw[];
    uint32_t rb = smem_u32(raw);
    char* sm = raw + ((1024u - (rb & 1023u)) & 1023u);
    const uint32_t sb = smem_u32(sm);
    const int t = threadIdx.x, lane = t & 31, wid = t >> 5;
    const int b = blockIdx.z, h = blockIdx.y, i0 = blockIdx.x * 64;
    const int bh = b * H_ + h;
    const int rq = lane >> 2, q2 = 2 * (lane & 3);

    float tv = 0.0f;
#pragma unroll
    for (int kk = 0; kk < 5; kk++)
        if ((lane >> kk) & 1) tv += gamma[h * 5 + kk];

    // stage Q (64x64 hi/lo) into stage0, then build A-fragments in registers
#pragma unroll
    for (int i = 0; i < 4; i++) {
        int pos = t + i * 128, row = pos >> 3, cs = pos & 7;
        unsigned off = SW128((unsigned)(row * 128 + cs * 16));
        size_t g = ((size_t)bh * L_ + i0 + row) * 64 + cs * 8;
        *(uint4*)(sm + off)        = *(const uint4*)(g_qhi + g);
        *(uint4*)(sm + 8192 + off) = *(const uint4*)(g_qlo + g);
    }
    __syncthreads();
    unsigned qh[4][4], ql[4][4];
    {
        int arow = wid * 16 + (lane & 15);
        int ak = (lane >> 4) * 8;
#pragma unroll
        for (int ks = 0; ks < 4; ks++) {
            unsigned off = SW128((unsigned)(arow * 128 + (ak + ks * 16) * 2));
            ldm4(qh[ks], sb + off);
            ldm4(ql[ks], sb + 8192 + off);
        }
    }
    __syncthreads();

    // prefetch tile 0 into stage 0
    {
#pragma unroll
        for (int i = 0; i < 4; i++) {
            int pos = t + i * 128, row = pos >> 3, cs = pos & 7;
            unsigned off = SW128((unsigned)(row * 128 + cs * 16));
            size_t g = ((size_t)bh * L_ + row) * 64 + cs * 8;
            CPA(sb + off,         g_khi + g);
            CPA(sb + 8192 + off,  g_klo + g);
            CPA(sb + 16384 + off, g_vhi + g);
            CPA(sb + 24576 + off, g_vlo + g);
        }
        CPC();
    }

    float O[8][4];
#pragma unroll
    for (int f = 0; f < 8; f++)
#pragma unroll
        for (int c = 0; c < 4; c++) O[f][c] = 0.0f;
    float m0r = -1e30f, m1r = -1e30f, l0r = 0.0f, l1r = 0.0f;

    const int ig0 = i0 + wid * 16 + rq;
    const unsigned char* mr0 = g_mask + ((size_t)b << 20) + (size_t)ig0 * 1024;
    const unsigned char* mr1 = mr0 + 8 * 1024;

    const int kb_row = ((lane >> 4) << 3) + (lane & 7);
    const int kb_k   = ((lane >> 3) & 1) * 8;
    const int vb_j   = ((lane >> 3) & 1) * 8 + (lane & 7);
    const int vb_d   = (lane >> 4) * 8;

    for (int jt = 0; jt < 16; jt++) {
        if (jt < 15) {
            const uint32_t stb = sb + (unsigned)((jt + 1) & 1) * 32768u;
            const int j1 = (jt + 1) * 64;
#pragma unroll
            for (int i = 0; i < 4; i++) {
                int pos = t + i * 128, row = pos >> 3, cs = pos & 7;
                unsigned off = SW128((unsigned)(row * 128 + cs * 16));
                size_t g = ((size_t)bh * L_ + j1 + row) * 64 + cs * 8;
                CPA(stb + off,         g_khi + g);
                CPA(stb + 8192 + off,  g_klo + g);
                CPA(stb + 16384 + off, g_vhi + g);
                CPA(stb + 24576 + off, g_vlo + g);
            }
            CPC(); CPW(1);
        } else CPW(0);
        __syncthreads();
        const uint32_t base = sb + (unsigned)(jt & 1) * 32768u;
        const int j0 = jt * 64;

        // S = Q K^T (16 x 64 per warp), 3-pass
        float S[8][4];
#pragma unroll
        for (int f = 0; f < 8; f++)
#pragma unroll
            for (int c = 0; c < 4; c++) S[f][c] = 0.0f;
#pragma unroll
        for (int ks = 0; ks < 4; ks++) {
#pragma unroll
            for (int nf4 = 0; nf4 < 4; nf4++) {
                unsigned off = SW128((unsigned)((kb_row + nf4 * 16) * 128 + (kb_k + ks * 16) * 2));
                unsigned bhf[4], blf[4];
                ldm4(bhf, base + off);
                ldm4(blf, base + 8192 + off);
                mma_bf16(S[2 * nf4], qh[ks], bhf);
                mma_bf16(S[2 * nf4], qh[ks], blf);
                mma_bf16(S[2 * nf4], ql[ks], bhf);
                mma_bf16(S[2 * nf4 + 1], qh[ks], bhf + 2);
                mma_bf16(S[2 * nf4 + 1], qh[ks], blf + 2);
                mma_bf16(S[2 * nf4 + 1], ql[ks], bhf + 2);
            }
        }

        // bias + online softmax (rows rq, rq+8)
        float mx0 = -1e30f, mx1 = -1e30f;
#pragma unroll
        for (int f = 0; f < 8; f++) {
            int cb = j0 + f * 8 + q2;
            unsigned short w0 = *(const unsigned short*)(mr0 + cb);
            unsigned short w1 = *(const unsigned short*)(mr1 + cb);
            S[f][0] += __shfl_sync(0xffffffffu, tv, w0 & 31u);
            S[f][1] += __shfl_sync(0xffffffffu, tv, (w0 >> 8) & 31u);
            S[f][2] += __shfl_sync(0xffffffffu, tv, w1 & 31u);
            S[f][3] += __shfl_sync(0xffffffffu, tv, (w1 >> 8) & 31u);
            mx0 = fmaxf(mx0, fmaxf(S[f][0], S[f][1]));
            mx1 = fmaxf(mx1, fmaxf(S[f][2], S[f][3]));
        }
        mx0 = fmaxf(mx0, __shfl_xor_sync(0xffffffffu, mx0, 1));
        mx0 = fmaxf(mx0, __shfl_xor_sync(0xffffffffu, mx0, 2));
        mx1 = fmaxf(mx1, __shfl_xor_sync(0xffffffffu, mx1, 1));
        mx1 = fmaxf(mx1, __shfl_xor_sync(0xffffffffu, mx1, 2));
        float nm0 = fmaxf(m0r, mx0), nm1 = fmaxf(m1r, mx1);
        float fac0 = __expf(m0r - nm0), fac1 = __expf(m1r - nm1);
        m0r = nm0; m1r = nm1;
        float rs0 = 0.0f, rs1 = 0.0f;
        unsigned ph01[8], ph23[8], pl01[8], pl23[8];
#pragma unroll
        for (int f = 0; f < 8; f++) {
            S[f][0] = __expf(S[f][0] - nm0); S[f][1] = __expf(S[f][1] - nm0);
            S[f][2] = __expf(S[f][2] - nm1); S[f][3] = __expf(S[f][3] - nm1);
            rs0 += S[f][0] + S[f][1];
            rs1 += S[f][2] + S[f][3];
            split2(S[f][0], S[f][1], ph01[f], pl01[f]);
            split2(S[f][2], S[f][3], ph23[f], pl23[f]);
            O[f][0] *= fac0; O[f][1] *= fac0;
            O[f][2] *= fac1; O[f][3] *= fac1;
        }
        rs0 += __shfl_xor_sync(0xffffffffu, rs0, 1);
        rs0 += __shfl_xor_sync(0xffffffffu, rs0, 2);
        rs1 += __shfl_xor_sync(0xffffffffu, rs1, 1);
        rs1 += __shfl_xor_sync(0xffffffffu, rs1, 2);
        l0r = l0r * fac0 + rs0;
        l1r = l1r * fac1 + rs1;

        // O += P V  (3-pass: Ph*Vh + Ph*Vl + Pl*Vh)
#pragma unroll
        for (int ks = 0; ks < 4; ks++) {
            unsigned ah[4] = { ph01[2 * ks], ph23[2 * ks], ph01[2 * ks + 1], ph23[2 * ks + 1] };
            unsigned al[4] = { pl01[2 * ks], pl23[2 * ks], pl01[2 * ks + 1], pl23[2 * ks + 1] };
#pragma unroll
            for (int nf4 = 0; nf4 < 4; nf4++) {
                unsigned off = SW128((unsigned)((vb_j + ks * 16) * 128 + (vb_d + nf4 * 16) * 2));
                unsigned bvh[4], bvl[4];
                ldm4t(bvh, base + 16384 + off);
                ldm4t(bvl, base + 24576 + off);
                mma_bf16(O[2 * nf4], ah, bvh);
                mma_bf16(O[2 * nf4], ah, bvl);
                mma_bf16(O[2 * nf4], al, bvh);
                mma_bf16(O[2 * nf4 + 1], ah, bvh + 2);
                mma_bf16(O[2 * nf4 + 1], ah, bvl + 2);
                mma_bf16(O[2 * nf4 + 1], al, bvh + 2);
            }
        }
        __syncthreads();
    }

    // epilogue: normalize and store split to g_ao
    float inv0 = 1.0f / l0r, inv1 = 1.0f / l1r;
    size_t base0 = ((size_t)(b << 10) + ig0) * 512 + h * 64;
    size_t base1 = base0 + 8 * 512;
#pragma unroll
    for (int f = 0; f < 8; f++) {
        unsigned hh, lw;
        split2(O[f][0] * inv0, O[f][1] * inv0, hh, lw);
        *(unsigned*)(g_aohi + base0 + f * 8 + q2) = hh;
        *(unsigned*)(g_aolo + base0 + f * 8 + q2) = lw;
        split2(O[f][2] * inv1, O[f][3] * inv1, hh, lw);
        *(unsigned*)(g_aohi + base1 + f * 8 + q2) = hh;
        *(unsigned*)(g_aolo + base1 + f * 8 + q2) = lw;
    }
}

// ---------------- launch --------------------------------------------------------
extern "C" void kernel_launch(void* const* d_in, const int* in_sizes, int n_in,
                              void* d_out, int out_size) {
    const float* x      = (const float*)d_in[0];
    const float* adj    = (const float*)d_in[1];
    const float* dist   = (const float*)d_in[2];
    const float* w_qkv  = (const float*)d_in[3];
    const float* w_proj = (const float*)d_in[4];
    const float* gamma  = (const float*)d_in[5];
    float* out = (float*)d_out;

    cudaFuncSetAttribute(mm_kernel, cudaFuncAttributeMaxDynamicSharedMemorySize, GDYN);
    cudaFuncSetAttribute(attn_mma, cudaFuncAttributeMaxDynamicSharedMemorySize, ADYN);

    pack_kernel<<<(B_ * L_ * L_) / 256, 256>>>(adj, dist);
    mask_kernel<<<dim3(L_ / 32, L_ / 32, B_), 256>>>();
    split_x<<<(M_TOT * C_) / 256, 256>>>(x);
    split_w<<<(786432 + 262144) / 256, 256>>>(w_qkv, w_proj);
    mm_kernel<<<dim3(12, 64), 256, GDYN>>>(0, nullptr);   // qkv
    attn_mma<<<dim3(L_ / 64, H_, B_), 128, ADYN>>>(gamma);
    mm_kernel<<<dim3(4, 64), 256, GDYN>>>(1, out);        // proj
}

// round 7
// speedup vs baseline: 3.2358x; 1.1672x over previous
#include <cuda_runtime.h>
#include <cuda_fp16.h>
#include <cstdint>

#define B_ 8
#define L_ 1024
#define C_ 512
#define H_ 8
#define D_ 64
#define M_TOT (B_*L_)

// ---------------- static device scratch -------------------------------------
__device__ unsigned g_adjbits[B_*L_*(L_/32)];
__device__ unsigned g_distbits[B_*L_*(L_/32)];
__device__ unsigned char g_mask[(size_t)B_*L_*L_];

__device__ __half g_xh[M_TOT*C_];
__device__ __half g_wqT_hi[3*C_*C_], g_wqT_lo[3*C_*C_];  // [1536][512]
__device__ __half g_wpT_hi[C_*C_],   g_wpT_lo[C_*C_];    // [512][512]
__device__ __half g_qh[B_*H_*L_*D_];                      // pre-scaled 1/8, hi only
__device__ __half g_kh[B_*H_*L_*D_], g_kl[B_*H_*L_*D_];
__device__ __half g_vh[B_*H_*L_*D_], g_vl[B_*H_*L_*D_];
__device__ __half g_aoh[M_TOT*C_];                        // hi only

// ---------------- helpers -----------------------------------------------------
__device__ __forceinline__ uint32_t smem_u32(const void* p) {
    uint32_t a;
    asm("{ .reg .u64 t; cvta.to.shared.u64 t, %1; cvt.u32.u64 %0, t; }" : "=r"(a) : "l"(p));
    return a;
}
#define SW128(o) ((o) ^ (((o) >> 3) & 0x70))

#define CPA(dst, src) asm volatile("cp.async.cg.shared.global [%0], [%1], 16;" :: "r"(dst), "l"(src))
#define CPC()  asm volatile("cp.async.commit_group;")
#define CPW(n) asm volatile("cp.async.wait_group %0;" :: "n"(n))

__device__ __forceinline__ void mma_f16(float* c, const unsigned* a, const unsigned* b) {
    asm volatile("mma.sync.aligned.m16n8k16.row.col.f32.f16.f16.f32 "
        "{%0,%1,%2,%3}, {%4,%5,%6,%7}, {%8,%9}, {%0,%1,%2,%3};"
        : "+f"(c[0]), "+f"(c[1]), "+f"(c[2]), "+f"(c[3])
        : "r"(a[0]), "r"(a[1]), "r"(a[2]), "r"(a[3]), "r"(b[0]), "r"(b[1]));
}
__device__ __forceinline__ void ldm4(unsigned* r, uint32_t a) {
    asm volatile("ldmatrix.sync.aligned.m8n8.x4.shared.b16 {%0,%1,%2,%3}, [%4];"
        : "=r"(r[0]), "=r"(r[1]), "=r"(r[2]), "=r"(r[3]) : "r"(a));
}
__device__ __forceinline__ void ldm4t(unsigned* r, uint32_t a) {
    asm volatile("ldmatrix.sync.aligned.m8n8.x4.trans.shared.b16 {%0,%1,%2,%3}, [%4];"
        : "=r"(r[0]), "=r"(r[1]), "=r"(r[2]), "=r"(r[3]) : "r"(a));
}
__device__ __forceinline__ unsigned packh2(float a, float b) {
    __half2 hv = __floats2half2_rn(a, b);
    return *(unsigned*)&hv;
}
__device__ __forceinline__ void split2h(float a, float b, unsigned& h, unsigned& l) {
    __half2 hv = __floats2half2_rn(a, b);
    __half2 lv = __floats2half2_rn(a - __half2float(hv.x), b - __half2float(hv.y));
    h = *(unsigned*)&hv; l = *(unsigned*)&lv;
}

// ---------------- pack / mask (unchanged, passing) ---------------------------
__global__ void pack_kernel(const float* __restrict__ adj, const float* __restrict__ dist) {
    unsigned e = blockIdx.x * 256u + threadIdx.x;
    unsigned j = e & (L_ - 1u), i = (e >> 10) & (L_ - 1u);
    bool ab = (adj[e] != 0.0f) && (i != 0u) && (j != 0u);
    unsigned aw = __ballot_sync(0xffffffffu, ab);
    unsigned dw = __ballot_sync(0xffffffffu, dist[e] > 0.0f);
    if ((threadIdx.x & 31u) == 0u) { g_adjbits[e >> 5] = aw; g_distbits[e >> 5] = dw; }
}

__global__ void mask_kernel() {
    const int b = blockIdx.z, i0 = blockIdx.y * 32, j0 = blockIdx.x * 32;
    __shared__ unsigned Ai[32][33], Aj[32][33];
    const int t = threadIdx.x;
#pragma unroll
    for (int k = 0; k < 4; k++) {
        int pos = t + k * 256, r = pos >> 5, w = pos & 31;
        Ai[r][w] = g_adjbits[((b << 10) + i0 + r) * 32 + w];
        Aj[r][w] = g_adjbits[((b << 10) + j0 + r) * 32 + w];
    }
    __syncthreads();
    const int il = t >> 3, jb = (t & 7) << 2, ig = i0 + il;
    const unsigned di = g_distbits[((b << 10) + ig) * 32 + (j0 >> 5)];
    unsigned sbits = 0u;
    for (int w = 0; w < 32; w++) {
        unsigned ai = Ai[il][w];
#pragma unroll
        for (int jj = 0; jj < 4; jj++)
            if (ai & Aj[jb + jj][w]) sbits |= (1u << jj);
        if (sbits == 0xFu) break;
    }
    unsigned word = 0u;
#pragma unroll
    for (int jj = 0; jj < 4; jj++) {
        int jl = jb + jj;
        unsigned fwd = (Ai[il][j0 >> 5] >> jl) & 1u;
        unsigned bwd = (Aj[jl][i0 >> 5] >> il) & 1u;
        unsigned dfw = (di >> jl) & 1u;
        unsigned dbw = (g_distbits[((b << 10) + j0 + jl) * 32 + (i0 >> 5)] >> il) & 1u;
        unsigned st = (sbits >> jj) & 1u;
        word |= (fwd | (bwd << 1) | (dfw << 2) | (dbw << 3) | (st << 4)) << (8 * jj);
    }
    *reinterpret_cast<unsigned*>(g_mask + (((size_t)((b << 10) + ig)) << 10) + j0 + jb) = word;
}

// ---------------- splits -------------------------------------------------------
__global__ void split_x(const float* __restrict__ x) {
    int i = blockIdx.x * 256 + threadIdx.x;
    g_xh[i] = __float2half_rn(x[i]);
}
__global__ void split_w(const float* __restrict__ wq, const float* __restrict__ wp) {
    int i = blockIdx.x * 256 + threadIdx.x;
    if (i < 786432) {
        int k = i / 1536, n = i % 1536;
        float v = wq[i];
        __half h = __float2half_rn(v);
        g_wqT_hi[n * 512 + k] = h;
        g_wqT_lo[n * 512 + k] = __float2half_rn(v - __half2float(h));
    } else {
        int j = i - 786432, k = j / 512, n = j % 512;
        float v = wp[j];
        __half h = __float2half_rn(v);
        g_wpT_hi[n * 512 + k] = h;
        g_wpT_lo[n * 512 + k] = __float2half_rn(v - __half2float(h));
    }
}

// ---------------- fp16 GEMM: 128x128 CTA tile, K=512, 2-stage cp.async --------
// stage s at s*49152: Ahi 0, Bhi 16K, Blo 32K (each 128x64 fp16, SW128)
#define GDYN (98304 + 1024)
__global__ void __launch_bounds__(256) mm_kernel(int mode, float* __restrict__ out) {
    extern __shared__ char raw[];
    uint32_t rb = smem_u32(raw);
    char* sm = raw + ((1024u - (rb & 1023u)) & 1023u);
    const uint32_t sb = smem_u32(sm);
    const int t = threadIdx.x, lane = t & 31, wid = t >> 5;
    const int wm = wid & 3, wn = wid >> 2;
    const int n0 = blockIdx.x * 128, m0 = blockIdx.y * 128;

    const __half *Ah, *Bh, *Bl;
    if (mode == 0) { Ah = g_xh;  Bh = g_wqT_hi; Bl = g_wqT_lo; }
    else           { Ah = g_aoh; Bh = g_wpT_hi; Bl = g_wpT_lo; }

    float C[2][8][4];
#pragma unroll
    for (int m = 0; m < 2; m++)
#pragma unroll
        for (int f = 0; f < 8; f++)
#pragma unroll
            for (int c = 0; c < 4; c++) C[m][f][c] = 0.0f;

    const int a_row = wm * 32 + (lane & 15);
    const int a_k   = (lane >> 4) * 8;
    const int b_row = wn * 64 + ((lane >> 4) << 3) + (lane & 7);
    const int b_k   = ((lane >> 3) & 1) * 8;

    auto pf = [&](int kc, uint32_t stb) {
#pragma unroll
        for (int i = 0; i < 4; i++) {
            int pos = t + i * 256, row = pos >> 3, cs = pos & 7;
            unsigned off = SW128((unsigned)(row * 128 + cs * 16));
            size_t ga = (size_t)(m0 + row) * 512 + kc * 64 + cs * 8;
            size_t gb = (size_t)(n0 + row) * 512 + kc * 64 + cs * 8;
            CPA(stb + off,         Ah + ga);
            CPA(stb + 16384 + off, Bh + gb);
            CPA(stb + 32768 + off, Bl + gb);
        }
    };
    pf(0, sb);
    CPC();

    for (int kc = 0; kc < 8; kc++) {
        if (kc < 7) { pf(kc + 1, sb + (unsigned)((kc + 1) & 1) * 49152u); CPC(); CPW(1); }
        else CPW(0);
        __syncthreads();
        const uint32_t base = sb + (unsigned)(kc & 1) * 49152u;
#pragma unroll
        for (int ks = 0; ks < 4; ks++) {
            unsigned ah[2][4];
#pragma unroll
            for (int mf = 0; mf < 2; mf++) {
                unsigned off = SW128((unsigned)((a_row + mf * 16) * 128 + (a_k + ks * 16) * 2));
                ldm4(ah[mf], base + off);
            }
#pragma unroll
            for (int nf4 = 0; nf4 < 4; nf4++) {
                unsigned off = SW128((unsigned)((b_row + nf4 * 16) * 128 + (b_k + ks * 16) * 2));
                unsigned bh[4], bl[4];
                ldm4(bh, base + 16384 + off);
                ldm4(bl, base + 32768 + off);
#pragma unroll
                for (int mf = 0; mf < 2; mf++) {
                    mma_f16(C[mf][2 * nf4], ah[mf], bh);
                    mma_f16(C[mf][2 * nf4], ah[mf], bl);
                    mma_f16(C[mf][2 * nf4 + 1], ah[mf], bh + 2);
                    mma_f16(C[mf][2 * nf4 + 1], ah[mf], bl + 2);
                }
            }
        }
        __syncthreads();
    }

    const int rq = lane >> 2, q2 = 2 * (lane & 3);
    if (mode == 1) {
#pragma unroll
        for (int mf = 0; mf < 2; mf++)
#pragma unroll
            for (int f = 0; f < 8; f++) {
                int row = m0 + wm * 32 + mf * 16 + rq;
                int col = n0 + wn * 64 + f * 8 + q2;
                float2 v0; v0.x = C[mf][f][0]; v0.y = C[mf][f][1];
                float2 v1; v1.x = C[mf][f][2]; v1.y = C[mf][f][3];
                *(float2*)(out + (size_t)row * 512 + col) = v0;
                *(float2*)(out + (size_t)(row + 8) * 512 + col) = v1;
            }
    } else {
        int part = n0 >> 9;
        int h = ((n0 + wn * 64) >> 6) & 7;
        int bb = m0 >> 10, lbase = (m0 & 1023) + wm * 32;
        if (part == 0) {
#pragma unroll
            for (int mf = 0; mf < 2; mf++)
#pragma unroll
                for (int f = 0; f < 8; f++) {
                    int ll = lbase + mf * 16 + rq;
                    size_t base = ((size_t)(bb * 8 + h) * 1024 + ll) * 64 + f * 8 + q2;
                    *(unsigned*)(g_qh + base)          = packh2(C[mf][f][0] * 0.125f, C[mf][f][1] * 0.125f);
                    *(unsigned*)(g_qh + base + 8 * 64) = packh2(C[mf][f][2] * 0.125f, C[mf][f][3] * 0.125f);
                }
        } else {
            __half *dh = (part == 1) ? g_kh : g_vh;
            __half *dl = (part == 1) ? g_kl : g_vl;
#pragma unroll
            for (int mf = 0; mf < 2; mf++)
#pragma unroll
                for (int f = 0; f < 8; f++) {
                    int ll = lbase + mf * 16 + rq;
                    size_t base = ((size_t)(bb * 8 + h) * 1024 + ll) * 64 + f * 8 + q2;
                    unsigned hh, lw;
                    split2h(C[mf][f][0], C[mf][f][1], hh, lw);
                    *(unsigned*)(dh + base) = hh; *(unsigned*)(dl + base) = lw;
                    split2h(C[mf][f][2], C[mf][f][3], hh, lw);
                    *(unsigned*)(dh + base + 8 * 64) = hh; *(unsigned*)(dl + base + 8 * 64) = lw;
                }
        }
    }
}

// ---------------- attention: fp16 flash, 256 thr / 128 q-rows, 2-stage --------
// stage s at s*32768: Kh 0, Kl 8K, Vh 16K, Vl 24K (each 64x64 fp16, SW128)
#define ADYN (65536 + 1024)
__global__ void __launch_bounds__(256, 2) attn_mma(const float* __restrict__ gamma) {
    extern __shared__ char raw[];
    uint32_t rb = smem_u32(raw);
    char* sm = raw + ((1024u - (rb & 1023u)) & 1023u);
    const uint32_t sb = smem_u32(sm);
    const int t = threadIdx.x, lane = t & 31, wid = t >> 5;
    const int b = blockIdx.z, h = blockIdx.y, i0 = blockIdx.x * 128;
    const int bh = b * H_ + h;
    const int rq = lane >> 2, q2 = 2 * (lane & 3);

    float tv = 0.0f;
#pragma unroll
    for (int kk = 0; kk < 5; kk++)
        if ((lane >> kk) & 1) tv += gamma[h * 5 + kk];

    // stage Q (128x64 fp16 hi) into stage0, then build A-fragments in registers
#pragma unroll
    for (int i = 0; i < 4; i++) {
        int pos = t + i * 256, row = pos >> 3, cs = pos & 7;
        unsigned off = SW128((unsigned)(row * 128 + cs * 16));
        size_t g = ((size_t)bh * L_ + i0 + row) * 64 + cs * 8;
        *(uint4*)(sm + off) = *(const uint4*)(g_qh + g);
    }
    __syncthreads();
    unsigned qh[4][4];
    {
        int arow = wid * 16 + (lane & 15);
        int ak = (lane >> 4) * 8;
#pragma unroll
        for (int ks = 0; ks < 4; ks++) {
            unsigned off = SW128((unsigned)(arow * 128 + (ak + ks * 16) * 2));
            ldm4(qh[ks], sb + off);
        }
    }
    __syncthreads();

    // prefetch tile 0 into stage 0
#pragma unroll
    for (int i = 0; i < 2; i++) {
        int pos = t + i * 256, row = pos >> 3, cs = pos & 7;
        unsigned off = SW128((unsigned)(row * 128 + cs * 16));
        size_t g = ((size_t)bh * L_ + row) * 64 + cs * 8;
        CPA(sb + off,         g_kh + g);
        CPA(sb + 8192 + off,  g_kl + g);
        CPA(sb + 16384 + off, g_vh + g);
        CPA(sb + 24576 + off, g_vl + g);
    }
    CPC();

    float O[8][4];
#pragma unroll
    for (int f = 0; f < 8; f++)
#pragma unroll
        for (int c = 0; c < 4; c++) O[f][c] = 0.0f;
    float m0r = -1e30f, m1r = -1e30f, l0r = 0.0f, l1r = 0.0f;

    const int ig0 = i0 + wid * 16 + rq;
    const unsigned char* mr0 = g_mask + ((size_t)b << 20) + (size_t)ig0 * 1024;
    const unsigned char* mr1 = mr0 + 8 * 1024;

    const int kb_row = ((lane >> 4) << 3) + (lane & 7);
    const int kb_k   = ((lane >> 3) & 1) * 8;
    const int vb_j   = ((lane >> 3) & 1) * 8 + (lane & 7);
    const int vb_d   = (lane >> 4) * 8;

    for (int jt = 0; jt < 16; jt++) {
        if (jt < 15) {
            const uint32_t stb = sb + (unsigned)((jt + 1) & 1) * 32768u;
            const int j1 = (jt + 1) * 64;
#pragma unroll
            for (int i = 0; i < 2; i++) {
                int pos = t + i * 256, row = pos >> 3, cs = pos & 7;
                unsigned off = SW128((unsigned)(row * 128 + cs * 16));
                size_t g = ((size_t)bh * L_ + j1 + row) * 64 + cs * 8;
                CPA(stb + off,         g_kh + g);
                CPA(stb + 8192 + off,  g_kl + g);
                CPA(stb + 16384 + off, g_vh + g);
                CPA(stb + 24576 + off, g_vl + g);
            }
            CPC(); CPW(1);
        } else CPW(0);
        __syncthreads();
        const uint32_t base = sb + (unsigned)(jt & 1) * 32768u;
        const int j0 = jt * 64;

        // S = Q K^T (16 x 64 per warp), 2-pass (Qh*Kh + Qh*Kl)
        float S[8][4];
#pragma unroll
        for (int f = 0; f < 8; f++)
#pragma unroll
            for (int c = 0; c < 4; c++) S[f][c] = 0.0f;
#pragma unroll
        for (int ks = 0; ks < 4; ks++) {
#pragma unroll
            for (int nf4 = 0; nf4 < 4; nf4++) {
                unsigned off = SW128((unsigned)((kb_row + nf4 * 16) * 128 + (kb_k + ks * 16) * 2));
                unsigned bhf[4], blf[4];
                ldm4(bhf, base + off);
                ldm4(blf, base + 8192 + off);
                mma_f16(S[2 * nf4], qh[ks], bhf);
                mma_f16(S[2 * nf4], qh[ks], blf);
                mma_f16(S[2 * nf4 + 1], qh[ks], bhf + 2);
                mma_f16(S[2 * nf4 + 1], qh[ks], blf + 2);
            }
        }

        // bias + online softmax (rows rq, rq+8)
        float mx0 = -1e30f, mx1 = -1e30f;
#pragma unroll
        for (int f = 0; f < 8; f++) {
            int cb = j0 + f * 8 + q2;
            unsigned short w0 = *(const unsigned short*)(mr0 + cb);
            unsigned short w1 = *(const unsigned short*)(mr1 + cb);
            S[f][0] += __shfl_sync(0xffffffffu, tv, w0 & 31u);
            S[f][1] += __shfl_sync(0xffffffffu, tv, (w0 >> 8) & 31u);
            S[f][2] += __shfl_sync(0xffffffffu, tv, w1 & 31u);
            S[f][3] += __shfl_sync(0xffffffffu, tv, (w1 >> 8) & 31u);
            mx0 = fmaxf(mx0, fmaxf(S[f][0], S[f][1]));
            mx1 = fmaxf(mx1, fmaxf(S[f][2], S[f][3]));
        }
        mx0 = fmaxf(mx0, __shfl_xor_sync(0xffffffffu, mx0, 1));
        mx0 = fmaxf(mx0, __shfl_xor_sync(0xffffffffu, mx0, 2));
        mx1 = fmaxf(mx1, __shfl_xor_sync(0xffffffffu, mx1, 1));
        mx1 = fmaxf(mx1, __shfl_xor_sync(0xffffffffu, mx1, 2));
        float nm0 = fmaxf(m0r, mx0), nm1 = fmaxf(m1r, mx1);
        float fac0 = __expf(m0r - nm0), fac1 = __expf(m1r - nm1);
        m0r = nm0; m1r = nm1;
        float rs0 = 0.0f, rs1 = 0.0f;
        unsigned ph01[8], ph23[8];
#pragma unroll
        for (int f = 0; f < 8; f++) {
            S[f][0] = __expf(S[f][0] - nm0); S[f][1] = __expf(S[f][1] - nm0);
            S[f][2] = __expf(S[f][2] - nm1); S[f][3] = __expf(S[f][3] - nm1);
            rs0 += S[f][0] + S[f][1];
            rs1 += S[f][2] + S[f][3];
            ph01[f] = packh2(S[f][0], S[f][1]);
            ph23[f] = packh2(S[f][2], S[f][3]);
            O[f][0] *= fac0; O[f][1] *= fac0;
            O[f][2] *= fac1; O[f][3] *= fac1;
        }
        rs0 += __shfl_xor_sync(0xffffffffu, rs0, 1);
        rs0 += __shfl_xor_sync(0xffffffffu, rs0, 2);
        rs1 += __shfl_xor_sync(0xffffffffu, rs1, 1);
        rs1 += __shfl_xor_sync(0xffffffffu, rs1, 2);
        l0r = l0r * fac0 + rs0;
        l1r = l1r * fac1 + rs1;

        // O += P V  (2-pass: Ph*Vh + Ph*Vl)
#pragma unroll
        for (int ks = 0; ks < 4; ks++) {
            unsigned ah[4] = { ph01[2 * ks], ph23[2 * ks], ph01[2 * ks + 1], ph23[2 * ks + 1] };
#pragma unroll
            for (int nf4 = 0; nf4 < 4; nf4++) {
                unsigned off = SW128((unsigned)((vb_j + ks * 16) * 128 + (vb_d + nf4 * 16) * 2));
                unsigned bvh[4], bvl[4];
                ldm4t(bvh, base + 16384 + off);
                ldm4t(bvl, base + 24576 + off);
                mma_f16(O[2 * nf4], ah, bvh);
                mma_f16(O[2 * nf4], ah, bvl);
                mma_f16(O[2 * nf4 + 1], ah, bvh + 2);
                mma_f16(O[2 * nf4 + 1], ah, bvl + 2);
            }
        }
        __syncthreads();
    }

    // epilogue: normalize and store fp16 hi to g_aoh
    float inv0 = 1.0f / l0r, inv1 = 1.0f / l1r;
    size_t base0 = ((size_t)(b << 10) + ig0) * 512 + h * 64;
    size_t base1 = base0 + 8 * 512;
#pragma unroll
    for (int f = 0; f < 8; f++) {
        *(unsigned*)(g_aoh + base0 + f * 8 + q2) = packh2(O[f][0] * inv0, O[f][1] * inv0);
        *(unsigned*)(g_aoh + base1 + f * 8 + q2) = packh2(O[f][2] * inv1, O[f][3] * inv1);
    }
}

// ---------------- launch --------------------------------------------------------
extern "C" void kernel_launch(void* const* d_in, const int* in_sizes, int n_in,
                              void* d_out, int out_size) {
    const float* x      = (const float*)d_in[0];
    const float* adj    = (const float*)d_in[1];
    const float* dist   = (const float*)d_in[2];
    const float* w_qkv  = (const float*)d_in[3];
    const float* w_proj = (const float*)d_in[4];
    const float* gamma  = (const float*)d_in[5];
    float* out = (float*)d_out;

    cudaFuncSetAttribute(mm_kernel, cudaFuncAttributeMaxDynamicSharedMemorySize, GDYN);
    cudaFuncSetAttribute(attn_mma, cudaFuncAttributeMaxDynamicSharedMemorySize, ADYN);

    pack_kernel<<<(B_ * L_ * L_) / 256, 256>>>(adj, dist);
    mask_kernel<<<dim3(L_ / 32, L_ / 32, B_), 256>>>();
    split_x<<<(M_TOT * C_) / 256, 256>>>(x);
    split_w<<<(786432 + 262144) / 256, 256>>>(w_qkv, w_proj);
    mm_kernel<<<dim3(12, 64), 256, GDYN>>>(0, nullptr);   // qkv
    attn_mma<<<dim3(L_ / 128, H_, B_), 256, ADYN>>>(gamma);
    mm_kernel<<<dim3(4, 64), 256, GDYN>>>(1, out);        // proj
}

// round 8
// speedup vs baseline: 3.8624x; 1.1936x over previous
#include <cuda_runtime.h>
#include <cuda_fp16.h>
#include <cstdint>

#define B_ 8
#define L_ 1024
#define C_ 512
#define H_ 8
#define D_ 64
#define M_TOT (B_*L_)

// ---------------- static device scratch -------------------------------------
__device__ unsigned g_adjbits[B_*L_*(L_/32)];
__device__ unsigned g_distbits[B_*L_*(L_/32)];
__device__ unsigned char g_mask[(size_t)B_*L_*L_];

__device__ __half g_xh[M_TOT*C_];
__device__ __half g_wqT_hi[3*C_*C_], g_wqT_lo[3*C_*C_];  // [1536][512]
__device__ __half g_wpT_hi[C_*C_],   g_wpT_lo[C_*C_];    // [512][512]
__device__ __half g_qh[B_*H_*L_*D_];                      // pre-scaled 1/8
__device__ __half g_kh[B_*H_*L_*D_];
__device__ __half g_vh[B_*H_*L_*D_];
__device__ __half g_aoh[M_TOT*C_];

// ---------------- helpers -----------------------------------------------------
__device__ __forceinline__ uint32_t smem_u32(const void* p) {
    uint32_t a;
    asm("{ .reg .u64 t; cvta.to.shared.u64 t, %1; cvt.u32.u64 %0, t; }" : "=r"(a) : "l"(p));
    return a;
}
#define SW128(o) ((o) ^ (((o) >> 3) & 0x70))

#define CPA(dst, src) asm volatile("cp.async.cg.shared.global [%0], [%1], 16;" :: "r"(dst), "l"(src))
#define CPC()  asm volatile("cp.async.commit_group;")
#define CPW(n) asm volatile("cp.async.wait_group %0;" :: "n"(n))

__device__ __forceinline__ void mma_f16(float* c, const unsigned* a, const unsigned* b) {
    asm volatile("mma.sync.aligned.m16n8k16.row.col.f32.f16.f16.f32 "
        "{%0,%1,%2,%3}, {%4,%5,%6,%7}, {%8,%9}, {%0,%1,%2,%3};"
        : "+f"(c[0]), "+f"(c[1]), "+f"(c[2]), "+f"(c[3])
        : "r"(a[0]), "r"(a[1]), "r"(a[2]), "r"(a[3]), "r"(b[0]), "r"(b[1]));
}
__device__ __forceinline__ void ldm4(unsigned* r, uint32_t a) {
    asm volatile("ldmatrix.sync.aligned.m8n8.x4.shared.b16 {%0,%1,%2,%3}, [%4];"
        : "=r"(r[0]), "=r"(r[1]), "=r"(r[2]), "=r"(r[3]) : "r"(a));
}
__device__ __forceinline__ void ldm4t(unsigned* r, uint32_t a) {
    asm volatile("ldmatrix.sync.aligned.m8n8.x4.trans.shared.b16 {%0,%1,%2,%3}, [%4];"
        : "=r"(r[0]), "=r"(r[1]), "=r"(r[2]), "=r"(r[3]) : "r"(a));
}
__device__ __forceinline__ unsigned packh2(float a, float b) {
    __half2 hv = __floats2half2_rn(a, b);
    return *(unsigned*)&hv;
}

// ---------------- pack / mask (unchanged, passing) ---------------------------
__global__ void pack_kernel(const float* __restrict__ adj, const float* __restrict__ dist) {
    unsigned e = blockIdx.x * 256u + threadIdx.x;
    unsigned j = e & (L_ - 1u), i = (e >> 10) & (L_ - 1u);
    bool ab = (adj[e] != 0.0f) && (i != 0u) && (j != 0u);
    unsigned aw = __ballot_sync(0xffffffffu, ab);
    unsigned dw = __ballot_sync(0xffffffffu, dist[e] > 0.0f);
    if ((threadIdx.x & 31u) == 0u) { g_adjbits[e >> 5] = aw; g_distbits[e >> 5] = dw; }
}

__global__ void mask_kernel() {
    const int b = blockIdx.z, i0 = blockIdx.y * 32, j0 = blockIdx.x * 32;
    __shared__ unsigned Ai[32][33], Aj[32][33];
    const int t = threadIdx.x;
#pragma unroll
    for (int k = 0; k < 4; k++) {
        int pos = t + k * 256, r = pos >> 5, w = pos & 31;
        Ai[r][w] = g_adjbits[((b << 10) + i0 + r) * 32 + w];
        Aj[r][w] = g_adjbits[((b << 10) + j0 + r) * 32 + w];
    }
    __syncthreads();
    const int il = t >> 3, jb = (t & 7) << 2, ig = i0 + il;
    const unsigned di = g_distbits[((b << 10) + ig) * 32 + (j0 >> 5)];
    unsigned sbits = 0u;
    for (int w = 0; w < 32; w++) {
        unsigned ai = Ai[il][w];
#pragma unroll
        for (int jj = 0; jj < 4; jj++)
            if (ai & Aj[jb + jj][w]) sbits |= (1u << jj);
        if (sbits == 0xFu) break;
    }
    unsigned word = 0u;
#pragma unroll
    for (int jj = 0; jj < 4; jj++) {
        int jl = jb + jj;
        unsigned fwd = (Ai[il][j0 >> 5] >> jl) & 1u;
        unsigned bwd = (Aj[jl][i0 >> 5] >> il) & 1u;
        unsigned dfw = (di >> jl) & 1u;
        unsigned dbw = (g_distbits[((b << 10) + j0 + jl) * 32 + (i0 >> 5)] >> il) & 1u;
        unsigned st = (sbits >> jj) & 1u;
        word |= (fwd | (bwd << 1) | (dfw << 2) | (dbw << 3) | (st << 4)) << (8 * jj);
    }
    *reinterpret_cast<unsigned*>(g_mask + (((size_t)((b << 10) + ig)) << 10) + j0 + jb) = word;
}

// ---------------- splits -------------------------------------------------------
__global__ void split_x(const float* __restrict__ x) {
    int i = blockIdx.x * 256 + threadIdx.x;
    g_xh[i] = __float2half_rn(x[i]);
}

// coalesced smem tile transpose: w[K][N] -> wT[N][K] split hi/lo
// block handles a 32x32 tile; 256 threads
__global__ void split_w(const float* __restrict__ wq, const float* __restrict__ wp) {
    __shared__ float tile[32][33];
    int bid = blockIdx.x;
    const float* src; __half *dh, *dl; int N;
    if (bid < 768) { src = wq; dh = g_wqT_hi; dl = g_wqT_lo; N = 1536; }
    else           { bid -= 768; src = wp; dh = g_wpT_hi; dl = g_wpT_lo; N = 512; }
    int tn = N >> 5;                 // tiles along n
    int k0 = (bid / tn) * 32, n0 = (bid % tn) * 32;
    int c = threadIdx.x & 31, r0 = threadIdx.x >> 5;   // 8 rows per pass
#pragma unroll
    for (int p = 0; p < 4; p++) {
        int r = r0 + p * 8;
        tile[r][c] = src[(size_t)(k0 + r) * N + n0 + c];
    }
    __syncthreads();
#pragma unroll
    for (int p = 0; p < 4; p++) {
        int r = r0 + p * 8;          // row of wT within tile (= n index)
        float v = tile[c][r];
        __half h = __float2half_rn(v);
        size_t o = (size_t)(n0 + r) * 512 + k0 + c;
        dh[o] = h;
        dl[o] = __float2half_rn(v - __half2float(h));
    }
}

// ---------------- fp16 GEMM: 128x128 CTA tile, K=512, 2-stage cp.async --------
// stage s at s*49152: Ah 0, Bh 16K, Bl 32K (each 128x64 fp16, SW128)
#define GDYN (98304 + 1024)
__global__ void __launch_bounds__(256) mm_kernel(int mode, float* __restrict__ out) {
    extern __shared__ char raw[];
    uint32_t rb = smem_u32(raw);
    char* sm = raw + ((1024u - (rb & 1023u)) & 1023u);
    const uint32_t sb = smem_u32(sm);
    const int t = threadIdx.x, lane = t & 31, wid = t >> 5;
    const int wm = wid & 3, wn = wid >> 2;
    const int n0 = blockIdx.x * 128, m0 = blockIdx.y * 128;

    const __half *Ah, *Bh, *Bl;
    if (mode == 0) { Ah = g_xh;  Bh = g_wqT_hi; Bl = g_wqT_lo; }
    else           { Ah = g_aoh; Bh = g_wpT_hi; Bl = g_wpT_lo; }

    float C[2][8][4];
#pragma unroll
    for (int m = 0; m < 2; m++)
#pragma unroll
        for (int f = 0; f < 8; f++)
#pragma unroll
            for (int c = 0; c < 4; c++) C[m][f][c] = 0.0f;

    const int a_row = wm * 32 + (lane & 15);
    const int a_k   = (lane >> 4) * 8;
    const int b_row = wn * 64 + ((lane >> 4) << 3) + (lane & 7);
    const int b_k   = ((lane >> 3) & 1) * 8;

    auto pf = [&](int kc, uint32_t stb) {
#pragma unroll
        for (int i = 0; i < 4; i++) {
            int pos = t + i * 256, row = pos >> 3, cs = pos & 7;
            unsigned off = SW128((unsigned)(row * 128 + cs * 16));
            size_t ga = (size_t)(m0 + row) * 512 + kc * 64 + cs * 8;
            size_t gb = (size_t)(n0 + row) * 512 + kc * 64 + cs * 8;
            CPA(stb + off,         Ah + ga);
            CPA(stb + 16384 + off, Bh + gb);
            CPA(stb + 32768 + off, Bl + gb);
        }
    };
    pf(0, sb);
    CPC();

    for (int kc = 0; kc < 8; kc++) {
        if (kc < 7) { pf(kc + 1, sb + (unsigned)((kc + 1) & 1) * 49152u); CPC(); CPW(1); }
        else CPW(0);
        __syncthreads();
        const uint32_t base = sb + (unsigned)(kc & 1) * 49152u;
#pragma unroll
        for (int ks = 0; ks < 4; ks++) {
            unsigned ah[2][4];
#pragma unroll
            for (int mf = 0; mf < 2; mf++) {
                unsigned off = SW128((unsigned)((a_row + mf * 16) * 128 + (a_k + ks * 16) * 2));
                ldm4(ah[mf], base + off);
            }
#pragma unroll
            for (int nf4 = 0; nf4 < 4; nf4++) {
                unsigned off = SW128((unsigned)((b_row + nf4 * 16) * 128 + (b_k + ks * 16) * 2));
                unsigned bh[4], bl[4];
                ldm4(bh, base + 16384 + off);
                ldm4(bl, base + 32768 + off);
#pragma unroll
                for (int mf = 0; mf < 2; mf++) {
                    mma_f16(C[mf][2 * nf4], ah[mf], bh);
                    mma_f16(C[mf][2 * nf4], ah[mf], bl);
                    mma_f16(C[mf][2 * nf4 + 1], ah[mf], bh + 2);
                    mma_f16(C[mf][2 * nf4 + 1], ah[mf], bl + 2);
                }
            }
        }
        __syncthreads();
    }

    const int rq = lane >> 2, q2 = 2 * (lane & 3);
    if (mode == 1) {
#pragma unroll
        for (int mf = 0; mf < 2; mf++)
#pragma unroll
            for (int f = 0; f < 8; f++) {
                int row = m0 + wm * 32 + mf * 16 + rq;
                int col = n0 + wn * 64 + f * 8 + q2;
                float2 v0; v0.x = C[mf][f][0]; v0.y = C[mf][f][1];
                float2 v1; v1.x = C[mf][f][2]; v1.y = C[mf][f][3];
                *(float2*)(out + (size_t)row * 512 + col) = v0;
                *(float2*)(out + (size_t)(row + 8) * 512 + col) = v1;
            }
    } else {
        int part = n0 >> 9;
        int h = ((n0 + wn * 64) >> 6) & 7;
        __half* dst = (part == 0) ? g_qh : (part == 1) ? g_kh : g_vh;
        float sc = (part == 0) ? 0.125f : 1.0f;
        int bb = m0 >> 10, lbase = (m0 & 1023) + wm * 32;
#pragma unroll
        for (int mf = 0; mf < 2; mf++)
#pragma unroll
            for (int f = 0; f < 8; f++) {
                int ll = lbase + mf * 16 + rq;
                size_t base = ((size_t)(bb * 8 + h) * 1024 + ll) * 64 + f * 8 + q2;
                *(unsigned*)(dst + base)          = packh2(C[mf][f][0] * sc, C[mf][f][1] * sc);
                *(unsigned*)(dst + base + 8 * 64) = packh2(C[mf][f][2] * sc, C[mf][f][3] * sc);
            }
    }
}

// ---------------- attention: fp16 flash, 256 thr / 128 q-rows, 3-stage --------
// stage s at s*16384: Kh 0, Vh 8K (each 64x64 fp16, SW128)
#define ADYN (49152 + 1024)
__global__ void __launch_bounds__(256, 2) attn_mma(const float* __restrict__ gamma) {
    extern __shared__ char raw[];
    uint32_t rb = smem_u32(raw);
    char* sm = raw + ((1024u - (rb & 1023u)) & 1023u);
    const uint32_t sb = smem_u32(sm);
    const int t = threadIdx.x, lane = t & 31, wid = t >> 5;
    const int b = blockIdx.z, h = blockIdx.y, i0 = blockIdx.x * 128;
    const int bh = b * H_ + h;
    const int rq = lane >> 2, q2 = 2 * (lane & 3);

    float tv = 0.0f;
#pragma unroll
    for (int kk = 0; kk < 5; kk++)
        if ((lane >> kk) & 1) tv += gamma[h * 5 + kk];

    // stage Q (128x64 fp16) into stage0, build A-fragments in registers
#pragma unroll
    for (int i = 0; i < 4; i++) {
        int pos = t + i * 256, row = pos >> 3, cs = pos & 7;
        unsigned off = SW128((unsigned)(row * 128 + cs * 16));
        size_t g = ((size_t)bh * L_ + i0 + row) * 64 + cs * 8;
        *(uint4*)(sm + off) = *(const uint4*)(g_qh + g);
    }
    __syncthreads();
    unsigned qh[4][4];
    {
        int arow = wid * 16 + (lane & 15);
        int ak = (lane >> 4) * 8;
#pragma unroll
        for (int ks = 0; ks < 4; ks++) {
            unsigned off = SW128((unsigned)(arow * 128 + (ak + ks * 16) * 2));
            ldm4(qh[ks], sb + off);
        }
    }
    __syncthreads();

    auto pf = [&](int jtile, uint32_t stb) {
#pragma unroll
        for (int i = 0; i < 2; i++) {
            int pos = t + i * 256, row = pos >> 3, cs = pos & 7;
            unsigned off = SW128((unsigned)(row * 128 + cs * 16));
            size_t g = ((size_t)bh * L_ + jtile * 64 + row) * 64 + cs * 8;
            CPA(stb + off,        g_kh + g);
            CPA(stb + 8192 + off, g_vh + g);
        }
    };
    pf(0, sb); CPC();
    pf(1, sb + 16384u); CPC();

    float O[8][4];
#pragma unroll
    for (int f = 0; f < 8; f++)
#pragma unroll
        for (int c = 0; c < 4; c++) O[f][c] = 0.0f;
    float m0r = -1e30f, m1r = -1e30f, l0r = 0.0f, l1r = 0.0f;

    const int ig0 = i0 + wid * 16 + rq;
    const unsigned char* mr0 = g_mask + ((size_t)b << 20) + (size_t)ig0 * 1024;
    const unsigned char* mr1 = mr0 + 8 * 1024;

    const int kb_row = ((lane >> 4) << 3) + (lane & 7);
    const int kb_k   = ((lane >> 3) & 1) * 8;
    const int vb_j   = ((lane >> 3) & 1) * 8 + (lane & 7);
    const int vb_d   = (lane >> 4) * 8;

    int stg = 0;
    for (int jt = 0; jt < 16; jt++) {
        if (jt < 14) {
            int s2 = (jt + 2) % 3;
            pf(jt + 2, sb + (unsigned)s2 * 16384u);
            CPC(); CPW(2);
        } else if (jt == 14) CPW(1);
        else CPW(0);
        __syncthreads();
        const uint32_t base = sb + (unsigned)stg * 16384u;
        stg = (stg + 1 == 3) ? 0 : stg + 1;
        const int j0 = jt * 64;

        // S = Q K^T (16 x 64 per warp), single pass
        float S[8][4];
#pragma unroll
        for (int f = 0; f < 8; f++)
#pragma unroll
            for (int c = 0; c < 4; c++) S[f][c] = 0.0f;
#pragma unroll
        for (int ks = 0; ks < 4; ks++) {
#pragma unroll
            for (int nf4 = 0; nf4 < 4; nf4++) {
                unsigned off = SW128((unsigned)((kb_row + nf4 * 16) * 128 + (kb_k + ks * 16) * 2));
                unsigned bhf[4];
                ldm4(bhf, base + off);
                mma_f16(S[2 * nf4], qh[ks], bhf);
                mma_f16(S[2 * nf4 + 1], qh[ks], bhf + 2);
            }
        }

        // bias + online softmax (rows rq, rq+8)
        float mx0 = -1e30f, mx1 = -1e30f;
#pragma unroll
        for (int f = 0; f < 8; f++) {
            int cb = j0 + f * 8 + q2;
            unsigned short w0 = *(const unsigned short*)(mr0 + cb);
            unsigned short w1 = *(const unsigned short*)(mr1 + cb);
            S[f][0] += __shfl_sync(0xffffffffu, tv, w0 & 31u);
            S[f][1] += __shfl_sync(0xffffffffu, tv, (w0 >> 8) & 31u);
            S[f][2] += __shfl_sync(0xffffffffu, tv, w1 & 31u);
            S[f][3] += __shfl_sync(0xffffffffu, tv, (w1 >> 8) & 31u);
            mx0 = fmaxf(mx0, fmaxf(S[f][0], S[f][1]));
            mx1 = fmaxf(mx1, fmaxf(S[f][2], S[f][3]));
        }
        mx0 = fmaxf(mx0, __shfl_xor_sync(0xffffffffu, mx0, 1));
        mx0 = fmaxf(mx0, __shfl_xor_sync(0xffffffffu, mx0, 2));
        mx1 = fmaxf(mx1, __shfl_xor_sync(0xffffffffu, mx1, 1));
        mx1 = fmaxf(mx1, __shfl_xor_sync(0xffffffffu, mx1, 2));
        float nm0 = fmaxf(m0r, mx0), nm1 = fmaxf(m1r, mx1);
        float fac0 = __expf(m0r - nm0), fac1 = __expf(m1r - nm1);
        m0r = nm0; m1r = nm1;
        float rs0 = 0.0f, rs1 = 0.0f;
        unsigned ph01[8], ph23[8];
#pragma unroll
        for (int f = 0; f < 8; f++) {
            S[f][0] = __expf(S[f][0] - nm0); S[f][1] = __expf(S[f][1] - nm0);
            S[f][2] = __expf(S[f][2] - nm1); S[f][3] = __expf(S[f][3] - nm1);
            rs0 += S[f][0] + S[f][1];
            rs1 += S[f][2] + S[f][3];
            ph01[f] = packh2(S[f][0], S[f][1]);
            ph23[f] = packh2(S[f][2], S[f][3]);
            O[f][0] *= fac0; O[f][1] *= fac0;
            O[f][2] *= fac1; O[f][3] *= fac1;
        }
        rs0 += __shfl_xor_sync(0xffffffffu, rs0, 1);
        rs0 += __shfl_xor_sync(0xffffffffu, rs0, 2);
        rs1 += __shfl_xor_sync(0xffffffffu, rs1, 1);
        rs1 += __shfl_xor_sync(0xffffffffu, rs1, 2);
        l0r = l0r * fac0 + rs0;
        l1r = l1r * fac1 + rs1;

        // O += P V  (single pass)
#pragma unroll
        for (int ks = 0; ks < 4; ks++) {
            unsigned ah[4] = { ph01[2 * ks], ph23[2 * ks], ph01[2 * ks + 1], ph23[2 * ks + 1] };
#pragma unroll
            for (int nf4 = 0; nf4 < 4; nf4++) {
                unsigned off = SW128((unsigned)((vb_j + ks * 16) * 128 + (vb_d + nf4 * 16) * 2));
                unsigned bvh[4];
                ldm4t(bvh, base + 8192 + off);
                mma_f16(O[2 * nf4], ah, bvh);
                mma_f16(O[2 * nf4 + 1], ah, bvh + 2);
            }
        }
        __syncthreads();
    }

    // epilogue
    float inv0 = 1.0f / l0r, inv1 = 1.0f / l1r;
    size_t base0 = ((size_t)(b << 10) + ig0) * 512 + h * 64;
    size_t base1 = base0 + 8 * 512;
#pragma unroll
    for (int f = 0; f < 8; f++) {
        *(unsigned*)(g_aoh + base0 + f * 8 + q2) = packh2(O[f][0] * inv0, O[f][1] * inv0);
        *(unsigned*)(g_aoh + base1 + f * 8 + q2) = packh2(O[f][2] * inv1, O[f][3] * inv1);
    }
}

// ---------------- launch --------------------------------------------------------
extern "C" void kernel_launch(void* const* d_in, const int* in_sizes, int n_in,
                              void* d_out, int out_size) {
    const float* x      = (const float*)d_in[0];
    const float* adj    = (const float*)d_in[1];
    const float* dist   = (const float*)d_in[2];
    const float* w_qkv  = (const float*)d_in[3];
    const float* w_proj = (const float*)d_in[4];
    const float* gamma  = (const float*)d_in[5];
    float* out = (float*)d_out;

    cudaFuncSetAttribute(mm_kernel, cudaFuncAttributeMaxDynamicSharedMemorySize, GDYN);
    cudaFuncSetAttribute(attn_mma, cudaFuncAttributeMaxDynamicSharedMemorySize, ADYN);

    pack_kernel<<<(B_ * L_ * L_) / 256, 256>>>(adj, dist);
    mask_kernel<<<dim3(L_ / 32, L_ / 32, B_), 256>>>();
    split_x<<<(M_TOT * C_) / 256, 256>>>(x);
    split_w<<<768 + 256, 256>>>(w_qkv, w_proj);
    mm_kernel<<<dim3(12, 64), 256, GDYN>>>(0, nullptr);   // qkv
    attn_mma<<<dim3(L_ / 128, H_, B_), 256, ADYN>>>(gamma);
    mm_kernel<<<dim3(4, 64), 256, GDYN>>>(1, out);        // proj
}

// round 9
// speedup vs baseline: 4.5846x; 1.1870x over previous
#include <cuda_runtime.h>
#include <cuda_fp16.h>
#include <cstdint>

#define B_ 8
#define L_ 1024
#define C_ 512
#define H_ 8
#define D_ 64
#define M_TOT (B_*L_)

// ---------------- static device scratch -------------------------------------
__device__ unsigned g_adjbits[B_*L_*(L_/32)];
__device__ unsigned g_distbits[B_*L_*(L_/32)];
__device__ unsigned char g_mask[(size_t)B_*L_*L_];

__device__ __half g_xh[M_TOT*C_];
__device__ __half g_wqT[3*C_*C_];   // [1536][512] fp16
__device__ __half g_wpT[C_*C_];     // [512][512]  fp16
__device__ __half g_qh[B_*H_*L_*D_];  // pre-scaled 1/8
__device__ __half g_kh[B_*H_*L_*D_];
__device__ __half g_vh[B_*H_*L_*D_];
__device__ __half g_aoh[M_TOT*C_];

// ---------------- helpers -----------------------------------------------------
__device__ __forceinline__ uint32_t smem_u32(const void* p) {
    uint32_t a;
    asm("{ .reg .u64 t; cvta.to.shared.u64 t, %1; cvt.u32.u64 %0, t; }" : "=r"(a) : "l"(p));
    return a;
}
#define SW128(o) ((o) ^ (((o) >> 3) & 0x70))

#define CPA(dst, src) asm volatile("cp.async.cg.shared.global [%0], [%1], 16;" :: "r"(dst), "l"(src))
#define CPC()  asm volatile("cp.async.commit_group;")
#define CPW(n) asm volatile("cp.async.wait_group %0;" :: "n"(n))

__device__ __forceinline__ void mma_f16(float* c, const unsigned* a, const unsigned* b) {
    asm volatile("mma.sync.aligned.m16n8k16.row.col.f32.f16.f16.f32 "
        "{%0,%1,%2,%3}, {%4,%5,%6,%7}, {%8,%9}, {%0,%1,%2,%3};"
        : "+f"(c[0]), "+f"(c[1]), "+f"(c[2]), "+f"(c[3])
        : "r"(a[0]), "r"(a[1]), "r"(a[2]), "r"(a[3]), "r"(b[0]), "r"(b[1]));
}
__device__ __forceinline__ void ldm4(unsigned* r, uint32_t a) {
    asm volatile("ldmatrix.sync.aligned.m8n8.x4.shared.b16 {%0,%1,%2,%3}, [%4];"
        : "=r"(r[0]), "=r"(r[1]), "=r"(r[2]), "=r"(r[3]) : "r"(a));
}
__device__ __forceinline__ void ldm4t(unsigned* r, uint32_t a) {
    asm volatile("ldmatrix.sync.aligned.m8n8.x4.trans.shared.b16 {%0,%1,%2,%3}, [%4];"
        : "=r"(r[0]), "=r"(r[1]), "=r"(r[2]), "=r"(r[3]) : "r"(a));
}
__device__ __forceinline__ unsigned packh2(float a, float b) {
    __half2 hv = __floats2half2_rn(a, b);
    return *(unsigned*)&hv;
}

// ---------------- pack / mask (unchanged, passing) ---------------------------
__global__ void pack_kernel(const float* __restrict__ adj, const float* __restrict__ dist) {
    unsigned e = blockIdx.x * 256u + threadIdx.x;
    unsigned j = e & (L_ - 1u), i = (e >> 10) & (L_ - 1u);
    bool ab = (adj[e] != 0.0f) && (i != 0u) && (j != 0u);
    unsigned aw = __ballot_sync(0xffffffffu, ab);
    unsigned dw = __ballot_sync(0xffffffffu, dist[e] > 0.0f);
    if ((threadIdx.x & 31u) == 0u) { g_adjbits[e >> 5] = aw; g_distbits[e >> 5] = dw; }
}

__global__ void mask_kernel() {
    const int b = blockIdx.z, i0 = blockIdx.y * 32, j0 = blockIdx.x * 32;
    __shared__ unsigned Ai[32][33], Aj[32][33];
    const int t = threadIdx.x;
#pragma unroll
    for (int k = 0; k < 4; k++) {
        int pos = t + k * 256, r = pos >> 5, w = pos & 31;
        Ai[r][w] = g_adjbits[((b << 10) + i0 + r) * 32 + w];
        Aj[r][w] = g_adjbits[((b << 10) + j0 + r) * 32 + w];
    }
    __syncthreads();
    const int il = t >> 3, jb = (t & 7) << 2, ig = i0 + il;
    const unsigned di = g_distbits[((b << 10) + ig) * 32 + (j0 >> 5)];
    unsigned sbits = 0u;
    for (int w = 0; w < 32; w++) {
        unsigned ai = Ai[il][w];
#pragma unroll
        for (int jj = 0; jj < 4; jj++)
            if (ai & Aj[jb + jj][w]) sbits |= (1u << jj);
        if (sbits == 0xFu) break;
    }
    unsigned word = 0u;
#pragma unroll
    for (int jj = 0; jj < 4; jj++) {
        int jl = jb + jj;
        unsigned fwd = (Ai[il][j0 >> 5] >> jl) & 1u;
        unsigned bwd = (Aj[jl][i0 >> 5] >> il) & 1u;
        unsigned dfw = (di >> jl) & 1u;
        unsigned dbw = (g_distbits[((b << 10) + j0 + jl) * 32 + (i0 >> 5)] >> il) & 1u;
        unsigned st = (sbits >> jj) & 1u;
        word |= (fwd | (bwd << 1) | (dfw << 2) | (dbw << 3) | (st << 4)) << (8 * jj);
    }
    *reinterpret_cast<unsigned*>(g_mask + (((size_t)((b << 10) + ig)) << 10) + j0 + jb) = word;
}

// ---------------- splits -------------------------------------------------------
__global__ void split_x(const float* __restrict__ x) {
    int i = blockIdx.x * 256 + threadIdx.x;
    g_xh[i] = __float2half_rn(x[i]);
}

// coalesced smem tile transpose: w[K][N] -> wT[N][K] fp16
__global__ void split_w(const float* __restrict__ wq, const float* __restrict__ wp) {
    __shared__ float tile[32][33];
    int bid = blockIdx.x;
    const float* src; __half* dh; int N;
    if (bid < 768) { src = wq; dh = g_wqT; N = 1536; }
    else           { bid -= 768; src = wp; dh = g_wpT; N = 512; }
    int tn = N >> 5;
    int k0 = (bid / tn) * 32, n0 = (bid % tn) * 32;
    int c = threadIdx.x & 31, r0 = threadIdx.x >> 5;
#pragma unroll
    for (int p = 0; p < 4; p++) {
        int r = r0 + p * 8;
        tile[r][c] = src[(size_t)(k0 + r) * N + n0 + c];
    }
    __syncthreads();
#pragma unroll
    for (int p = 0; p < 4; p++) {
        int r = r0 + p * 8;
        dh[(size_t)(n0 + r) * 512 + k0 + c] = __float2half_rn(tile[c][r]);
    }
}

// ---------------- fp16 GEMM: 128x128 CTA tile, K=512, 3-stage cp.async --------
// stage s at s*32768: Ah 0, Bh 16K (each 128x64 fp16, SW128)
#define GDYN (98304 + 1024)
__global__ void __launch_bounds__(256) mm_kernel(int mode, float* __restrict__ out) {
    extern __shared__ char raw[];
    uint32_t rb = smem_u32(raw);
    char* sm = raw + ((1024u - (rb & 1023u)) & 1023u);
    const uint32_t sb = smem_u32(sm);
    const int t = threadIdx.x, lane = t & 31, wid = t >> 5;
    const int wm = wid & 3, wn = wid >> 2;
    const int n0 = blockIdx.x * 128, m0 = blockIdx.y * 128;

    const __half *Ah, *Bh;
    if (mode == 0) { Ah = g_xh;  Bh = g_wqT; }
    else           { Ah = g_aoh; Bh = g_wpT; }

    float C[2][8][4];
#pragma unroll
    for (int m = 0; m < 2; m++)
#pragma unroll
        for (int f = 0; f < 8; f++)
#pragma unroll
            for (int c = 0; c < 4; c++) C[m][f][c] = 0.0f;

    const int a_row = wm * 32 + (lane & 15);
    const int a_k   = (lane >> 4) * 8;
    const int b_row = wn * 64 + ((lane >> 4) << 3) + (lane & 7);
    const int b_k   = ((lane >> 3) & 1) * 8;

    auto pf = [&](int kc, uint32_t stb) {
#pragma unroll
        for (int i = 0; i < 4; i++) {
            int pos = t + i * 256, row = pos >> 3, cs = pos & 7;
            unsigned off = SW128((unsigned)(row * 128 + cs * 16));
            size_t ga = (size_t)(m0 + row) * 512 + kc * 64 + cs * 8;
            size_t gb = (size_t)(n0 + row) * 512 + kc * 64 + cs * 8;
            CPA(stb + off,         Ah + ga);
            CPA(stb + 16384 + off, Bh + gb);
        }
    };
    pf(0, sb); CPC();
    pf(1, sb + 32768u); CPC();

    for (int kc = 0; kc < 8; kc++) {
        if (kc < 6) {
            pf(kc + 2, sb + (unsigned)((kc + 2) % 3) * 32768u);
            CPC(); CPW(2);
        } else if (kc == 6) CPW(1);
        else CPW(0);
        __syncthreads();
        const uint32_t base = sb + (unsigned)(kc % 3) * 32768u;
#pragma unroll
        for (int ks = 0; ks < 4; ks++) {
            unsigned ah[2][4];
#pragma unroll
            for (int mf = 0; mf < 2; mf++) {
                unsigned off = SW128((unsigned)((a_row + mf * 16) * 128 + (a_k + ks * 16) * 2));
                ldm4(ah[mf], base + off);
            }
#pragma unroll
            for (int nf4 = 0; nf4 < 4; nf4++) {
                unsigned off = SW128((unsigned)((b_row + nf4 * 16) * 128 + (b_k + ks * 16) * 2));
                unsigned bh[4];
                ldm4(bh, base + 16384 + off);
#pragma unroll
                for (int mf = 0; mf < 2; mf++) {
                    mma_f16(C[mf][2 * nf4], ah[mf], bh);
                    mma_f16(C[mf][2 * nf4 + 1], ah[mf], bh + 2);
                }
            }
        }
        __syncthreads();
    }

    const int rq = lane >> 2, q2 = 2 * (lane & 3);
    if (mode == 1) {
#pragma unroll
        for (int mf = 0; mf < 2; mf++)
#pragma unroll
            for (int f = 0; f < 8; f++) {
                int row = m0 + wm * 32 + mf * 16 + rq;
                int col = n0 + wn * 64 + f * 8 + q2;
                float2 v0; v0.x = C[mf][f][0]; v0.y = C[mf][f][1];
                float2 v1; v1.x = C[mf][f][2]; v1.y = C[mf][f][3];
                *(float2*)(out + (size_t)row * 512 + col) = v0;
                *(float2*)(out + (size_t)(row + 8) * 512 + col) = v1;
            }
    } else {
        int part = n0 >> 9;
        int h = ((n0 + wn * 64) >> 6) & 7;
        __half* dst = (part == 0) ? g_qh : (part == 1) ? g_kh : g_vh;
        float sc = (part == 0) ? 0.125f : 1.0f;
        int bb = m0 >> 10, lbase = (m0 & 1023) + wm * 32;
#pragma unroll
        for (int mf = 0; mf < 2; mf++)
#pragma unroll
            for (int f = 0; f < 8; f++) {
                int ll = lbase + mf * 16 + rq;
                size_t base = ((size_t)(bb * 8 + h) * 1024 + ll) * 64 + f * 8 + q2;
                *(unsigned*)(dst + base)          = packh2(C[mf][f][0] * sc, C[mf][f][1] * sc);
                *(unsigned*)(dst + base + 8 * 64) = packh2(C[mf][f][2] * sc, C[mf][f][3] * sc);
            }
    }
}

// ---------------- attention: fp16 flash, 256 thr / 128 q-rows, 3-stage --------
// stage s at s*16384: Kh 0, Vh 8K (each 64x64 fp16, SW128)  [round-8 winner]
#define ADYN (49152 + 1024)
__global__ void __launch_bounds__(256, 2) attn_mma(const float* __restrict__ gamma) {
    extern __shared__ char raw[];
    uint32_t rb = smem_u32(raw);
    char* sm = raw + ((1024u - (rb & 1023u)) & 1023u);
    const uint32_t sb = smem_u32(sm);
    const int t = threadIdx.x, lane = t & 31, wid = t >> 5;
    const int b = blockIdx.z, h = blockIdx.y, i0 = blockIdx.x * 128;
    const int bh = b * H_ + h;
    const int rq = lane >> 2, q2 = 2 * (lane & 3);

    float tv = 0.0f;
#pragma unroll
    for (int kk = 0; kk < 5; kk++)
        if ((lane >> kk) & 1) tv += gamma[h * 5 + kk];

    // stage Q (128x64 fp16) into stage0, build A-fragments in registers
#pragma unroll
    for (int i = 0; i < 4; i++) {
        int pos = t + i * 256, row = pos >> 3, cs = pos & 7;
        unsigned off = SW128((unsigned)(row * 128 + cs * 16));
        size_t g = ((size_t)bh * L_ + i0 + row) * 64 + cs * 8;
        *(uint4*)(sm + off) = *(const uint4*)(g_qh + g);
    }
    __syncthreads();
    unsigned qh[4][4];
    {
        int arow = wid * 16 + (lane & 15);
        int ak = (lane >> 4) * 8;
#pragma unroll
        for (int ks = 0; ks < 4; ks++) {
            unsigned off = SW128((unsigned)(arow * 128 + (ak + ks * 16) * 2));
            ldm4(qh[ks], sb + off);
        }
    }
    __syncthreads();

    auto pf = [&](int jtile, uint32_t stb) {
#pragma unroll
        for (int i = 0; i < 2; i++) {
            int pos = t + i * 256, row = pos >> 3, cs = pos & 7;
            unsigned off = SW128((unsigned)(row * 128 + cs * 16));
            size_t g = ((size_t)bh * L_ + jtile * 64 + row) * 64 + cs * 8;
            CPA(stb + off,        g_kh + g);
            CPA(stb + 8192 + off, g_vh + g);
        }
    };
    pf(0, sb); CPC();
    pf(1, sb + 16384u); CPC();

    float O[8][4];
#pragma unroll
    for (int f = 0; f < 8; f++)
#pragma unroll
        for (int c = 0; c < 4; c++) O[f][c] = 0.0f;
    float m0r = -1e30f, m1r = -1e30f, l0r = 0.0f, l1r = 0.0f;

    const int ig0 = i0 + wid * 16 + rq;
    const unsigned char* mr0 = g_mask + ((size_t)b << 20) + (size_t)ig0 * 1024;
    const unsigned char* mr1 = mr0 + 8 * 1024;

    const int kb_row = ((lane >> 4) << 3) + (lane & 7);
    const int kb_k   = ((lane >> 3) & 1) * 8;
    const int vb_j   = ((lane >> 3) & 1) * 8 + (lane & 7);
    const int vb_d   = (lane >> 4) * 8;

    int stg = 0;
    for (int jt = 0; jt < 16; jt++) {
        if (jt < 14) {
            int s2 = (jt + 2) % 3;
            pf(jt + 2, sb + (unsigned)s2 * 16384u);
            CPC(); CPW(2);
        } else if (jt == 14) CPW(1);
        else CPW(0);
        __syncthreads();
        const uint32_t base = sb + (unsigned)stg * 16384u;
        stg = (stg + 1 == 3) ? 0 : stg + 1;
        const int j0 = jt * 64;

        // S = Q K^T
        float S[8][4];
#pragma unroll
        for (int f = 0; f < 8; f++)
#pragma unroll
            for (int c = 0; c < 4; c++) S[f][c] = 0.0f;
#pragma unroll
        for (int ks = 0; ks < 4; ks++) {
#pragma unroll
            for (int nf4 = 0; nf4 < 4; nf4++) {
                unsigned off = SW128((unsigned)((kb_row + nf4 * 16) * 128 + (kb_k + ks * 16) * 2));
                unsigned bhf[4];
                ldm4(bhf, base + off);
                mma_f16(S[2 * nf4], qh[ks], bhf);
                mma_f16(S[2 * nf4 + 1], qh[ks], bhf + 2);
            }
        }

        // bias + online softmax (rows rq, rq+8)
        float mx0 = -1e30f, mx1 = -1e30f;
#pragma unroll
        for (int f = 0; f < 8; f++) {
            int cb = j0 + f * 8 + q2;
            unsigned short w0 = *(const unsigned short*)(mr0 + cb);
            unsigned short w1 = *(const unsigned short*)(mr1 + cb);
            S[f][0] += __shfl_sync(0xffffffffu, tv, w0 & 31u);
            S[f][1] += __shfl_sync(0xffffffffu, tv, (w0 >> 8) & 31u);
            S[f][2] += __shfl_sync(0xffffffffu, tv, w1 & 31u);
            S[f][3] += __shfl_sync(0xffffffffu, tv, (w1 >> 8) & 31u);
            mx0 = fmaxf(mx0, fmaxf(S[f][0], S[f][1]));
            mx1 = fmaxf(mx1, fmaxf(S[f][2], S[f][3]));
        }
        mx0 = fmaxf(mx0, __shfl_xor_sync(0xffffffffu, mx0, 1));
        mx0 = fmaxf(mx0, __shfl_xor_sync(0xffffffffu, mx0, 2));
        mx1 = fmaxf(mx1, __shfl_xor_sync(0xffffffffu, mx1, 1));
        mx1 = fmaxf(mx1, __shfl_xor_sync(0xffffffffu, mx1, 2));
        float nm0 = fmaxf(m0r, mx0), nm1 = fmaxf(m1r, mx1);
        float fac0 = __expf(m0r - nm0), fac1 = __expf(m1r - nm1);
        m0r = nm0; m1r = nm1;
        float rs0 = 0.0f, rs1 = 0.0f;
        unsigned ph01[8], ph23[8];
#pragma unroll
        for (int f = 0; f < 8; f++) {
            S[f][0] = __expf(S[f][0] - nm0); S[f][1] = __expf(S[f][1] - nm0);
            S[f][2] = __expf(S[f][2] - nm1); S[f][3] = __expf(S[f][3] - nm1);
            rs0 += S[f][0] + S[f][1];
            rs1 += S[f][2] + S[f][3];
            ph01[f] = packh2(S[f][0], S[f][1]);
            ph23[f] = packh2(S[f][2], S[f][3]);
            O[f][0] *= fac0; O[f][1] *= fac0;
            O[f][2] *= fac1; O[f][3] *= fac1;
        }
        rs0 += __shfl_xor_sync(0xffffffffu, rs0, 1);
        rs0 += __shfl_xor_sync(0xffffffffu, rs0, 2);
        rs1 += __shfl_xor_sync(0xffffffffu, rs1, 1);
        rs1 += __shfl_xor_sync(0xffffffffu, rs1, 2);
        l0r = l0r * fac0 + rs0;
        l1r = l1r * fac1 + rs1;

        // O += P V
#pragma unroll
        for (int ks = 0; ks < 4; ks++) {
            unsigned ah[4] = { ph01[2 * ks], ph23[2 * ks], ph01[2 * ks + 1], ph23[2 * ks + 1] };
#pragma unroll
            for (int nf4 = 0; nf4 < 4; nf4++) {
                unsigned off = SW128((unsigned)((vb_j + ks * 16) * 128 + (vb_d + nf4 * 16) * 2));
                unsigned bvh[4];
                ldm4t(bvh, base + 8192 + off);
                mma_f16(O[2 * nf4], ah, bvh);
                mma_f16(O[2 * nf4 + 1], ah, bvh + 2);
            }
        }
        __syncthreads();
    }

    // epilogue
    float inv0 = 1.0f / l0r, inv1 = 1.0f / l1r;
    size_t base0 = ((size_t)(b << 10) + ig0) * 512 + h * 64;
    size_t base1 = base0 + 8 * 512;
#pragma unroll
    for (int f = 0; f < 8; f++) {
        *(unsigned*)(g_aoh + base0 + f * 8 + q2) = packh2(O[f][0] * inv0, O[f][1] * inv0);
        *(unsigned*)(g_aoh + base1 + f * 8 + q2) = packh2(O[f][2] * inv1, O[f][3] * inv1);
    }
}

// ---------------- launch --------------------------------------------------------
extern "C" void kernel_launch(void* const* d_in, const int* in_sizes, int n_in,
                              void* d_out, int out_size) {
    const float* x      = (const float*)d_in[0];
    const float* adj    = (const float*)d_in[1];
    const float* dist   = (const float*)d_in[2];
    const float* w_qkv  = (const float*)d_in[3];
    const float* w_proj = (const float*)d_in[4];
    const float* gamma  = (const float*)d_in[5];
    float* out = (float*)d_out;

    cudaFuncSetAttribute(mm_kernel, cudaFuncAttributeMaxDynamicSharedMemorySize, GDYN);
    cudaFuncSetAttribute(attn_mma, cudaFuncAttributeMaxDynamicSharedMemorySize, ADYN);

    pack_kernel<<<(B_ * L_ * L_) / 256, 256>>>(adj, dist);
    mask_kernel<<<dim3(L_ / 32, L_ / 32, B_), 256>>>();
    split_x<<<(M_TOT * C_) / 256, 256>>>(x);
    split_w<<<768 + 256, 256>>>(w_qkv, w_proj);
    mm_kernel<<<dim3(12, 64), 256, GDYN>>>(0, nullptr);   // qkv
    attn_mma<<<dim3(L_ / 128, H_, B_), 256, ADYN>>>(gamma);
    mm_kernel<<<dim3(4, 64), 256, GDYN>>>(1, out);        // proj
}

// round 10
// speedup vs baseline: 4.7571x; 1.0376x over previous
#include <cuda_runtime.h>
#include <cuda_fp16.h>
#include <cstdint>

#define B_ 8
#define L_ 1024
#define C_ 512
#define H_ 8
#define D_ 64
#define M_TOT (B_*L_)

// ---------------- static device scratch -------------------------------------
__device__ unsigned g_adjbits[B_*L_*(L_/32)];
__device__ unsigned g_distbits[B_*L_*(L_/32)];
__device__ unsigned char g_mask[(size_t)B_*L_*L_];

__device__ __half g_xh[M_TOT*C_];
__device__ __half g_wqT[3*C_*C_];   // [1536][512] fp16
__device__ __half g_wpT[C_*C_];     // [512][512]  fp16
__device__ __half g_qh[B_*H_*L_*D_];  // pre-scaled (1/8)*log2e
__device__ __half g_kh[B_*H_*L_*D_];
__device__ __half g_vh[B_*H_*L_*D_];
__device__ __half g_aoh[M_TOT*C_];

// ---------------- host-side stream fork (static init, no device mem) ---------
namespace {
struct AuxStream {
    cudaStream_t s = nullptr;
    cudaEvent_t fork = nullptr, join = nullptr;
    AuxStream() {
        cudaStreamCreateWithFlags(&s, cudaStreamNonBlocking);
        cudaEventCreateWithFlags(&fork, cudaEventDisableTiming);
        cudaEventCreateWithFlags(&join, cudaEventDisableTiming);
    }
};
AuxStream g_aux;
}

// ---------------- device helpers ----------------------------------------------
__device__ __forceinline__ uint32_t smem_u32(const void* p) {
    uint32_t a;
    asm("{ .reg .u64 t; cvta.to.shared.u64 t, %1; cvt.u32.u64 %0, t; }" : "=r"(a) : "l"(p));
    return a;
}
#define SW128(o) ((o) ^ (((o) >> 3) & 0x70))

#define CPA(dst, src) asm volatile("cp.async.cg.shared.global [%0], [%1], 16;" :: "r"(dst), "l"(src))
#define CPC()  asm volatile("cp.async.commit_group;")
#define CPW(n) asm volatile("cp.async.wait_group %0;" :: "n"(n))

__device__ __forceinline__ void mma_f16(float* c, const unsigned* a, const unsigned* b) {
    asm volatile("mma.sync.aligned.m16n8k16.row.col.f32.f16.f16.f32 "
        "{%0,%1,%2,%3}, {%4,%5,%6,%7}, {%8,%9}, {%0,%1,%2,%3};"
        : "+f"(c[0]), "+f"(c[1]), "+f"(c[2]), "+f"(c[3])
        : "r"(a[0]), "r"(a[1]), "r"(a[2]), "r"(a[3]), "r"(b[0]), "r"(b[1]));
}
__device__ __forceinline__ void ldm4(unsigned* r, uint32_t a) {
    asm volatile("ldmatrix.sync.aligned.m8n8.x4.shared.b16 {%0,%1,%2,%3}, [%4];"
        : "=r"(r[0]), "=r"(r[1]), "=r"(r[2]), "=r"(r[3]) : "r"(a));
}
__device__ __forceinline__ void ldm4t(unsigned* r, uint32_t a) {
    asm volatile("ldmatrix.sync.aligned.m8n8.x4.trans.shared.b16 {%0,%1,%2,%3}, [%4];"
        : "=r"(r[0]), "=r"(r[1]), "=r"(r[2]), "=r"(r[3]) : "r"(a));
}
__device__ __forceinline__ unsigned packh2(float a, float b) {
    __half2 hv = __floats2half2_rn(a, b);
    return *(unsigned*)&hv;
}
__device__ __forceinline__ float ex2(float x) {
    float y;
    asm("ex2.approx.ftz.f32 %0, %1;" : "=f"(y) : "f"(x));
    return y;
}

// ---------------- pack / mask (unchanged, passing) ---------------------------
__global__ void pack_kernel(const float* __restrict__ adj, const float* __restrict__ dist) {
    unsigned e = blockIdx.x * 256u + threadIdx.x;
    unsigned j = e & (L_ - 1u), i = (e >> 10) & (L_ - 1u);
    bool ab = (adj[e] != 0.0f) && (i != 0u) && (j != 0u);
    unsigned aw = __ballot_sync(0xffffffffu, ab);
    unsigned dw = __ballot_sync(0xffffffffu, dist[e] > 0.0f);
    if ((threadIdx.x & 31u) == 0u) { g_adjbits[e >> 5] = aw; g_distbits[e >> 5] = dw; }
}

__global__ void mask_kernel() {
    const int b = blockIdx.z, i0 = blockIdx.y * 32, j0 = blockIdx.x * 32;
    __shared__ unsigned Ai[32][33], Aj[32][33];
    const int t = threadIdx.x;
#pragma unroll
    for (int k = 0; k < 4; k++) {
        int pos = t + k * 256, r = pos >> 5, w = pos & 31;
        Ai[r][w] = g_adjbits[((b << 10) + i0 + r) * 32 + w];
        Aj[r][w] = g_adjbits[((b << 10) + j0 + r) * 32 + w];
    }
    __syncthreads();
    const int il = t >> 3, jb = (t & 7) << 2, ig = i0 + il;
    const unsigned di = g_distbits[((b << 10) + ig) * 32 + (j0 >> 5)];
    unsigned sbits = 0u;
    for (int w = 0; w < 32; w++) {
        unsigned ai = Ai[il][w];
#pragma unroll
        for (int jj = 0; jj < 4; jj++)
            if (ai & Aj[jb + jj][w]) sbits |= (1u << jj);
        if (sbits == 0xFu) break;
    }
    unsigned word = 0u;
#pragma unroll
    for (int jj = 0; jj < 4; jj++) {
        int jl = jb + jj;
        unsigned fwd = (Ai[il][j0 >> 5] >> jl) & 1u;
        unsigned bwd = (Aj[jl][i0 >> 5] >> il) & 1u;
        unsigned dfw = (di >> jl) & 1u;
        unsigned dbw = (g_distbits[((b << 10) + j0 + jl) * 32 + (i0 >> 5)] >> il) & 1u;
        unsigned st = (sbits >> jj) & 1u;
        word |= (fwd | (bwd << 1) | (dfw << 2) | (dbw << 3) | (st << 4)) << (8 * jj);
    }
    *reinterpret_cast<unsigned*>(g_mask + (((size_t)((b << 10) + ig)) << 10) + j0 + jb) = word;
}

// ---------------- splits -------------------------------------------------------
__global__ void split_x(const float* __restrict__ x) {
    int i = blockIdx.x * 256 + threadIdx.x;
    g_xh[i] = __float2half_rn(x[i]);
}

__global__ void split_w(const float* __restrict__ wq, const float* __restrict__ wp) {
    __shared__ float tile[32][33];
    int bid = blockIdx.x;
    const float* src; __half* dh; int N;
    if (bid < 768) { src = wq; dh = g_wqT; N = 1536; }
    else           { bid -= 768; src = wp; dh = g_wpT; N = 512; }
    int tn = N >> 5;
    int k0 = (bid / tn) * 32, n0 = (bid % tn) * 32;
    int c = threadIdx.x & 31, r0 = threadIdx.x >> 5;
#pragma unroll
    for (int p = 0; p < 4; p++) {
        int r = r0 + p * 8;
        tile[r][c] = src[(size_t)(k0 + r) * N + n0 + c];
    }
    __syncthreads();
#pragma unroll
    for (int p = 0; p < 4; p++) {
        int r = r0 + p * 8;
        dh[(size_t)(n0 + r) * 512 + k0 + c] = __float2half_rn(tile[c][r]);
    }
}

// ---------------- fp16 GEMM: 128x128 CTA tile, K=512, 3-stage, 1 barrier/iter --
// stage s at s*32768: Ah 0, Bh 16K (each 128x64 fp16, SW128)
#define GDYN (98304 + 1024)
__global__ void __launch_bounds__(256) mm_kernel(int mode, float* __restrict__ out) {
    extern __shared__ char raw[];
    uint32_t rb = smem_u32(raw);
    char* sm = raw + ((1024u - (rb & 1023u)) & 1023u);
    const uint32_t sb = smem_u32(sm);
    const int t = threadIdx.x, lane = t & 31, wid = t >> 5;
    const int wm = wid & 3, wn = wid >> 2;
    const int n0 = blockIdx.x * 128, m0 = blockIdx.y * 128;

    const __half *Ah, *Bh;
    if (mode == 0) { Ah = g_xh;  Bh = g_wqT; }
    else           { Ah = g_aoh; Bh = g_wpT; }

    float C[2][8][4];
#pragma unroll
    for (int m = 0; m < 2; m++)
#pragma unroll
        for (int f = 0; f < 8; f++)
#pragma unroll
            for (int c = 0; c < 4; c++) C[m][f][c] = 0.0f;

    const int a_row = wm * 32 + (lane & 15);
    const int a_k   = (lane >> 4) * 8;
    const int b_row = wn * 64 + ((lane >> 4) << 3) + (lane & 7);
    const int b_k   = ((lane >> 3) & 1) * 8;

    auto pf = [&](int kc, uint32_t stb) {
#pragma unroll
        for (int i = 0; i < 4; i++) {
            int pos = t + i * 256, row = pos >> 3, cs = pos & 7;
            unsigned off = SW128((unsigned)(row * 128 + cs * 16));
            size_t ga = (size_t)(m0 + row) * 512 + kc * 64 + cs * 8;
            size_t gb = (size_t)(n0 + row) * 512 + kc * 64 + cs * 8;
            CPA(stb + off,         Ah + ga);
            CPA(stb + 16384 + off, Bh + gb);
        }
    };
    pf(0, sb); CPC();
    pf(1, sb + 32768u); CPC();

    for (int kc = 0; kc < 8; kc++) {
        if (kc < 7) CPW(1); else CPW(0);
        __syncthreads();
        if (kc < 6) { pf(kc + 2, sb + (unsigned)((kc + 2) % 3) * 32768u); CPC(); }
        const uint32_t base = sb + (unsigned)(kc % 3) * 32768u;
#pragma unroll
        for (int ks = 0; ks < 4; ks++) {
            unsigned ah[2][4];
#pragma unroll
            for (int mf = 0; mf < 2; mf++) {
                unsigned off = SW128((unsigned)((a_row + mf * 16) * 128 + (a_k + ks * 16) * 2));
                ldm4(ah[mf], base + off);
            }
#pragma unroll
            for (int nf4 = 0; nf4 < 4; nf4++) {
                unsigned off = SW128((unsigned)((b_row + nf4 * 16) * 128 + (b_k + ks * 16) * 2));
                unsigned bh[4];
                ldm4(bh, base + 16384 + off);
#pragma unroll
                for (int mf = 0; mf < 2; mf++) {
                    mma_f16(C[mf][2 * nf4], ah[mf], bh);
                    mma_f16(C[mf][2 * nf4 + 1], ah[mf], bh + 2);
                }
            }
        }
    }

    const int rq = lane >> 2, q2 = 2 * (lane & 3);
    if (mode == 1) {
#pragma unroll
        for (int mf = 0; mf < 2; mf++)
#pragma unroll
            for (int f = 0; f < 8; f++) {
                int row = m0 + wm * 32 + mf * 16 + rq;
                int col = n0 + wn * 64 + f * 8 + q2;
                float2 v0; v0.x = C[mf][f][0]; v0.y = C[mf][f][1];
                float2 v1; v1.x = C[mf][f][2]; v1.y = C[mf][f][3];
                *(float2*)(out + (size_t)row * 512 + col) = v0;
                *(float2*)(out + (size_t)(row + 8) * 512 + col) = v1;
            }
    } else {
        int part = n0 >> 9;
        int h = ((n0 + wn * 64) >> 6) & 7;
        __half* dst = (part == 0) ? g_qh : (part == 1) ? g_kh : g_vh;
        // q pre-scale folds softmax 1/sqrt(D) AND log2(e) for ex2-based softmax
        float sc = (part == 0) ? 0.125f * 1.44269504f : 1.0f;
        int bb = m0 >> 10, lbase = (m0 & 1023) + wm * 32;
#pragma unroll
        for (int mf = 0; mf < 2; mf++)
#pragma unroll
            for (int f = 0; f < 8; f++) {
                int ll = lbase + mf * 16 + rq;
                size_t base = ((size_t)(bb * 8 + h) * 1024 + ll) * 64 + f * 8 + q2;
                *(unsigned*)(dst + base)          = packh2(C[mf][f][0] * sc, C[mf][f][1] * sc);
                *(unsigned*)(dst + base + 8 * 64) = packh2(C[mf][f][2] * sc, C[mf][f][3] * sc);
            }
    }
}

// ---------------- attention: fp16 flash, 256 thr / 128 q-rows, 3-stage,
//                  1 barrier/tile, base-2 softmax
// stage s at s*16384: Kh 0, Vh 8K (each 64x64 fp16, SW128)
#define ADYN (49152 + 1024)
__global__ void __launch_bounds__(256, 2) attn_mma(const float* __restrict__ gamma) {
    extern __shared__ char raw[];
    uint32_t rb = smem_u32(raw);
    char* sm = raw + ((1024u - (rb & 1023u)) & 1023u);
    const uint32_t sb = smem_u32(sm);
    const int t = threadIdx.x, lane = t & 31, wid = t >> 5;
    const int b = blockIdx.z, h = blockIdx.y, i0 = blockIdx.x * 128;
    const int bh = b * H_ + h;
    const int rq = lane >> 2, q2 = 2 * (lane & 3);

    float tv = 0.0f;
#pragma unroll
    for (int kk = 0; kk < 5; kk++)
        if ((lane >> kk) & 1) tv += gamma[h * 5 + kk];
    tv *= 1.44269504f;   // base-2 softmax domain

    // stage Q (128x64 fp16) into stage0, build A-fragments in registers
#pragma unroll
    for (int i = 0; i < 4; i++) {
        int pos = t + i * 256, row = pos >> 3, cs = pos & 7;
        unsigned off = SW128((unsigned)(row * 128 + cs * 16));
        size_t g = ((size_t)bh * L_ + i0 + row) * 64 + cs * 8;
        *(uint4*)(sm + off) = *(const uint4*)(g_qh + g);
    }
    __syncthreads();
    unsigned qh[4][4];
    {
        int arow = wid * 16 + (lane & 15);
        int ak = (lane >> 4) * 8;
#pragma unroll
        for (int ks = 0; ks < 4; ks++) {
            unsigned off = SW128((unsigned)(arow * 128 + (ak + ks * 16) * 2));
            ldm4(qh[ks], sb + off);
        }
    }
    __syncthreads();

    auto pf = [&](int jtile, uint32_t stb) {
#pragma unroll
        for (int i = 0; i < 2; i++) {
            int pos = t + i * 256, row = pos >> 3, cs = pos & 7;
            unsigned off = SW128((unsigned)(row * 128 + cs * 16));
            size_t g = ((size_t)bh * L_ + jtile * 64 + row) * 64 + cs * 8;
            CPA(stb + off,        g_kh + g);
            CPA(stb + 8192 + off, g_vh + g);
        }
    };
    pf(0, sb); CPC();
    pf(1, sb + 16384u); CPC();

    float O[8][4];
#pragma unroll
    for (int f = 0; f < 8; f++)
#pragma unroll
        for (int c = 0; c < 4; c++) O[f][c] = 0.0f;
    float m0r = -1e30f, m1r = -1e30f, l0r = 0.0f, l1r = 0.0f;

    const int ig0 = i0 + wid * 16 + rq;
    const unsigned char* mr0 = g_mask + ((size_t)b << 20) + (size_t)ig0 * 1024;
    const unsigned char* mr1 = mr0 + 8 * 1024;

    const int kb_row = ((lane >> 4) << 3) + (lane & 7);
    const int kb_k   = ((lane >> 3) & 1) * 8;
    const int vb_j   = ((lane >> 3) & 1) * 8 + (lane & 7);
    const int vb_d   = (lane >> 4) * 8;

    for (int jt = 0; jt < 16; jt++) {
        if (jt < 15) CPW(1); else CPW(0);
        __syncthreads();
        if (jt < 14) { pf(jt + 2, sb + (unsigned)((jt + 2) % 3) * 16384u); CPC(); }
        const uint32_t base = sb + (unsigned)(jt % 3) * 16384u;
        const int j0 = jt * 64;

        // S = Q K^T
        float S[8][4];
#pragma unroll
        for (int f = 0; f < 8; f++)
#pragma unroll
            for (int c = 0; c < 4; c++) S[f][c] = 0.0f;
#pragma unroll
        for (int ks = 0; ks < 4; ks++) {
#pragma unroll
            for (int nf4 = 0; nf4 < 4; nf4++) {
                unsigned off = SW128((unsigned)((kb_row + nf4 * 16) * 128 + (kb_k + ks * 16) * 2));
                unsigned bhf[4];
                ldm4(bhf, base + off);
                mma_f16(S[2 * nf4], qh[ks], bhf);
                mma_f16(S[2 * nf4 + 1], qh[ks], bhf + 2);
            }
        }

        // bias + online softmax (base-2 domain; rows rq, rq+8)
        float mx0 = -1e30f, mx1 = -1e30f;
#pragma unroll
        for (int f = 0; f < 8; f++) {
            int cb = j0 + f * 8 + q2;
            unsigned short w0 = *(const unsigned short*)(mr0 + cb);
            unsigned short w1 = *(const unsigned short*)(mr1 + cb);
            S[f][0] += __shfl_sync(0xffffffffu, tv, w0 & 31u);
            S[f][1] += __shfl_sync(0xffffffffu, tv, (w0 >> 8) & 31u);
            S[f][2] += __shfl_sync(0xffffffffu, tv, w1 & 31u);
            S[f][3] += __shfl_sync(0xffffffffu, tv, (w1 >> 8) & 31u);
            mx0 = fmaxf(mx0, fmaxf(S[f][0], S[f][1]));
            mx1 = fmaxf(mx1, fmaxf(S[f][2], S[f][3]));
        }
        mx0 = fmaxf(mx0, __shfl_xor_sync(0xffffffffu, mx0, 1));
        mx0 = fmaxf(mx0, __shfl_xor_sync(0xffffffffu, mx0, 2));
        mx1 = fmaxf(mx1, __shfl_xor_sync(0xffffffffu, mx1, 1));
        mx1 = fmaxf(mx1, __shfl_xor_sync(0xffffffffu, mx1, 2));
        float nm0 = fmaxf(m0r, mx0), nm1 = fmaxf(m1r, mx1);
        float fac0 = ex2(m0r - nm0), fac1 = ex2(m1r - nm1);
        m0r = nm0; m1r = nm1;
        float rs0 = 0.0f, rs1 = 0.0f;
        unsigned ph01[8], ph23[8];
#pragma unroll
        for (int f = 0; f < 8; f++) {
            S[f][0] = ex2(S[f][0] - nm0); S[f][1] = ex2(S[f][1] - nm0);
            S[f][2] = ex2(S[f][2] - nm1); S[f][3] = ex2(S[f][3] - nm1);
            rs0 += S[f][0] + S[f][1];
            rs1 += S[f][2] + S[f][3];
            ph01[f] = packh2(S[f][0], S[f][1]);
            ph23[f] = packh2(S[f][2], S[f][3]);
            O[f][0] *= fac0; O[f][1] *= fac0;
            O[f][2] *= fac1; O[f][3] *= fac1;
        }
        rs0 += __shfl_xor_sync(0xffffffffu, rs0, 1);
        rs0 += __shfl_xor_sync(0xffffffffu, rs0, 2);
        rs1 += __shfl_xor_sync(0xffffffffu, rs1, 1);
        rs1 += __shfl_xor_sync(0xffffffffu, rs1, 2);
        l0r = l0r * fac0 + rs0;
        l1r = l1r * fac1 + rs1;

        // O += P V
#pragma unroll
        for (int ks = 0; ks < 4; ks++) {
            unsigned ah[4] = { ph01[2 * ks], ph23[2 * ks], ph01[2 * ks + 1], ph23[2 * ks + 1] };
#pragma unroll
            for (int nf4 = 0; nf4 < 4; nf4++) {
                unsigned off = SW128((unsigned)((vb_j + ks * 16) * 128 + (vb_d + nf4 * 16) * 2));
                unsigned bvh[4];
                ldm4t(bvh, base + 8192 + off);
                mma_f16(O[2 * nf4], ah, bvh);
                mma_f16(O[2 * nf4 + 1], ah, bvh + 2);
            }
        }
    }

    // epilogue
    float inv0 = 1.0f / l0r, inv1 = 1.0f / l1r;
    size_t base0 = ((size_t)(b << 10) + ig0) * 512 + h * 64;
    size_t base1 = base0 + 8 * 512;
#pragma unroll
    for (int f = 0; f < 8; f++) {
        *(unsigned*)(g_aoh + base0 + f * 8 + q2) = packh2(O[f][0] * inv0, O[f][1] * inv0);
        *(unsigned*)(g_aoh + base1 + f * 8 + q2) = packh2(O[f][2] * inv1, O[f][3] * inv1);
    }
}

// ---------------- launch --------------------------------------------------------
extern "C" void kernel_launch(void* const* d_in, const int* in_sizes, int n_in,
                              void* d_out, int out_size) {
    const float* x      = (const float*)d_in[0];
    const float* adj    = (const float*)d_in[1];
    const float* dist   = (const float*)d_in[2];
    const float* w_qkv  = (const float*)d_in[3];
    const float* w_proj = (const float*)d_in[4];
    const float* gamma  = (const float*)d_in[5];
    float* out = (float*)d_out;

    cudaFuncSetAttribute(mm_kernel, cudaFuncAttributeMaxDynamicSharedMemorySize, GDYN);
    cudaFuncSetAttribute(attn_mma, cudaFuncAttributeMaxDynamicSharedMemorySize, ADYN);

    cudaStream_t ms = cudaStreamPerThread;

    // fork: bitmask chain on side stream, overlapped with split+qkv
    cudaEventRecord(g_aux.fork, ms);
    cudaStreamWaitEvent(g_aux.s, g_aux.fork, 0);
    pack_kernel<<<(B_ * L_ * L_) / 256, 256, 0, g_aux.s>>>(adj, dist);
    mask_kernel<<<dim3(L_ / 32, L_ / 32, B_), 256, 0, g_aux.s>>>();
    cudaEventRecord(g_aux.join, g_aux.s);

    split_x<<<(M_TOT * C_) / 256, 256, 0, ms>>>(x);
    split_w<<<768 + 256, 256, 0, ms>>>(w_qkv, w_proj);
    mm_kernel<<<dim3(12, 64), 256, GDYN, ms>>>(0, nullptr);   // qkv

    // join: attn needs both qkv outputs and the mask
    cudaStreamWaitEvent(ms, g_aux.join, 0);
    attn_mma<<<dim3(L_ / 128, H_, B_), 256, ADYN, ms>>>(gamma);
    mm_kernel<<<dim3(4, 64), 256, GDYN, ms>>>(1, out);        // proj
}

// round 11
// speedup vs baseline: 4.9439x; 1.0393x over previous
#include <cuda_runtime.h>
#include <cuda_fp16.h>
#include <cstdint>

#define B_ 8
#define L_ 1024
#define C_ 512
#define H_ 8
#define D_ 64
#define M_TOT (B_*L_)

// ---------------- static device scratch -------------------------------------
__device__ unsigned g_adjbits[B_*L_*(L_/32)];
__device__ unsigned g_distbits[B_*L_*(L_/32)];
__device__ unsigned char g_mask[(size_t)B_*L_*L_];

__device__ __half g_xh[M_TOT*C_];
__device__ __half g_wqT[3*C_*C_];   // [1536][512] fp16
__device__ __half g_wpT[C_*C_];     // [512][512]  fp16
__device__ __half g_qh[B_*H_*L_*D_];  // pre-scaled (1/8)*log2e
__device__ __half g_kh[B_*H_*L_*D_];
__device__ __half g_vh[B_*H_*L_*D_];
__device__ __half g_aoh[M_TOT*C_];

// ---------------- host-side stream fork (static init, no device mem) ---------
namespace {
struct AuxStream {
    cudaStream_t s = nullptr;
    cudaEvent_t fork = nullptr, join = nullptr;
    AuxStream() {
        cudaStreamCreateWithFlags(&s, cudaStreamNonBlocking);
        cudaEventCreateWithFlags(&fork, cudaEventDisableTiming);
        cudaEventCreateWithFlags(&join, cudaEventDisableTiming);
    }
};
AuxStream g_aux;
}

// ---------------- device helpers ----------------------------------------------
__device__ __forceinline__ uint32_t smem_u32(const void* p) {
    uint32_t a;
    asm("{ .reg .u64 t; cvta.to.shared.u64 t, %1; cvt.u32.u64 %0, t; }" : "=r"(a) : "l"(p));
    return a;
}
#define SW128(o) ((o) ^ (((o) >> 3) & 0x70))

#define CPA(dst, src) asm volatile("cp.async.cg.shared.global [%0], [%1], 16;" :: "r"(dst), "l"(src))
#define CPC()  asm volatile("cp.async.commit_group;")
#define CPW(n) asm volatile("cp.async.wait_group %0;" :: "n"(n))

__device__ __forceinline__ void mma_f16(float* c, const unsigned* a, const unsigned* b) {
    asm volatile("mma.sync.aligned.m16n8k16.row.col.f32.f16.f16.f32 "
        "{%0,%1,%2,%3}, {%4,%5,%6,%7}, {%8,%9}, {%0,%1,%2,%3};"
        : "+f"(c[0]), "+f"(c[1]), "+f"(c[2]), "+f"(c[3])
        : "r"(a[0]), "r"(a[1]), "r"(a[2]), "r"(a[3]), "r"(b[0]), "r"(b[1]));
}
__device__ __forceinline__ void ldm4(unsigned* r, uint32_t a) {
    asm volatile("ldmatrix.sync.aligned.m8n8.x4.shared.b16 {%0,%1,%2,%3}, [%4];"
        : "=r"(r[0]), "=r"(r[1]), "=r"(r[2]), "=r"(r[3]) : "r"(a));
}
__device__ __forceinline__ void ldm4t(unsigned* r, uint32_t a) {
    asm volatile("ldmatrix.sync.aligned.m8n8.x4.trans.shared.b16 {%0,%1,%2,%3}, [%4];"
        : "=r"(r[0]), "=r"(r[1]), "=r"(r[2]), "=r"(r[3]) : "r"(a));
}
__device__ __forceinline__ unsigned packh2(float a, float b) {
    __half2 hv = __floats2half2_rn(a, b);
    return *(unsigned*)&hv;
}
__device__ __forceinline__ float ex2(float x) {
    float y;
    asm("ex2.approx.ftz.f32 %0, %1;" : "=f"(y) : "f"(x));
    return y;
}
// two exponentials (base 2) in one MUFU op; output IS the fp16x2 P fragment
__device__ __forceinline__ unsigned h2ex2(unsigned x) {
    unsigned y;
    asm("ex2.approx.f16x2 %0, %1;" : "=r"(y) : "r"(x));
    return y;
}

// ---------------- pack / mask (unchanged, passing) ---------------------------
__global__ void pack_kernel(const float* __restrict__ adj, const float* __restrict__ dist) {
    unsigned e = blockIdx.x * 256u + threadIdx.x;
    unsigned j = e & (L_ - 1u), i = (e >> 10) & (L_ - 1u);
    bool ab = (adj[e] != 0.0f) && (i != 0u) && (j != 0u);
    unsigned aw = __ballot_sync(0xffffffffu, ab);
    unsigned dw = __ballot_sync(0xffffffffu, dist[e] > 0.0f);
    if ((threadIdx.x & 31u) == 0u) { g_adjbits[e >> 5] = aw; g_distbits[e >> 5] = dw; }
}

__global__ void mask_kernel() {
    const int b = blockIdx.z, i0 = blockIdx.y * 32, j0 = blockIdx.x * 32;
    __shared__ unsigned Ai[32][33], Aj[32][33];
    const int t = threadIdx.x;
#pragma unroll
    for (int k = 0; k < 4; k++) {
        int pos = t + k * 256, r = pos >> 5, w = pos & 31;
        Ai[r][w] = g_adjbits[((b << 10) + i0 + r) * 32 + w];
        Aj[r][w] = g_adjbits[((b << 10) + j0 + r) * 32 + w];
    }
    __syncthreads();
    const int il = t >> 3, jb = (t & 7) << 2, ig = i0 + il;
    const unsigned di = g_distbits[((b << 10) + ig) * 32 + (j0 >> 5)];
    unsigned sbits = 0u;
    for (int w = 0; w < 32; w++) {
        unsigned ai = Ai[il][w];
#pragma unroll
        for (int jj = 0; jj < 4; jj++)
            if (ai & Aj[jb + jj][w]) sbits |= (1u << jj);
        if (sbits == 0xFu) break;
    }
    unsigned word = 0u;
#pragma unroll
    for (int jj = 0; jj < 4; jj++) {
        int jl = jb + jj;
        unsigned fwd = (Ai[il][j0 >> 5] >> jl) & 1u;
        unsigned bwd = (Aj[jl][i0 >> 5] >> il) & 1u;
        unsigned dfw = (di >> jl) & 1u;
        unsigned dbw = (g_distbits[((b << 10) + j0 + jl) * 32 + (i0 >> 5)] >> il) & 1u;
        unsigned st = (sbits >> jj) & 1u;
        word |= (fwd | (bwd << 1) | (dfw << 2) | (dbw << 3) | (st << 4)) << (8 * jj);
    }
    *reinterpret_cast<unsigned*>(g_mask + (((size_t)((b << 10) + ig)) << 10) + j0 + jb) = word;
}

// ---------------- splits -------------------------------------------------------
__global__ void split_x(const float* __restrict__ x) {
    int i = blockIdx.x * 256 + threadIdx.x;
    g_xh[i] = __float2half_rn(x[i]);
}

__global__ void split_w(const float* __restrict__ wq, const float* __restrict__ wp) {
    __shared__ float tile[32][33];
    int bid = blockIdx.x;
    const float* src; __half* dh; int N;
    if (bid < 768) { src = wq; dh = g_wqT; N = 1536; }
    else           { bid -= 768; src = wp; dh = g_wpT; N = 512; }
    int tn = N >> 5;
    int k0 = (bid / tn) * 32, n0 = (bid % tn) * 32;
    int c = threadIdx.x & 31, r0 = threadIdx.x >> 5;
#pragma unroll
    for (int p = 0; p < 4; p++) {
        int r = r0 + p * 8;
        tile[r][c] = src[(size_t)(k0 + r) * N + n0 + c];
    }
    __syncthreads();
#pragma unroll
    for (int p = 0; p < 4; p++) {
        int r = r0 + p * 8;
        dh[(size_t)(n0 + r) * 512 + k0 + c] = __float2half_rn(tile[c][r]);
    }
}

// ---------------- fp16 GEMM: 128x128 CTA tile, K=512, 3-stage, 1 barrier/iter --
// stage s at s*32768: Ah 0, Bh 16K (each 128x64 fp16, SW128)
#define GDYN (98304 + 1024)
__global__ void __launch_bounds__(256) mm_kernel(int mode, float* __restrict__ out) {
    extern __shared__ char raw[];
    uint32_t rb = smem_u32(raw);
    char* sm = raw + ((1024u - (rb & 1023u)) & 1023u);
    const uint32_t sb = smem_u32(sm);
    const int t = threadIdx.x, lane = t & 31, wid = t >> 5;
    const int wm = wid & 3, wn = wid >> 2;
    const int n0 = blockIdx.x * 128, m0 = blockIdx.y * 128;

    const __half *Ah, *Bh;
    if (mode == 0) { Ah = g_xh;  Bh = g_wqT; }
    else           { Ah = g_aoh; Bh = g_wpT; }

    float C[2][8][4];
#pragma unroll
    for (int m = 0; m < 2; m++)
#pragma unroll
        for (int f = 0; f < 8; f++)
#pragma unroll
            for (int c = 0; c < 4; c++) C[m][f][c] = 0.0f;

    const int a_row = wm * 32 + (lane & 15);
    const int a_k   = (lane >> 4) * 8;
    const int b_row = wn * 64 + ((lane >> 4) << 3) + (lane & 7);
    const int b_k   = ((lane >> 3) & 1) * 8;

    auto pf = [&](int kc, uint32_t stb) {
#pragma unroll
        for (int i = 0; i < 4; i++) {
            int pos = t + i * 256, row = pos >> 3, cs = pos & 7;
            unsigned off = SW128((unsigned)(row * 128 + cs * 16));
            size_t ga = (size_t)(m0 + row) * 512 + kc * 64 + cs * 8;
            size_t gb = (size_t)(n0 + row) * 512 + kc * 64 + cs * 8;
            CPA(stb + off,         Ah + ga);
            CPA(stb + 16384 + off, Bh + gb);
        }
    };
    pf(0, sb); CPC();
    pf(1, sb + 32768u); CPC();

    for (int kc = 0; kc < 8; kc++) {
        if (kc < 7) CPW(1); else CPW(0);
        __syncthreads();
        if (kc < 6) { pf(kc + 2, sb + (unsigned)((kc + 2) % 3) * 32768u); CPC(); }
        const uint32_t base = sb + (unsigned)(kc % 3) * 32768u;
#pragma unroll
        for (int ks = 0; ks < 4; ks++) {
            unsigned ah[2][4];
#pragma unroll
            for (int mf = 0; mf < 2; mf++) {
                unsigned off = SW128((unsigned)((a_row + mf * 16) * 128 + (a_k + ks * 16) * 2));
                ldm4(ah[mf], base + off);
            }
#pragma unroll
            for (int nf4 = 0; nf4 < 4; nf4++) {
                unsigned off = SW128((unsigned)((b_row + nf4 * 16) * 128 + (b_k + ks * 16) * 2));
                unsigned bh[4];
                ldm4(bh, base + 16384 + off);
#pragma unroll
                for (int mf = 0; mf < 2; mf++) {
                    mma_f16(C[mf][2 * nf4], ah[mf], bh);
                    mma_f16(C[mf][2 * nf4 + 1], ah[mf], bh + 2);
                }
            }
        }
    }

    const int rq = lane >> 2, q2 = 2 * (lane & 3);
    if (mode == 1) {
#pragma unroll
        for (int mf = 0; mf < 2; mf++)
#pragma unroll
            for (int f = 0; f < 8; f++) {
                int row = m0 + wm * 32 + mf * 16 + rq;
                int col = n0 + wn * 64 + f * 8 + q2;
                float2 v0; v0.x = C[mf][f][0]; v0.y = C[mf][f][1];
                float2 v1; v1.x = C[mf][f][2]; v1.y = C[mf][f][3];
                *(float2*)(out + (size_t)row * 512 + col) = v0;
                *(float2*)(out + (size_t)(row + 8) * 512 + col) = v1;
            }
    } else {
        int part = n0 >> 9;
        int h = ((n0 + wn * 64) >> 6) & 7;
        __half* dst = (part == 0) ? g_qh : (part == 1) ? g_kh : g_vh;
        float sc = (part == 0) ? 0.125f * 1.44269504f : 1.0f;
        int bb = m0 >> 10, lbase = (m0 & 1023) + wm * 32;
#pragma unroll
        for (int mf = 0; mf < 2; mf++)
#pragma unroll
            for (int f = 0; f < 8; f++) {
                int ll = lbase + mf * 16 + rq;
                size_t base = ((size_t)(bb * 8 + h) * 1024 + ll) * 64 + f * 8 + q2;
                *(unsigned*)(dst + base)          = packh2(C[mf][f][0] * sc, C[mf][f][1] * sc);
                *(unsigned*)(dst + base + 8 * 64) = packh2(C[mf][f][2] * sc, C[mf][f][3] * sc);
            }
    }
}

// ---------------- attention: fp16 flash, base-2 softmax, l via ones-MMA -------
// stage s at s*16384: Kh 0, Vh 8K (each 64x64 fp16, SW128)
#define ADYN (49152 + 1024)
__global__ void __launch_bounds__(256, 2) attn_mma(const float* __restrict__ gamma) {
    extern __shared__ char raw[];
    uint32_t rb = smem_u32(raw);
    char* sm = raw + ((1024u - (rb & 1023u)) & 1023u);
    const uint32_t sb = smem_u32(sm);
    const int t = threadIdx.x, lane = t & 31, wid = t >> 5;
    const int b = blockIdx.z, h = blockIdx.y, i0 = blockIdx.x * 128;
    const int bh = b * H_ + h;
    const int rq = lane >> 2, q2 = 2 * (lane & 3);

    float tv = 0.0f;
#pragma unroll
    for (int kk = 0; kk < 5; kk++)
        if ((lane >> kk) & 1) tv += gamma[h * 5 + kk];
    tv *= 1.44269504f;   // base-2 softmax domain

    // stage Q (128x64 fp16) into stage0, build A-fragments in registers
#pragma unroll
    for (int i = 0; i < 4; i++) {
        int pos = t + i * 256, row = pos >> 3, cs = pos & 7;
        unsigned off = SW128((unsigned)(row * 128 + cs * 16));
        size_t g = ((size_t)bh * L_ + i0 + row) * 64 + cs * 8;
        *(uint4*)(sm + off) = *(const uint4*)(g_qh + g);
    }
    __syncthreads();
    unsigned qh[4][4];
    {
        int arow = wid * 16 + (lane & 15);
        int ak = (lane >> 4) * 8;
#pragma unroll
        for (int ks = 0; ks < 4; ks++) {
            unsigned off = SW128((unsigned)(arow * 128 + (ak + ks * 16) * 2));
            ldm4(qh[ks], sb + off);
        }
    }
    __syncthreads();

    auto pf = [&](int jtile, uint32_t stb) {
#pragma unroll
        for (int i = 0; i < 2; i++) {
            int pos = t + i * 256, row = pos >> 3, cs = pos & 7;
            unsigned off = SW128((unsigned)(row * 128 + cs * 16));
            size_t g = ((size_t)bh * L_ + jtile * 64 + row) * 64 + cs * 8;
            CPA(stb + off,        g_kh + g);
            CPA(stb + 8192 + off, g_vh + g);
        }
    };
    pf(0, sb); CPC();
    pf(1, sb + 16384u); CPC();

    float O[8][4];
#pragma unroll
    for (int f = 0; f < 8; f++)
#pragma unroll
        for (int c = 0; c < 4; c++) O[f][c] = 0.0f;
    float OL[4] = {0.0f, 0.0f, 0.0f, 0.0f};   // l accumulator: OL = P @ ones
    float m0r = -1e30f, m1r = -1e30f;

    const unsigned onesb[2] = { 0x3C003C00u, 0x3C003C00u };  // fp16 1.0 x4

    const int ig0 = i0 + wid * 16 + rq;
    const unsigned char* mr0 = g_mask + ((size_t)b << 20) + (size_t)ig0 * 1024;
    const unsigned char* mr1 = mr0 + 8 * 1024;

    const int kb_row = ((lane >> 4) << 3) + (lane & 7);
    const int kb_k   = ((lane >> 3) & 1) * 8;
    const int vb_j   = ((lane >> 3) & 1) * 8 + (lane & 7);
    const int vb_d   = (lane >> 4) * 8;

    for (int jt = 0; jt < 16; jt++) {
        if (jt < 15) CPW(1); else CPW(0);
        __syncthreads();
        if (jt < 14) { pf(jt + 2, sb + (unsigned)((jt + 2) % 3) * 16384u); CPC(); }
        const uint32_t base = sb + (unsigned)(jt % 3) * 16384u;
        const int j0 = jt * 64;

        // S = Q K^T
        float S[8][4];
#pragma unroll
        for (int f = 0; f < 8; f++)
#pragma unroll
            for (int c = 0; c < 4; c++) S[f][c] = 0.0f;
#pragma unroll
        for (int ks = 0; ks < 4; ks++) {
#pragma unroll
            for (int nf4 = 0; nf4 < 4; nf4++) {
                unsigned off = SW128((unsigned)((kb_row + nf4 * 16) * 128 + (kb_k + ks * 16) * 2));
                unsigned bhf[4];
                ldm4(bhf, base + off);
                mma_f16(S[2 * nf4], qh[ks], bhf);
                mma_f16(S[2 * nf4 + 1], qh[ks], bhf + 2);
            }
        }

        // bias + online max (base-2 domain; rows rq, rq+8)
        float mx0 = -1e30f, mx1 = -1e30f;
#pragma unroll
        for (int f = 0; f < 8; f++) {
            int cb = j0 + f * 8 + q2;
            unsigned short w0 = *(const unsigned short*)(mr0 + cb);
            unsigned short w1 = *(const unsigned short*)(mr1 + cb);
            S[f][0] += __shfl_sync(0xffffffffu, tv, w0 & 31u);
            S[f][1] += __shfl_sync(0xffffffffu, tv, (w0 >> 8) & 31u);
            S[f][2] += __shfl_sync(0xffffffffu, tv, w1 & 31u);
            S[f][3] += __shfl_sync(0xffffffffu, tv, (w1 >> 8) & 31u);
            mx0 = fmaxf(mx0, fmaxf(S[f][0], S[f][1]));
            mx1 = fmaxf(mx1, fmaxf(S[f][2], S[f][3]));
        }
        mx0 = fmaxf(mx0, __shfl_xor_sync(0xffffffffu, mx0, 1));
        mx0 = fmaxf(mx0, __shfl_xor_sync(0xffffffffu, mx0, 2));
        mx1 = fmaxf(mx1, __shfl_xor_sync(0xffffffffu, mx1, 1));
        mx1 = fmaxf(mx1, __shfl_xor_sync(0xffffffffu, mx1, 2));
        float nm0 = fmaxf(m0r, mx0), nm1 = fmaxf(m1r, mx1);
        float fac0 = ex2(m0r - nm0), fac1 = ex2(m1r - nm1);
        m0r = nm0; m1r = nm1;

        // P = 2^(S - nm): fp16x2 exponentials, output IS the MMA fragment
        unsigned ph01[8], ph23[8];
#pragma unroll
        for (int f = 0; f < 8; f++) {
            ph01[f] = h2ex2(packh2(S[f][0] - nm0, S[f][1] - nm0));
            ph23[f] = h2ex2(packh2(S[f][2] - nm1, S[f][3] - nm1));
            O[f][0] *= fac0; O[f][1] *= fac0;
            O[f][2] *= fac1; O[f][3] *= fac1;
        }
        OL[0] *= fac0; OL[1] *= fac0; OL[2] *= fac1; OL[3] *= fac1;

        // O += P V ;  OL += P @ ones (row sums)
#pragma unroll
        for (int ks = 0; ks < 4; ks++) {
            unsigned ah[4] = { ph01[2 * ks], ph23[2 * ks], ph01[2 * ks + 1], ph23[2 * ks + 1] };
            mma_f16(OL, ah, onesb);
#pragma unroll
            for (int nf4 = 0; nf4 < 4; nf4++) {
                unsigned off = SW128((unsigned)((vb_j + ks * 16) * 128 + (vb_d + nf4 * 16) * 2));
                unsigned bvh[4];
                ldm4t(bvh, base + 8192 + off);
                mma_f16(O[2 * nf4], ah, bvh);
                mma_f16(O[2 * nf4 + 1], ah, bvh + 2);
            }
        }
    }

    // epilogue: l comes straight from the ones-MMA accumulator
    float inv0 = 1.0f / OL[0], inv1 = 1.0f / OL[2];
    size_t base0 = ((size_t)(b << 10) + ig0) * 512 + h * 64;
    size_t base1 = base0 + 8 * 512;
#pragma unroll
    for (int f = 0; f < 8; f++) {
        *(unsigned*)(g_aoh + base0 + f * 8 + q2) = packh2(O[f][0] * inv0, O[f][1] * inv0);
        *(unsigned*)(g_aoh + base1 + f * 8 + q2) = packh2(O[f][2] * inv1, O[f][3] * inv1);
    }
}

// ---------------- launch --------------------------------------------------------
extern "C" void kernel_launch(void* const* d_in, const int* in_sizes, int n_in,
                              void* d_out, int out_size) {
    const float* x      = (const float*)d_in[0];
    const float* adj    = (const float*)d_in[1];
    const float* dist   = (const float*)d_in[2];
    const float* w_qkv  = (const float*)d_in[3];
    const float* w_proj = (const float*)d_in[4];
    const float* gamma  = (const float*)d_in[5];
    float* out = (float*)d_out;

    cudaFuncSetAttribute(mm_kernel, cudaFuncAttributeMaxDynamicSharedMemorySize, GDYN);
    cudaFuncSetAttribute(attn_mma, cudaFuncAttributeMaxDynamicSharedMemorySize, ADYN);

    cudaStream_t ms = cudaStreamPerThread;

    cudaEventRecord(g_aux.fork, ms);
    cudaStreamWaitEvent(g_aux.s, g_aux.fork, 0);
    pack_kernel<<<(B_ * L_ * L_) / 256, 256, 0, g_aux.s>>>(adj, dist);
    mask_kernel<<<dim3(L_ / 32, L_ / 32, B_), 256, 0, g_aux.s>>>();
    cudaEventRecord(g_aux.join, g_aux.s);

    split_x<<<(M_TOT * C_) / 256, 256, 0, ms>>>(x);
    split_w<<<768 + 256, 256, 0, ms>>>(w_qkv, w_proj);
    mm_kernel<<<dim3(12, 64), 256, GDYN, ms>>>(0, nullptr);   // qkv

    cudaStreamWaitEvent(ms, g_aux.join, 0);
    attn_mma<<<dim3(L_ / 128, H_, B_), 256, ADYN, ms>>>(gamma);
    mm_kernel<<<dim3(4, 64), 256, GDYN, ms>>>(1, out);        // proj
}

// round 12
// speedup vs baseline: 5.3625x; 1.0847x over previous
#include <cuda_runtime.h>
#include <cuda_fp16.h>
#include <cstdint>

#define B_ 8
#define L_ 1024
#define C_ 512
#define H_ 8
#define D_ 64
#define M_TOT (B_*L_)

// ---------------- static device scratch -------------------------------------
__device__ unsigned g_adjbits[B_*L_*(L_/32)];
__device__ unsigned g_distbits[B_*L_*(L_/32)];
__device__ unsigned char g_mask[(size_t)B_*L_*L_];

__device__ __half g_xh[M_TOT*C_];
__device__ __half g_wqT[3*C_*C_];   // [1536][512] fp16
__device__ __half g_wpT[C_*C_];     // [512][512]  fp16
__device__ __half g_qh[B_*H_*L_*D_];  // pre-scaled (1/8)*log2e
__device__ __half g_kh[B_*H_*L_*D_];
__device__ __half g_vh[B_*H_*L_*D_];
__device__ __half g_aoh[M_TOT*C_];

// ---------------- device helpers ----------------------------------------------
__device__ __forceinline__ uint32_t smem_u32(const void* p) {
    uint32_t a;
    asm("{ .reg .u64 t; cvta.to.shared.u64 t, %1; cvt.u32.u64 %0, t; }" : "=r"(a) : "l"(p));
    return a;
}
#define SW128(o) ((o) ^ (((o) >> 3) & 0x70))

#define CPA(dst, src) asm volatile("cp.async.cg.shared.global [%0], [%1], 16;" :: "r"(dst), "l"(src))
#define CPC()  asm volatile("cp.async.commit_group;")
#define CPW(n) asm volatile("cp.async.wait_group %0;" :: "n"(n))

__device__ __forceinline__ void mma_f16(float* c, const unsigned* a, const unsigned* b) {
    asm volatile("mma.sync.aligned.m16n8k16.row.col.f32.f16.f16.f32 "
        "{%0,%1,%2,%3}, {%4,%5,%6,%7}, {%8,%9}, {%0,%1,%2,%3};"
        : "+f"(c[0]), "+f"(c[1]), "+f"(c[2]), "+f"(c[3])
        : "r"(a[0]), "r"(a[1]), "r"(a[2]), "r"(a[3]), "r"(b[0]), "r"(b[1]));
}
__device__ __forceinline__ void ldm4(unsigned* r, uint32_t a) {
    asm volatile("ldmatrix.sync.aligned.m8n8.x4.shared.b16 {%0,%1,%2,%3}, [%4];"
        : "=r"(r[0]), "=r"(r[1]), "=r"(r[2]), "=r"(r[3]) : "r"(a));
}
__device__ __forceinline__ void ldm4t(unsigned* r, uint32_t a) {
    asm volatile("ldmatrix.sync.aligned.m8n8.x4.trans.shared.b16 {%0,%1,%2,%3}, [%4];"
        : "=r"(r[0]), "=r"(r[1]), "=r"(r[2]), "=r"(r[3]) : "r"(a));
}
__device__ __forceinline__ unsigned packh2(float a, float b) {
    __half2 hv = __floats2half2_rn(a, b);
    return *(unsigned*)&hv;
}
__device__ __forceinline__ float ex2(float x) {
    float y;
    asm("ex2.approx.ftz.f32 %0, %1;" : "=f"(y) : "f"(x));
    return y;
}
__device__ __forceinline__ unsigned h2ex2(unsigned x) {
    unsigned y;
    asm("ex2.approx.f16x2 %0, %1;" : "=r"(y) : "r"(x));
    return y;
}

// ---------------- fused k1: pack bitmasks + split_x ---------------------------
__global__ void prep1(const float* __restrict__ adj, const float* __restrict__ dist,
                      const float* __restrict__ x) {
    unsigned bid = blockIdx.x;
    if (bid < 32768u) {
        unsigned e = bid * 256u + threadIdx.x;
        unsigned j = e & (L_ - 1u), i = (e >> 10) & (L_ - 1u);
        bool ab = (adj[e] != 0.0f) && (i != 0u) && (j != 0u);
        unsigned aw = __ballot_sync(0xffffffffu, ab);
        unsigned dw = __ballot_sync(0xffffffffu, dist[e] > 0.0f);
        if ((threadIdx.x & 31u) == 0u) { g_adjbits[e >> 5] = aw; g_distbits[e >> 5] = dw; }
    } else {
        unsigned i = (bid - 32768u) * 256u + threadIdx.x;
        g_xh[i] = __float2half_rn(x[i]);
    }
}

// ---------------- fused k2: 5-bit mask + weight transpose ---------------------
__global__ void prep2(const float* __restrict__ wq, const float* __restrict__ wp) {
    unsigned bid = blockIdx.x;
    if (bid < 8192u) {
        const int b = bid >> 10;
        const int rem = bid & 1023;
        const int i0 = (rem >> 5) * 32, j0 = (rem & 31) * 32;
        __shared__ unsigned Ai[32][33], Aj[32][33];
        const int t = threadIdx.x;
#pragma unroll
        for (int k = 0; k < 4; k++) {
            int pos = t + k * 256, r = pos >> 5, w = pos & 31;
            Ai[r][w] = g_adjbits[((b << 10) + i0 + r) * 32 + w];
            Aj[r][w] = g_adjbits[((b << 10) + j0 + r) * 32 + w];
        }
        __syncthreads();
        const int il = t >> 3, jb = (t & 7) << 2, ig = i0 + il;
        const unsigned di = g_distbits[((b << 10) + ig) * 32 + (j0 >> 5)];
        unsigned sbits = 0u;
        for (int w = 0; w < 32; w++) {
            unsigned ai = Ai[il][w];
#pragma unroll
            for (int jj = 0; jj < 4; jj++)
                if (ai & Aj[jb + jj][w]) sbits |= (1u << jj);
            if (sbits == 0xFu) break;
        }
        unsigned word = 0u;
#pragma unroll
        for (int jj = 0; jj < 4; jj++) {
            int jl = jb + jj;
            unsigned fwd = (Ai[il][j0 >> 5] >> jl) & 1u;
            unsigned bwd = (Aj[jl][i0 >> 5] >> il) & 1u;
            unsigned dfw = (di >> jl) & 1u;
            unsigned dbw = (g_distbits[((b << 10) + j0 + jl) * 32 + (i0 >> 5)] >> il) & 1u;
            unsigned st = (sbits >> jj) & 1u;
            word |= (fwd | (bwd << 1) | (dfw << 2) | (dbw << 3) | (st << 4)) << (8 * jj);
        }
        *reinterpret_cast<unsigned*>(g_mask + (((size_t)((b << 10) + ig)) << 10) + j0 + jb) = word;
    } else {
        __shared__ float tile[32][33];
        int wb = bid - 8192;
        const float* src; __half* dh; int N;
        if (wb < 768) { src = wq; dh = g_wqT; N = 1536; }
        else          { wb -= 768; src = wp; dh = g_wpT; N = 512; }
        int tn = N >> 5;
        int k0 = (wb / tn) * 32, n0 = (wb % tn) * 32;
        int c = threadIdx.x & 31, r0 = threadIdx.x >> 5;
#pragma unroll
        for (int p = 0; p < 4; p++) {
            int r = r0 + p * 8;
            tile[r][c] = src[(size_t)(k0 + r) * N + n0 + c];
        }
        __syncthreads();
#pragma unroll
        for (int p = 0; p < 4; p++) {
            int r = r0 + p * 8;
            dh[(size_t)(n0 + r) * 512 + k0 + c] = __float2half_rn(tile[c][r]);
        }
    }
}

// ---------------- fp16 GEMM: 128x128 CTA tile, K=512, 3-stage, 1 barrier/iter --
#define GDYN (98304 + 1024)
__global__ void __launch_bounds__(256) mm_kernel(int mode, float* __restrict__ out) {
    extern __shared__ char raw[];
    uint32_t rb = smem_u32(raw);
    char* sm = raw + ((1024u - (rb & 1023u)) & 1023u);
    const uint32_t sb = smem_u32(sm);
    const int t = threadIdx.x, lane = t & 31, wid = t >> 5;
    const int wm = wid & 3, wn = wid >> 2;
    const int n0 = blockIdx.x * 128, m0 = blockIdx.y * 128;

    const __half *Ah, *Bh;
    if (mode == 0) { Ah = g_xh;  Bh = g_wqT; }
    else           { Ah = g_aoh; Bh = g_wpT; }

    float C[2][8][4];
#pragma unroll
    for (int m = 0; m < 2; m++)
#pragma unroll
        for (int f = 0; f < 8; f++)
#pragma unroll
            for (int c = 0; c < 4; c++) C[m][f][c] = 0.0f;

    const int a_row = wm * 32 + (lane & 15);
    const int a_k   = (lane >> 4) * 8;
    const int b_row = wn * 64 + ((lane >> 4) << 3) + (lane & 7);
    const int b_k   = ((lane >> 3) & 1) * 8;

    auto pf = [&](int kc, uint32_t stb) {
#pragma unroll
        for (int i = 0; i < 4; i++) {
            int pos = t + i * 256, row = pos >> 3, cs = pos & 7;
            unsigned off = SW128((unsigned)(row * 128 + cs * 16));
            size_t ga = (size_t)(m0 + row) * 512 + kc * 64 + cs * 8;
            size_t gb = (size_t)(n0 + row) * 512 + kc * 64 + cs * 8;
            CPA(stb + off,         Ah + ga);
            CPA(stb + 16384 + off, Bh + gb);
        }
    };
    pf(0, sb); CPC();
    pf(1, sb + 32768u); CPC();

    for (int kc = 0; kc < 8; kc++) {
        if (kc < 7) CPW(1); else CPW(0);
        __syncthreads();
        if (kc < 6) { pf(kc + 2, sb + (unsigned)((kc + 2) % 3) * 32768u); CPC(); }
        const uint32_t base = sb + (unsigned)(kc % 3) * 32768u;
#pragma unroll
        for (int ks = 0; ks < 4; ks++) {
            unsigned ah[2][4];
#pragma unroll
            for (int mf = 0; mf < 2; mf++) {
                unsigned off = SW128((unsigned)((a_row + mf * 16) * 128 + (a_k + ks * 16) * 2));
                ldm4(ah[mf], base + off);
            }
#pragma unroll
            for (int nf4 = 0; nf4 < 4; nf4++) {
                unsigned off = SW128((unsigned)((b_row + nf4 * 16) * 128 + (b_k + ks * 16) * 2));
                unsigned bh[4];
                ldm4(bh, base + 16384 + off);
#pragma unroll
                for (int mf = 0; mf < 2; mf++) {
                    mma_f16(C[mf][2 * nf4], ah[mf], bh);
                    mma_f16(C[mf][2 * nf4 + 1], ah[mf], bh + 2);
                }
            }
        }
    }

    const int rq = lane >> 2, q2 = 2 * (lane & 3);
    if (mode == 1) {
#pragma unroll
        for (int mf = 0; mf < 2; mf++)
#pragma unroll
            for (int f = 0; f < 8; f++) {
                int row = m0 + wm * 32 + mf * 16 + rq;
                int col = n0 + wn * 64 + f * 8 + q2;
                float2 v0; v0.x = C[mf][f][0]; v0.y = C[mf][f][1];
                float2 v1; v1.x = C[mf][f][2]; v1.y = C[mf][f][3];
                *(float2*)(out + (size_t)row * 512 + col) = v0;
                *(float2*)(out + (size_t)(row + 8) * 512 + col) = v1;
            }
    } else {
        int part = n0 >> 9;
        int h = ((n0 + wn * 64) >> 6) & 7;
        __half* dst = (part == 0) ? g_qh : (part == 1) ? g_kh : g_vh;
        float sc = (part == 0) ? 0.125f * 1.44269504f : 1.0f;
        int bb = m0 >> 10, lbase = (m0 & 1023) + wm * 32;
#pragma unroll
        for (int mf = 0; mf < 2; mf++)
#pragma unroll
            for (int f = 0; f < 8; f++) {
                int ll = lbase + mf * 16 + rq;
                size_t base = ((size_t)(bb * 8 + h) * 1024 + ll) * 64 + f * 8 + q2;
                *(unsigned*)(dst + base)          = packh2(C[mf][f][0] * sc, C[mf][f][1] * sc);
                *(unsigned*)(dst + base + 8 * 64) = packh2(C[mf][f][2] * sc, C[mf][f][3] * sc);
            }
    }
}

// ---------------- attention: fp16 flash, mask staged via cp.async -------------
// stage s at s*26624: Kh 0, Vh 8192, Mask 16384 (128 rows x 80B, rows=q-rows)
#define ASTG 26624
#define ADYN (3*ASTG + 1024)
__global__ void __launch_bounds__(256, 2) attn_mma(const float* __restrict__ gamma) {
    extern __shared__ char raw[];
    uint32_t rb = smem_u32(raw);
    char* sm = raw + ((1024u - (rb & 1023u)) & 1023u);
    const uint32_t sb = smem_u32(sm);
    const int t = threadIdx.x, lane = t & 31, wid = t >> 5;
    const int b = blockIdx.z, h = blockIdx.y, i0 = blockIdx.x * 128;
    const int bh = b * H_ + h;
    const int rq = lane >> 2, q2 = 2 * (lane & 3);

    float tv = 0.0f;
#pragma unroll
    for (int kk = 0; kk < 5; kk++)
        if ((lane >> kk) & 1) tv += gamma[h * 5 + kk];
    tv *= 1.44269504f;   // base-2 softmax domain

    // stage Q (128x64 fp16) into stage0 KV region, build A-fragments
#pragma unroll
    for (int i = 0; i < 4; i++) {
        int pos = t + i * 256, row = pos >> 3, cs = pos & 7;
        unsigned off = SW128((unsigned)(row * 128 + cs * 16));
        size_t g = ((size_t)bh * L_ + i0 + row) * 64 + cs * 8;
        *(uint4*)(sm + off) = *(const uint4*)(g_qh + g);
    }
    __syncthreads();
    unsigned qh[4][4];
    {
        int arow = wid * 16 + (lane & 15);
        int ak = (lane >> 4) * 8;
#pragma unroll
        for (int ks = 0; ks < 4; ks++) {
            unsigned off = SW128((unsigned)(arow * 128 + (ak + ks * 16) * 2));
            ldm4(qh[ks], sb + off);
        }
    }
    __syncthreads();

    const unsigned char* mbase = g_mask + ((size_t)b << 20) + (size_t)i0 * 1024;

    auto pf = [&](int jtile, uint32_t stb, char* stp) {
        int j0 = jtile * 64;
#pragma unroll
        for (int i = 0; i < 2; i++) {
            int pos = t + i * 256, row = pos >> 3, cs = pos & 7;
            unsigned off = SW128((unsigned)(row * 128 + cs * 16));
            size_t g = ((size_t)bh * L_ + j0 + row) * 64 + cs * 8;
            CPA(stb + off,        g_kh + g);
            CPA(stb + 8192 + off, g_vh + g);
            // mask: 512 chunks of 16B (128 rows x 4 chunks)
            int mrow = pos >> 2, mcs = pos & 3;
            CPA(stb + 16384u + (unsigned)(mrow * 80 + mcs * 16),
                mbase + (size_t)mrow * 1024 + j0 + mcs * 16);
        }
        (void)stp;
    };
    pf(0, sb, sm); CPC();
    pf(1, sb + ASTG, sm); CPC();

    float O[8][4];
#pragma unroll
    for (int f = 0; f < 8; f++)
#pragma unroll
        for (int c = 0; c < 4; c++) O[f][c] = 0.0f;
    float OL[4] = {0.0f, 0.0f, 0.0f, 0.0f};
    float m0r = -1e30f, m1r = -1e30f;

    const unsigned onesb[2] = { 0x3C003C00u, 0x3C003C00u };

    const int mrow0 = (wid * 16 + rq) * 80;       // smem mask row offsets
    const int mrow1 = mrow0 + 8 * 80;

    const int kb_row = ((lane >> 4) << 3) + (lane & 7);
    const int kb_k   = ((lane >> 3) & 1) * 8;
    const int vb_j   = ((lane >> 3) & 1) * 8 + (lane & 7);
    const int vb_d   = (lane >> 4) * 8;

    for (int jt = 0; jt < 16; jt++) {
        if (jt < 15) CPW(1); else CPW(0);
        __syncthreads();
        if (jt < 14) { pf(jt + 2, sb + (unsigned)((jt + 2) % 3) * ASTG, sm); CPC(); }
        const uint32_t base = sb + (unsigned)(jt % 3) * ASTG;
        const char* msm = sm + (size_t)(jt % 3) * ASTG + 16384;

        // S = Q K^T
        float S[8][4];
#pragma unroll
        for (int f = 0; f < 8; f++)
#pragma unroll
            for (int c = 0; c < 4; c++) S[f][c] = 0.0f;
#pragma unroll
        for (int ks = 0; ks < 4; ks++) {
#pragma unroll
            for (int nf4 = 0; nf4 < 4; nf4++) {
                unsigned off = SW128((unsigned)((kb_row + nf4 * 16) * 128 + (kb_k + ks * 16) * 2));
                unsigned bhf[4];
                ldm4(bhf, base + off);
                mma_f16(S[2 * nf4], qh[ks], bhf);
                mma_f16(S[2 * nf4 + 1], qh[ks], bhf + 2);
            }
        }

        // bias (from smem-staged mask) + online max
        float mx0 = -1e30f, mx1 = -1e30f;
#pragma unroll
        for (int f = 0; f < 8; f++) {
            int cb = f * 8 + q2;
            unsigned short w0 = *(const unsigned short*)(msm + mrow0 + cb);
            unsigned short w1 = *(const unsigned short*)(msm + mrow1 + cb);
            S[f][0] += __shfl_sync(0xffffffffu, tv, w0 & 31u);
            S[f][1] += __shfl_sync(0xffffffffu, tv, (w0 >> 8) & 31u);
            S[f][2] += __shfl_sync(0xffffffffu, tv, w1 & 31u);
            S[f][3] += __shfl_sync(0xffffffffu, tv, (w1 >> 8) & 31u);
            mx0 = fmaxf(mx0, fmaxf(S[f][0], S[f][1]));
            mx1 = fmaxf(mx1, fmaxf(S[f][2], S[f][3]));
        }
        mx0 = fmaxf(mx0, __shfl_xor_sync(0xffffffffu, mx0, 1));
        mx0 = fmaxf(mx0, __shfl_xor_sync(0xffffffffu, mx0, 2));
        mx1 = fmaxf(mx1, __shfl_xor_sync(0xffffffffu, mx1, 1));
        mx1 = fmaxf(mx1, __shfl_xor_sync(0xffffffffu, mx1, 2));
        float nm0 = fmaxf(m0r, mx0), nm1 = fmaxf(m1r, mx1);
        float fac0 = ex2(m0r - nm0), fac1 = ex2(m1r - nm1);
        m0r = nm0; m1r = nm1;

        // P = 2^(S - nm) via fp16x2 MUFU; output IS the MMA fragment
        unsigned ph01[8], ph23[8];
#pragma unroll
        for (int f = 0; f < 8; f++) {
            ph01[f] = h2ex2(packh2(S[f][0] - nm0, S[f][1] - nm0));
            ph23[f] = h2ex2(packh2(S[f][2] - nm1, S[f][3] - nm1));
        }
        // rescale O only if some lane's max moved (ballot-guarded)
        if (__ballot_sync(0xffffffffu, (fac0 != 1.0f) | (fac1 != 1.0f))) {
#pragma unroll
            for (int f = 0; f < 8; f++) {
                O[f][0] *= fac0; O[f][1] *= fac0;
                O[f][2] *= fac1; O[f][3] *= fac1;
            }
            OL[0] *= fac0; OL[1] *= fac0; OL[2] *= fac1; OL[3] *= fac1;
        }

        // O += P V ;  OL += P @ ones
#pragma unroll
        for (int ks = 0; ks < 4; ks++) {
            unsigned ah[4] = { ph01[2 * ks], ph23[2 * ks], ph01[2 * ks + 1], ph23[2 * ks + 1] };
            mma_f16(OL, ah, onesb);
#pragma unroll
            for (int nf4 = 0; nf4 < 4; nf4++) {
                unsigned off = SW128((unsigned)((vb_j + ks * 16) * 128 + (vb_d + nf4 * 16) * 2));
                unsigned bvh[4];
                ldm4t(bvh, base + 8192 + off);
                mma_f16(O[2 * nf4], ah, bvh);
                mma_f16(O[2 * nf4 + 1], ah, bvh + 2);
            }
        }
    }

    // epilogue
    float inv0 = 1.0f / OL[0], inv1 = 1.0f / OL[2];
    const int ig0 = i0 + wid * 16 + rq;
    size_t base0 = ((size_t)(b << 10) + ig0) * 512 + h * 64;
    size_t base1 = base0 + 8 * 512;
#pragma unroll
    for (int f = 0; f < 8; f++) {
        *(unsigned*)(g_aoh + base0 + f * 8 + q2) = packh2(O[f][0] * inv0, O[f][1] * inv0);
        *(unsigned*)(g_aoh + base1 + f * 8 + q2) = packh2(O[f][2] * inv1, O[f][3] * inv1);
    }
}

// ---------------- launch --------------------------------------------------------
extern "C" void kernel_launch(void* const* d_in, const int* in_sizes, int n_in,
                              void* d_out, int out_size) {
    const float* x      = (const float*)d_in[0];
    const float* adj    = (const float*)d_in[1];
    const float* dist   = (const float*)d_in[2];
    const float* w_qkv  = (const float*)d_in[3];
    const float* w_proj = (const float*)d_in[4];
    const float* gamma  = (const float*)d_in[5];
    float* out = (float*)d_out;

    cudaFuncSetAttribute(mm_kernel, cudaFuncAttributeMaxDynamicSharedMemorySize, GDYN);
    cudaFuncSetAttribute(attn_mma, cudaFuncAttributeMaxDynamicSharedMemorySize, ADYN);

    prep1<<<32768 + 16384, 256>>>(adj, dist, x);           // pack + split_x
    prep2<<<8192 + 1024, 256>>>(w_qkv, w_proj);            // mask + split_w
    mm_kernel<<<dim3(12, 64), 256, GDYN>>>(0, nullptr);    // qkv
    attn_mma<<<dim3(L_ / 128, H_, B_), 256, ADYN>>>(gamma);// attn (launch #4 -> profiled)
    mm_kernel<<<dim3(4, 64), 256, GDYN>>>(1, out);         // proj
}

// round 13
// speedup vs baseline: 5.5739x; 1.0394x over previous
#include <cuda_runtime.h>
#include <cuda_fp16.h>
#include <cstdint>

#define B_ 8
#define L_ 1024
#define C_ 512
#define H_ 8
#define D_ 64
#define M_TOT (B_*L_)

// ---------------- static device scratch -------------------------------------
__device__ unsigned g_adjbits[B_*L_*(L_/32)];
__device__ unsigned g_distbits[B_*L_*(L_/32)];
__device__ unsigned char g_mask[(size_t)B_*L_*L_];

__device__ __half g_xh[M_TOT*C_];
__device__ __half g_wqT[3*C_*C_];   // [1536][512] fp16
__device__ __half g_wpT[C_*C_];     // [512][512]  fp16
__device__ __half g_qh[B_*H_*L_*D_];  // pre-scaled (1/8)*log2e
__device__ __half g_kh[B_*H_*L_*D_];
__device__ __half g_vh[B_*H_*L_*D_];
__device__ __half g_aoh[M_TOT*C_];

// ---------------- device helpers ----------------------------------------------
__device__ __forceinline__ uint32_t smem_u32(const void* p) {
    uint32_t a;
    asm("{ .reg .u64 t; cvta.to.shared.u64 t, %1; cvt.u32.u64 %0, t; }" : "=r"(a) : "l"(p));
    return a;
}
#define SW128(o) ((o) ^ (((o) >> 3) & 0x70))

#define CPA(dst, src) asm volatile("cp.async.cg.shared.global [%0], [%1], 16;" :: "r"(dst), "l"(src))
#define CPC()  asm volatile("cp.async.commit_group;")
#define CPW(n) asm volatile("cp.async.wait_group %0;" :: "n"(n))

__device__ __forceinline__ void mma_f16(float* c, const unsigned* a, const unsigned* b) {
    asm volatile("mma.sync.aligned.m16n8k16.row.col.f32.f16.f16.f32 "
        "{%0,%1,%2,%3}, {%4,%5,%6,%7}, {%8,%9}, {%0,%1,%2,%3};"
        : "+f"(c[0]), "+f"(c[1]), "+f"(c[2]), "+f"(c[3])
        : "r"(a[0]), "r"(a[1]), "r"(a[2]), "r"(a[3]), "r"(b[0]), "r"(b[1]));
}
__device__ __forceinline__ void ldm4(unsigned* r, uint32_t a) {
    asm volatile("ldmatrix.sync.aligned.m8n8.x4.shared.b16 {%0,%1,%2,%3}, [%4];"
        : "=r"(r[0]), "=r"(r[1]), "=r"(r[2]), "=r"(r[3]) : "r"(a));
}
__device__ __forceinline__ void ldm4t(unsigned* r, uint32_t a) {
    asm volatile("ldmatrix.sync.aligned.m8n8.x4.trans.shared.b16 {%0,%1,%2,%3}, [%4];"
        : "=r"(r[0]), "=r"(r[1]), "=r"(r[2]), "=r"(r[3]) : "r"(a));
}
__device__ __forceinline__ unsigned packh2(float a, float b) {
    __half2 hv = __floats2half2_rn(a, b);
    return *(unsigned*)&hv;
}
__device__ __forceinline__ unsigned h2ex2(unsigned x) {
    unsigned y;
    asm("ex2.approx.f16x2 %0, %1;" : "=r"(y) : "r"(x));
    return y;
}

// ---------------- fused k1: pack bitmasks + split_x ---------------------------
__global__ void prep1(const float* __restrict__ adj, const float* __restrict__ dist,
                      const float* __restrict__ x) {
    unsigned bid = blockIdx.x;
    if (bid < 32768u) {
        unsigned e = bid * 256u + threadIdx.x;
        unsigned j = e & (L_ - 1u), i = (e >> 10) & (L_ - 1u);
        bool ab = (adj[e] != 0.0f) && (i != 0u) && (j != 0u);
        unsigned aw = __ballot_sync(0xffffffffu, ab);
        unsigned dw = __ballot_sync(0xffffffffu, dist[e] > 0.0f);
        if ((threadIdx.x & 31u) == 0u) { g_adjbits[e >> 5] = aw; g_distbits[e >> 5] = dw; }
    } else {
        unsigned i = (bid - 32768u) * 256u + threadIdx.x;
        g_xh[i] = __float2half_rn(x[i]);
    }
}

// ---------------- fused k2: 5-bit mask + weight transpose ---------------------
__global__ void prep2(const float* __restrict__ wq, const float* __restrict__ wp) {
    unsigned bid = blockIdx.x;
    if (bid < 8192u) {
        const int b = bid >> 10;
        const int rem = bid & 1023;
        const int i0 = (rem >> 5) * 32, j0 = (rem & 31) * 32;
        __shared__ unsigned Ai[32][33], Aj[32][33];
        const int t = threadIdx.x;
#pragma unroll
        for (int k = 0; k < 4; k++) {
            int pos = t + k * 256, r = pos >> 5, w = pos & 31;
            Ai[r][w] = g_adjbits[((b << 10) + i0 + r) * 32 + w];
            Aj[r][w] = g_adjbits[((b << 10) + j0 + r) * 32 + w];
        }
        __syncthreads();
        const int il = t >> 3, jb = (t & 7) << 2, ig = i0 + il;
        const unsigned di = g_distbits[((b << 10) + ig) * 32 + (j0 >> 5)];
        unsigned sbits = 0u;
        for (int w = 0; w < 32; w++) {
            unsigned ai = Ai[il][w];
#pragma unroll
            for (int jj = 0; jj < 4; jj++)
                if (ai & Aj[jb + jj][w]) sbits |= (1u << jj);
            if (sbits == 0xFu) break;
        }
        unsigned word = 0u;
#pragma unroll
        for (int jj = 0; jj < 4; jj++) {
            int jl = jb + jj;
            unsigned fwd = (Ai[il][j0 >> 5] >> jl) & 1u;
            unsigned bwd = (Aj[jl][i0 >> 5] >> il) & 1u;
            unsigned dfw = (di >> jl) & 1u;
            unsigned dbw = (g_distbits[((b << 10) + j0 + jl) * 32 + (i0 >> 5)] >> il) & 1u;
            unsigned st = (sbits >> jj) & 1u;
            word |= (fwd | (bwd << 1) | (dfw << 2) | (dbw << 3) | (st << 4)) << (8 * jj);
        }
        *reinterpret_cast<unsigned*>(g_mask + (((size_t)((b << 10) + ig)) << 10) + j0 + jb) = word;
    } else {
        __shared__ float tile[32][33];
        int wb = bid - 8192;
        const float* src; __half* dh; int N;
        if (wb < 768) { src = wq; dh = g_wqT; N = 1536; }
        else          { wb -= 768; src = wp; dh = g_wpT; N = 512; }
        int tn = N >> 5;
        int k0 = (wb / tn) * 32, n0 = (wb % tn) * 32;
        int c = threadIdx.x & 31, r0 = threadIdx.x >> 5;
#pragma unroll
        for (int p = 0; p < 4; p++) {
            int r = r0 + p * 8;
            tile[r][c] = src[(size_t)(k0 + r) * N + n0 + c];
        }
        __syncthreads();
#pragma unroll
        for (int p = 0; p < 4; p++) {
            int r = r0 + p * 8;
            dh[(size_t)(n0 + r) * 512 + k0 + c] = __float2half_rn(tile[c][r]);
        }
    }
}

// ---------------- fp16 GEMM: 128x128 CTA tile, K=512, 3-stage, 1 barrier/iter --
#define GDYN (98304 + 1024)
__global__ void __launch_bounds__(256) mm_kernel(int mode, float* __restrict__ out) {
    extern __shared__ char raw[];
    uint32_t rb = smem_u32(raw);
    char* sm = raw + ((1024u - (rb & 1023u)) & 1023u);
    const uint32_t sb = smem_u32(sm);
    const int t = threadIdx.x, lane = t & 31, wid = t >> 5;
    const int wm = wid & 3, wn = wid >> 2;
    const int n0 = blockIdx.x * 128, m0 = blockIdx.y * 128;

    const __half *Ah, *Bh;
    if (mode == 0) { Ah = g_xh;  Bh = g_wqT; }
    else           { Ah = g_aoh; Bh = g_wpT; }

    float C[2][8][4];
#pragma unroll
    for (int m = 0; m < 2; m++)
#pragma unroll
        for (int f = 0; f < 8; f++)
#pragma unroll
            for (int c = 0; c < 4; c++) C[m][f][c] = 0.0f;

    const int a_row = wm * 32 + (lane & 15);
    const int a_k   = (lane >> 4) * 8;
    const int b_row = wn * 64 + ((lane >> 4) << 3) + (lane & 7);
    const int b_k   = ((lane >> 3) & 1) * 8;

    auto pf = [&](int kc, uint32_t stb) {
#pragma unroll
        for (int i = 0; i < 4; i++) {
            int pos = t + i * 256, row = pos >> 3, cs = pos & 7;
            unsigned off = SW128((unsigned)(row * 128 + cs * 16));
            size_t ga = (size_t)(m0 + row) * 512 + kc * 64 + cs * 8;
            size_t gb = (size_t)(n0 + row) * 512 + kc * 64 + cs * 8;
            CPA(stb + off,         Ah + ga);
            CPA(stb + 16384 + off, Bh + gb);
        }
    };
    pf(0, sb); CPC();
    pf(1, sb + 32768u); CPC();

    for (int kc = 0; kc < 8; kc++) {
        if (kc < 7) CPW(1); else CPW(0);
        __syncthreads();
        if (kc < 6) { pf(kc + 2, sb + (unsigned)((kc + 2) % 3) * 32768u); CPC(); }
        const uint32_t base = sb + (unsigned)(kc % 3) * 32768u;
#pragma unroll
        for (int ks = 0; ks < 4; ks++) {
            unsigned ah[2][4];
#pragma unroll
            for (int mf = 0; mf < 2; mf++) {
                unsigned off = SW128((unsigned)((a_row + mf * 16) * 128 + (a_k + ks * 16) * 2));
                ldm4(ah[mf], base + off);
            }
#pragma unroll
            for (int nf4 = 0; nf4 < 4; nf4++) {
                unsigned off = SW128((unsigned)((b_row + nf4 * 16) * 128 + (b_k + ks * 16) * 2));
                unsigned bh[4];
                ldm4(bh, base + 16384 + off);
#pragma unroll
                for (int mf = 0; mf < 2; mf++) {
                    mma_f16(C[mf][2 * nf4], ah[mf], bh);
                    mma_f16(C[mf][2 * nf4 + 1], ah[mf], bh + 2);
                }
            }
        }
    }

    const int rq = lane >> 2, q2 = 2 * (lane & 3);
    if (mode == 1) {
#pragma unroll
        for (int mf = 0; mf < 2; mf++)
#pragma unroll
            for (int f = 0; f < 8; f++) {
                int row = m0 + wm * 32 + mf * 16 + rq;
                int col = n0 + wn * 64 + f * 8 + q2;
                float2 v0; v0.x = C[mf][f][0]; v0.y = C[mf][f][1];
                float2 v1; v1.x = C[mf][f][2]; v1.y = C[mf][f][3];
                *(float2*)(out + (size_t)row * 512 + col) = v0;
                *(float2*)(out + (size_t)(row + 8) * 512 + col) = v1;
            }
    } else {
        int part = n0 >> 9;
        int h = ((n0 + wn * 64) >> 6) & 7;
        __half* dst = (part == 0) ? g_qh : (part == 1) ? g_kh : g_vh;
        float sc = (part == 0) ? 0.125f * 1.44269504f : 1.0f;
        int bb = m0 >> 10, lbase = (m0 & 1023) + wm * 32;
#pragma unroll
        for (int mf = 0; mf < 2; mf++)
#pragma unroll
            for (int f = 0; f < 8; f++) {
                int ll = lbase + mf * 16 + rq;
                size_t base = ((size_t)(bb * 8 + h) * 1024 + ll) * 64 + f * 8 + q2;
                *(unsigned*)(dst + base)          = packh2(C[mf][f][0] * sc, C[mf][f][1] * sc);
                *(unsigned*)(dst + base + 8 * 64) = packh2(C[mf][f][2] * sc, C[mf][f][3] * sc);
            }
    }
}

// ---------------- attention: fixed-offset softmax (no online max) -------------
// P = 2^(S + tv - C); the 2^-C cancels exactly in (P V)/(P 1). C folded into tv.
// stage s at s*26624: Kh 0, Vh 8192, Mask 16384 (128 rows x 80B)
#define ASTG 26624
#define ADYN (3*ASTG + 1024)
__global__ void __launch_bounds__(256, 2) attn_mma(const float* __restrict__ gamma) {
    extern __shared__ char raw[];
    uint32_t rb = smem_u32(raw);
    char* sm = raw + ((1024u - (rb & 1023u)) & 1023u);
    const uint32_t sb = smem_u32(sm);
    const int t = threadIdx.x, lane = t & 31, wid = t >> 5;
    const int b = blockIdx.z, h = blockIdx.y, i0 = blockIdx.x * 128;
    const int bh = b * H_ + h;
    const int rq = lane >> 2, q2 = 2 * (lane & 3);

    // per-lane bias table entry, base-2 domain, minus fixed softmax offset C=4
    float tv = 0.0f;
#pragma unroll
    for (int kk = 0; kk < 5; kk++)
        if ((lane >> kk) & 1) tv += gamma[h * 5 + kk];
    tv = tv * 1.44269504f - 4.0f;

    // stage Q (128x64 fp16) into stage0 KV region, build A-fragments
#pragma unroll
    for (int i = 0; i < 4; i++) {
        int pos = t + i * 256, row = pos >> 3, cs = pos & 7;
        unsigned off = SW128((unsigned)(row * 128 + cs * 16));
        size_t g = ((size_t)bh * L_ + i0 + row) * 64 + cs * 8;
        *(uint4*)(sm + off) = *(const uint4*)(g_qh + g);
    }
    __syncthreads();
    unsigned qh[4][4];
    {
        int arow = wid * 16 + (lane & 15);
        int ak = (lane >> 4) * 8;
#pragma unroll
        for (int ks = 0; ks < 4; ks++) {
            unsigned off = SW128((unsigned)(arow * 128 + (ak + ks * 16) * 2));
            ldm4(qh[ks], sb + off);
        }
    }
    __syncthreads();

    const unsigned char* mbase = g_mask + ((size_t)b << 20) + (size_t)i0 * 1024;

    auto pf = [&](int jtile, uint32_t stb) {
        int j0 = jtile * 64;
#pragma unroll
        for (int i = 0; i < 2; i++) {
            int pos = t + i * 256, row = pos >> 3, cs = pos & 7;
            unsigned off = SW128((unsigned)(row * 128 + cs * 16));
            size_t g = ((size_t)bh * L_ + j0 + row) * 64 + cs * 8;
            CPA(stb + off,        g_kh + g);
            CPA(stb + 8192 + off, g_vh + g);
            int mrow = pos >> 2, mcs = pos & 3;
            CPA(stb + 16384u + (unsigned)(mrow * 80 + mcs * 16),
                mbase + (size_t)mrow * 1024 + j0 + mcs * 16);
        }
    };
    pf(0, sb); CPC();
    pf(1, sb + ASTG); CPC();

    float O[8][4];
#pragma unroll
    for (int f = 0; f < 8; f++)
#pragma unroll
        for (int c = 0; c < 4; c++) O[f][c] = 0.0f;
    float OL[4] = {0.0f, 0.0f, 0.0f, 0.0f};

    const unsigned onesb[2] = { 0x3C003C00u, 0x3C003C00u };

    const int mrow0 = (wid * 16 + rq) * 80;
    const int mrow1 = mrow0 + 8 * 80;

    const int kb_row = ((lane >> 4) << 3) + (lane & 7);
    const int kb_k   = ((lane >> 3) & 1) * 8;
    const int vb_j   = ((lane >> 3) & 1) * 8 + (lane & 7);
    const int vb_d   = (lane >> 4) * 8;

    for (int jt = 0; jt < 16; jt++) {
        if (jt < 15) CPW(1); else CPW(0);
        __syncthreads();
        if (jt < 14) { pf(jt + 2, sb + (unsigned)((jt + 2) % 3) * ASTG); CPC(); }
        const uint32_t base = sb + (unsigned)(jt % 3) * ASTG;
        const char* msm = sm + (size_t)(jt % 3) * ASTG + 16384;

        // S = Q K^T
        float S[8][4];
#pragma unroll
        for (int f = 0; f < 8; f++)
#pragma unroll
            for (int c = 0; c < 4; c++) S[f][c] = 0.0f;
#pragma unroll
        for (int ks = 0; ks < 4; ks++) {
#pragma unroll
            for (int nf4 = 0; nf4 < 4; nf4++) {
                unsigned off = SW128((unsigned)((kb_row + nf4 * 16) * 128 + (kb_k + ks * 16) * 2));
                unsigned bhf[4];
                ldm4(bhf, base + off);
                mma_f16(S[2 * nf4], qh[ks], bhf);
                mma_f16(S[2 * nf4 + 1], qh[ks], bhf + 2);
            }
        }

        // P = 2^(S + tv - C): bias via shfl table, exponent via fp16x2 MUFU
        unsigned ph01[8], ph23[8];
#pragma unroll
        for (int f = 0; f < 8; f++) {
            int cb = f * 8 + q2;
            unsigned short w0 = *(const unsigned short*)(msm + mrow0 + cb);
            unsigned short w1 = *(const unsigned short*)(msm + mrow1 + cb);
            float e0 = S[f][0] + __shfl_sync(0xffffffffu, tv, w0 & 31u);
            float e1 = S[f][1] + __shfl_sync(0xffffffffu, tv, (w0 >> 8) & 31u);
            float e2 = S[f][2] + __shfl_sync(0xffffffffu, tv, w1 & 31u);
            float e3 = S[f][3] + __shfl_sync(0xffffffffu, tv, (w1 >> 8) & 31u);
            ph01[f] = h2ex2(packh2(e0, e1));
            ph23[f] = h2ex2(packh2(e2, e3));
        }

        // O += P V ;  OL += P @ ones
#pragma unroll
        for (int ks = 0; ks < 4; ks++) {
            unsigned ah[4] = { ph01[2 * ks], ph23[2 * ks], ph01[2 * ks + 1], ph23[2 * ks + 1] };
            mma_f16(OL, ah, onesb);
#pragma unroll
            for (int nf4 = 0; nf4 < 4; nf4++) {
                unsigned off = SW128((unsigned)((vb_j + ks * 16) * 128 + (vb_d + nf4 * 16) * 2));
                unsigned bvh[4];
                ldm4t(bvh, base + 8192 + off);
                mma_f16(O[2 * nf4], ah, bvh);
                mma_f16(O[2 * nf4 + 1], ah, bvh + 2);
            }
        }
    }

    // epilogue
    float inv0 = 1.0f / OL[0], inv1 = 1.0f / OL[2];
    const int ig0 = i0 + wid * 16 + rq;
    size_t base0 = ((size_t)(b << 10) + ig0) * 512 + h * 64;
    size_t base1 = base0 + 8 * 512;
#pragma unroll
    for (int f = 0; f < 8; f++) {
        *(unsigned*)(g_aoh + base0 + f * 8 + q2) = packh2(O[f][0] * inv0, O[f][1] * inv0);
        *(unsigned*)(g_aoh + base1 + f * 8 + q2) = packh2(O[f][2] * inv1, O[f][3] * inv1);
    }
}

// ---------------- launch --------------------------------------------------------
extern "C" void kernel_launch(void* const* d_in, const int* in_sizes, int n_in,
                              void* d_out, int out_size) {
    const float* x      = (const float*)d_in[0];
    const float* adj    = (const float*)d_in[1];
    const float* dist   = (const float*)d_in[2];
    const float* w_qkv  = (const float*)d_in[3];
    const float* w_proj = (const float*)d_in[4];
    const float* gamma  = (const float*)d_in[5];
    float* out = (float*)d_out;

    cudaFuncSetAttribute(mm_kernel, cudaFuncAttributeMaxDynamicSharedMemorySize, GDYN);
    cudaFuncSetAttribute(attn_mma, cudaFuncAttributeMaxDynamicSharedMemorySize, ADYN);

    prep1<<<32768 + 16384, 256>>>(adj, dist, x);           // pack + split_x
    prep2<<<8192 + 1024, 256>>>(w_qkv, w_proj);            // mask + split_w
    mm_kernel<<<dim3(12, 64), 256, GDYN>>>(0, nullptr);    // qkv
    attn_mma<<<dim3(L_ / 128, H_, B_), 256, ADYN>>>(gamma);// attn (launch #4 -> profiled)
    mm_kernel<<<dim3(4, 64), 256, GDYN>>>(1, out);         // proj
}

// round 14
// speedup vs baseline: 5.8515x; 1.0498x over previous
#include <cuda_runtime.h>
#include <cuda_fp16.h>
#include <cstdint>

#define B_ 8
#define L_ 1024
#define C_ 512
#define H_ 8
#define D_ 64
#define M_TOT (B_*L_)

// ---------------- static device scratch -------------------------------------
__device__ unsigned g_adjbits[B_*L_*(L_/32)];
__device__ unsigned g_distbits[B_*L_*(L_/32)];
__device__ unsigned char g_mask[(size_t)B_*L_*L_];

__device__ __half g_xh[M_TOT*C_];
__device__ __half g_wqT[3*C_*C_];   // [1536][512] fp16
__device__ __half g_wpT[C_*C_];     // [512][512]  fp16
__device__ __half g_qh[B_*H_*L_*D_];  // pre-scaled (1/8)*log2e
__device__ __half g_kh[B_*H_*L_*D_];
__device__ __half g_vh[B_*H_*L_*D_];
__device__ __half g_aoh[M_TOT*C_];

// ---------------- host-side stream fork (static init; no device mem) ---------
namespace {
struct AuxStream {
    cudaStream_t s = nullptr;
    cudaEvent_t fork = nullptr, join = nullptr;
    AuxStream() {
        cudaStreamCreateWithFlags(&s, cudaStreamNonBlocking);
        cudaEventCreateWithFlags(&fork, cudaEventDisableTiming);
        cudaEventCreateWithFlags(&join, cudaEventDisableTiming);
    }
};
AuxStream g_aux;
}

// ---------------- device helpers ----------------------------------------------
__device__ __forceinline__ uint32_t smem_u32(const void* p) {
    uint32_t a;
    asm("{ .reg .u64 t; cvta.to.shared.u64 t, %1; cvt.u32.u64 %0, t; }" : "=r"(a) : "l"(p));
    return a;
}
#define SW128(o) ((o) ^ (((o) >> 3) & 0x70))

#define CPA(dst, src) asm volatile("cp.async.cg.shared.global [%0], [%1], 16;" :: "r"(dst), "l"(src))
#define CPC()  asm volatile("cp.async.commit_group;")
#define CPW(n) asm volatile("cp.async.wait_group %0;" :: "n"(n))

__device__ __forceinline__ void mma_f16(float* c, const unsigned* a, const unsigned* b) {
    asm volatile("mma.sync.aligned.m16n8k16.row.col.f32.f16.f16.f32 "
        "{%0,%1,%2,%3}, {%4,%5,%6,%7}, {%8,%9}, {%0,%1,%2,%3};"
        : "+f"(c[0]), "+f"(c[1]), "+f"(c[2]), "+f"(c[3])
        : "r"(a[0]), "r"(a[1]), "r"(a[2]), "r"(a[3]), "r"(b[0]), "r"(b[1]));
}
__device__ __forceinline__ void ldm4(unsigned* r, uint32_t a) {
    asm volatile("ldmatrix.sync.aligned.m8n8.x4.shared.b16 {%0,%1,%2,%3}, [%4];"
        : "=r"(r[0]), "=r"(r[1]), "=r"(r[2]), "=r"(r[3]) : "r"(a));
}
__device__ __forceinline__ void ldm4t(unsigned* r, uint32_t a) {
    asm volatile("ldmatrix.sync.aligned.m8n8.x4.trans.shared.b16 {%0,%1,%2,%3}, [%4];"
        : "=r"(r[0]), "=r"(r[1]), "=r"(r[2]), "=r"(r[3]) : "r"(a));
}
__device__ __forceinline__ unsigned packh2(float a, float b) {
    __half2 hv = __floats2half2_rn(a, b);
    return *(unsigned*)&hv;
}
__device__ __forceinline__ unsigned h2ex2(unsigned x) {
    unsigned y;
    asm("ex2.approx.f16x2 %0, %1;" : "=r"(y) : "r"(x));
    return y;
}

// ---------------- fused k1: pack bitmasks + split_x + weight transpose --------
__global__ void prep1(const float* __restrict__ adj, const float* __restrict__ dist,
                      const float* __restrict__ x,
                      const float* __restrict__ wq, const float* __restrict__ wp) {
    unsigned bid = blockIdx.x;
    if (bid < 32768u) {
        unsigned e = bid * 256u + threadIdx.x;
        unsigned j = e & (L_ - 1u), i = (e >> 10) & (L_ - 1u);
        bool ab = (adj[e] != 0.0f) && (i != 0u) && (j != 0u);
        unsigned aw = __ballot_sync(0xffffffffu, ab);
        unsigned dw = __ballot_sync(0xffffffffu, dist[e] > 0.0f);
        if ((threadIdx.x & 31u) == 0u) { g_adjbits[e >> 5] = aw; g_distbits[e >> 5] = dw; }
    } else if (bid < 49152u) {
        unsigned i = (bid - 32768u) * 256u + threadIdx.x;
        g_xh[i] = __float2half_rn(x[i]);
    } else {
        __shared__ float tile[32][33];
        int wb = bid - 49152;
        const float* src; __half* dh; int N;
        if (wb < 768) { src = wq; dh = g_wqT; N = 1536; }
        else          { wb -= 768; src = wp; dh = g_wpT; N = 512; }
        int tn = N >> 5;
        int k0 = (wb / tn) * 32, n0 = (wb % tn) * 32;
        int c = threadIdx.x & 31, r0 = threadIdx.x >> 5;
#pragma unroll
        for (int p = 0; p < 4; p++) {
            int r = r0 + p * 8;
            tile[r][c] = src[(size_t)(k0 + r) * N + n0 + c];
        }
        __syncthreads();
#pragma unroll
        for (int p = 0; p < 4; p++) {
            int r = r0 + p * 8;
            dh[(size_t)(n0 + r) * 512 + k0 + c] = __float2half_rn(tile[c][r]);
        }
    }
}

// ---------------- k2: 5-bit mask (side stream, overlaps qkv) ------------------
__global__ void mask_kernel() {
    const int b = blockIdx.z, i0 = blockIdx.y * 32, j0 = blockIdx.x * 32;
    __shared__ unsigned Ai[32][33], Aj[32][33];
    const int t = threadIdx.x;
#pragma unroll
    for (int k = 0; k < 4; k++) {
        int pos = t + k * 256, r = pos >> 5, w = pos & 31;
        Ai[r][w] = g_adjbits[((b << 10) + i0 + r) * 32 + w];
        Aj[r][w] = g_adjbits[((b << 10) + j0 + r) * 32 + w];
    }
    __syncthreads();
    const int il = t >> 3, jb = (t & 7) << 2, ig = i0 + il;
    const unsigned di = g_distbits[((b << 10) + ig) * 32 + (j0 >> 5)];
    unsigned sbits = 0u;
    for (int w = 0; w < 32; w++) {
        unsigned ai = Ai[il][w];
#pragma unroll
        for (int jj = 0; jj < 4; jj++)
            if (ai & Aj[jb + jj][w]) sbits |= (1u << jj);
        if (sbits == 0xFu) break;
    }
    unsigned word = 0u;
#pragma unroll
    for (int jj = 0; jj < 4; jj++) {
        int jl = jb + jj;
        unsigned fwd = (Ai[il][j0 >> 5] >> jl) & 1u;
        unsigned bwd = (Aj[jl][i0 >> 5] >> il) & 1u;
        unsigned dfw = (di >> jl) & 1u;
        unsigned dbw = (g_distbits[((b << 10) + j0 + jl) * 32 + (i0 >> 5)] >> il) & 1u;
        unsigned st = (sbits >> jj) & 1u;
        word |= (fwd | (bwd << 1) | (dfw << 2) | (dbw << 3) | (st << 4)) << (8 * jj);
    }
    *reinterpret_cast<unsigned*>(g_mask + (((size_t)((b << 10) + ig)) << 10) + j0 + jb) = word;
}

// ---------------- fp16 GEMM: 128x128 CTA tile, K=512, 3-stage -----------------
#define GDYN (98304 + 1024)
__global__ void __launch_bounds__(256) mm_kernel(int mode, float* __restrict__ out) {
    extern __shared__ char raw[];
    uint32_t rb = smem_u32(raw);
    char* sm = raw + ((1024u - (rb & 1023u)) & 1023u);
    const uint32_t sb = smem_u32(sm);
    const int t = threadIdx.x, lane = t & 31, wid = t >> 5;
    const int wm = wid & 3, wn = wid >> 2;
    const int n0 = blockIdx.x * 128, m0 = blockIdx.y * 128;

    const __half *Ah, *Bh;
    if (mode == 0) { Ah = g_xh;  Bh = g_wqT; }
    else           { Ah = g_aoh; Bh = g_wpT; }

    float C[2][8][4];
#pragma unroll
    for (int m = 0; m < 2; m++)
#pragma unroll
        for (int f = 0; f < 8; f++)
#pragma unroll
            for (int c = 0; c < 4; c++) C[m][f][c] = 0.0f;

    const int a_row = wm * 32 + (lane & 15);
    const int a_k   = (lane >> 4) * 8;
    const int b_row = wn * 64 + ((lane >> 4) << 3) + (lane & 7);
    const int b_k   = ((lane >> 3) & 1) * 8;

    auto pf = [&](int kc, uint32_t stb) {
#pragma unroll
        for (int i = 0; i < 4; i++) {
            int pos = t + i * 256, row = pos >> 3, cs = pos & 7;
            unsigned off = SW128((unsigned)(row * 128 + cs * 16));
            size_t ga = (size_t)(m0 + row) * 512 + kc * 64 + cs * 8;
            size_t gb = (size_t)(n0 + row) * 512 + kc * 64 + cs * 8;
            CPA(stb + off,         Ah + ga);
            CPA(stb + 16384 + off, Bh + gb);
        }
    };
    pf(0, sb); CPC();
    pf(1, sb + 32768u); CPC();

    for (int kc = 0; kc < 8; kc++) {
        if (kc < 7) CPW(1); else CPW(0);
        __syncthreads();
        if (kc < 6) { pf(kc + 2, sb + (unsigned)((kc + 2) % 3) * 32768u); CPC(); }
        const uint32_t base = sb + (unsigned)(kc % 3) * 32768u;
#pragma unroll
        for (int ks = 0; ks < 4; ks++) {
            unsigned ah[2][4];
#pragma unroll
            for (int mf = 0; mf < 2; mf++) {
                unsigned off = SW128((unsigned)((a_row + mf * 16) * 128 + (a_k + ks * 16) * 2));
                ldm4(ah[mf], base + off);
            }
#pragma unroll
            for (int nf4 = 0; nf4 < 4; nf4++) {
                unsigned off = SW128((unsigned)((b_row + nf4 * 16) * 128 + (b_k + ks * 16) * 2));
                unsigned bh[4];
                ldm4(bh, base + 16384 + off);
#pragma unroll
                for (int mf = 0; mf < 2; mf++) {
                    mma_f16(C[mf][2 * nf4], ah[mf], bh);
                    mma_f16(C[mf][2 * nf4 + 1], ah[mf], bh + 2);
                }
            }
        }
    }

    const int rq = lane >> 2, q2 = 2 * (lane & 3);
    if (mode == 1) {
#pragma unroll
        for (int mf = 0; mf < 2; mf++)
#pragma unroll
            for (int f = 0; f < 8; f++) {
                int row = m0 + wm * 32 + mf * 16 + rq;
                int col = n0 + wn * 64 + f * 8 + q2;
                float2 v0; v0.x = C[mf][f][0]; v0.y = C[mf][f][1];
                float2 v1; v1.x = C[mf][f][2]; v1.y = C[mf][f][3];
                *(float2*)(out + (size_t)row * 512 + col) = v0;
                *(float2*)(out + (size_t)(row + 8) * 512 + col) = v1;
            }
    } else {
        int part = n0 >> 9;
        int h = ((n0 + wn * 64) >> 6) & 7;
        __half* dst = (part == 0) ? g_qh : (part == 1) ? g_kh : g_vh;
        float sc = (part == 0) ? 0.125f * 1.44269504f : 1.0f;
        int bb = m0 >> 10, lbase = (m0 & 1023) + wm * 32;
#pragma unroll
        for (int mf = 0; mf < 2; mf++)
#pragma unroll
            for (int f = 0; f < 8; f++) {
                int ll = lbase + mf * 16 + rq;
                size_t base = ((size_t)(bb * 8 + h) * 1024 + ll) * 64 + f * 8 + q2;
                *(unsigned*)(dst + base)          = packh2(C[mf][f][0] * sc, C[mf][f][1] * sc);
                *(unsigned*)(dst + base + 8 * 64) = packh2(C[mf][f][2] * sc, C[mf][f][3] * sc);
            }
    }
}

// ---------------- attention: fixed-offset softmax, group-pipelined S/P/PV -----
// stage s at s*26624: Kh 0, Vh 8192, Mask 16384 (128 rows x 80B)
#define ASTG 26624
#define ADYN (3*ASTG + 1024)
__global__ void __launch_bounds__(256, 2) attn_mma(const float* __restrict__ gamma) {
    extern __shared__ char raw[];
    uint32_t rb = smem_u32(raw);
    char* sm = raw + ((1024u - (rb & 1023u)) & 1023u);
    const uint32_t sb = smem_u32(sm);
    const int t = threadIdx.x, lane = t & 31, wid = t >> 5;
    const int b = blockIdx.z, h = blockIdx.y, i0 = blockIdx.x * 128;
    const int bh = b * H_ + h;
    const int rq = lane >> 2, q2 = 2 * (lane & 3);

    // per-lane bias table, base-2 domain, minus fixed softmax offset C=4
    float tv = 0.0f;
#pragma unroll
    for (int kk = 0; kk < 5; kk++)
        if ((lane >> kk) & 1) tv += gamma[h * 5 + kk];
    tv = tv * 1.44269504f - 4.0f;

    // stage Q (128x64 fp16), build A-fragments
#pragma unroll
    for (int i = 0; i < 4; i++) {
        int pos = t + i * 256, row = pos >> 3, cs = pos & 7;
        unsigned off = SW128((unsigned)(row * 128 + cs * 16));
        size_t g = ((size_t)bh * L_ + i0 + row) * 64 + cs * 8;
        *(uint4*)(sm + off) = *(const uint4*)(g_qh + g);
    }
    __syncthreads();
    unsigned qh[4][4];
    {
        int arow = wid * 16 + (lane & 15);
        int ak = (lane >> 4) * 8;
#pragma unroll
        for (int ks = 0; ks < 4; ks++) {
            unsigned off = SW128((unsigned)(arow * 128 + (ak + ks * 16) * 2));
            ldm4(qh[ks], sb + off);
        }
    }
    __syncthreads();

    const unsigned char* mbase = g_mask + ((size_t)b << 20) + (size_t)i0 * 1024;

    auto pf = [&](int jtile, uint32_t stb) {
        int j0 = jtile * 64;
#pragma unroll
        for (int i = 0; i < 2; i++) {
            int pos = t + i * 256, row = pos >> 3, cs = pos & 7;
            unsigned off = SW128((unsigned)(row * 128 + cs * 16));
            size_t g = ((size_t)bh * L_ + j0 + row) * 64 + cs * 8;
            CPA(stb + off,        g_kh + g);
            CPA(stb + 8192 + off, g_vh + g);
            int mrow = pos >> 2, mcs = pos & 3;
            CPA(stb + 16384u + (unsigned)(mrow * 80 + mcs * 16),
                mbase + (size_t)mrow * 1024 + j0 + mcs * 16);
        }
    };
    pf(0, sb); CPC();
    pf(1, sb + ASTG); CPC();

    float O[8][4];
#pragma unroll
    for (int f = 0; f < 8; f++)
#pragma unroll
        for (int c = 0; c < 4; c++) O[f][c] = 0.0f;
    float OL[4] = {0.0f, 0.0f, 0.0f, 0.0f};

    const unsigned onesb[2] = { 0x3C003C00u, 0x3C003C00u };

    const int mrow0 = (wid * 16 + rq) * 80;
    const int mrow1 = mrow0 + 8 * 80;

    const int kb_row = ((lane >> 4) << 3) + (lane & 7);
    const int kb_k   = ((lane >> 3) & 1) * 8;
    const int vb_j   = ((lane >> 3) & 1) * 8 + (lane & 7);
    const int vb_d   = (lane >> 4) * 8;

    for (int jt = 0; jt < 16; jt++) {
        if (jt < 15) CPW(1); else CPW(0);
        __syncthreads();
        if (jt < 14) { pf(jt + 2, sb + (unsigned)((jt + 2) % 3) * ASTG); CPC(); }
        const uint32_t base = sb + (unsigned)(jt % 3) * ASTG;
        const char* msm = sm + (size_t)(jt % 3) * ASTG + 16384;

        // group-pipelined: S(g) -> softmax(g) -> PV step g ; PV(g) overlaps
        // with S/softmax(g+1) via ILP (independent accumulators).
#pragma unroll
        for (int g = 0; g < 4; g++) {
            float S0[4] = {0.f, 0.f, 0.f, 0.f};
            float S1[4] = {0.f, 0.f, 0.f, 0.f};
#pragma unroll
            for (int ks = 0; ks < 4; ks++) {
                unsigned off = SW128((unsigned)((kb_row + g * 16) * 128 + (kb_k + ks * 16) * 2));
                unsigned bhf[4];
                ldm4(bhf, base + off);
                mma_f16(S0, qh[ks], bhf);
                mma_f16(S1, qh[ks], bhf + 2);
            }
            // softmax for f0=2g (S0), f1=2g+1 (S1)
            int cb0 = (2 * g) * 8 + q2, cb1 = cb0 + 8;
            unsigned short a0 = *(const unsigned short*)(msm + mrow0 + cb0);
            unsigned short a1 = *(const unsigned short*)(msm + mrow1 + cb0);
            unsigned short b0 = *(const unsigned short*)(msm + mrow0 + cb1);
            unsigned short b1 = *(const unsigned short*)(msm + mrow1 + cb1);
            float e0 = S0[0] + __shfl_sync(0xffffffffu, tv, a0 & 31u);
            float e1 = S0[1] + __shfl_sync(0xffffffffu, tv, (a0 >> 8) & 31u);
            float e2 = S0[2] + __shfl_sync(0xffffffffu, tv, a1 & 31u);
            float e3 = S0[3] + __shfl_sync(0xffffffffu, tv, (a1 >> 8) & 31u);
            float f0 = S1[0] + __shfl_sync(0xffffffffu, tv, b0 & 31u);
            float f1 = S1[1] + __shfl_sync(0xffffffffu, tv, (b0 >> 8) & 31u);
            float f2 = S1[2] + __shfl_sync(0xffffffffu, tv, b1 & 31u);
            float f3 = S1[3] + __shfl_sync(0xffffffffu, tv, (b1 >> 8) & 31u);
            unsigned ah[4];
            ah[0] = h2ex2(packh2(e0, e1));
            ah[1] = h2ex2(packh2(e2, e3));
            ah[2] = h2ex2(packh2(f0, f1));
            ah[3] = h2ex2(packh2(f2, f3));
            // PV step g
            mma_f16(OL, ah, onesb);
#pragma unroll
            for (int nf4 = 0; nf4 < 4; nf4++) {
                unsigned off = SW128((unsigned)((vb_j + g * 16) * 128 + (vb_d + nf4 * 16) * 2));
                unsigned bvh[4];
                ldm4t(bvh, base + 8192 + off);
                mma_f16(O[2 * nf4], ah, bvh);
                mma_f16(O[2 * nf4 + 1], ah, bvh + 2);
            }
        }
    }

    // epilogue
    float inv0 = 1.0f / OL[0], inv1 = 1.0f / OL[2];
    const int ig0 = i0 + wid * 16 + rq;
    size_t base0 = ((size_t)(b << 10) + ig0) * 512 + h * 64;
    size_t base1 = base0 + 8 * 512;
#pragma unroll
    for (int f = 0; f < 8; f++) {
        *(unsigned*)(g_aoh + base0 + f * 8 + q2) = packh2(O[f][0] * inv0, O[f][1] * inv0);
        *(unsigned*)(g_aoh + base1 + f * 8 + q2) = packh2(O[f][2] * inv1, O[f][3] * inv1);
    }
}

// ---------------- launch --------------------------------------------------------
extern "C" void kernel_launch(void* const* d_in, const int* in_sizes, int n_in,
                              void* d_out, int out_size) {
    const float* x      = (const float*)d_in[0];
    const float* adj    = (const float*)d_in[1];
    const float* dist   = (const float*)d_in[2];
    const float* w_qkv  = (const float*)d_in[3];
    const float* w_proj = (const float*)d_in[4];
    const float* gamma  = (const float*)d_in[5];
    float* out = (float*)d_out;

    cudaFuncSetAttribute(mm_kernel, cudaFuncAttributeMaxDynamicSharedMemorySize, GDYN);
    cudaFuncSetAttribute(attn_mma, cudaFuncAttributeMaxDynamicSharedMemorySize, ADYN);

    cudaStream_t ms = cudaStreamPerThread;

    prep1<<<32768 + 16384 + 1024, 256, 0, ms>>>(adj, dist, x, w_qkv, w_proj);

    // fork: mask on side stream, overlapped with qkv GEMM
    cudaEventRecord(g_aux.fork, ms);
    cudaStreamWaitEvent(g_aux.s, g_aux.fork, 0);
    mask_kernel<<<dim3(32, 32, B_), 256, 0, g_aux.s>>>();
    cudaEventRecord(g_aux.join, g_aux.s);

    mm_kernel<<<dim3(12, 64), 256, GDYN, ms>>>(0, nullptr);   // qkv

    cudaStreamWaitEvent(ms, g_aux.join, 0);
    attn_mma<<<dim3(L_ / 128, H_, B_), 256, ADYN, ms>>>(gamma);
    mm_kernel<<<dim3(4, 64), 256, GDYN, ms>>>(1, out);        // proj
}

// round 15
// speedup vs baseline: 6.0597x; 1.0356x over previous
#include <cuda_runtime.h>
#include <cuda_fp16.h>
#include <cstdint>

#define B_ 8
#define L_ 1024
#define C_ 512
#define H_ 8
#define D_ 64
#define M_TOT (B_*L_)

// ---------------- static device scratch -------------------------------------
__device__ unsigned g_adjbits[B_*L_*(L_/32)];
__device__ unsigned g_distbits[B_*L_*(L_/32)];
__device__ unsigned char g_mask[(size_t)B_*L_*L_];

__device__ __half g_xh[M_TOT*C_];
__device__ __half g_wqT[3*C_*C_];   // [1536][512] fp16
__device__ __half g_wpT[C_*C_];     // [512][512]  fp16
__device__ __half g_qh[B_*H_*L_*D_];  // pre-scaled (1/8)*log2e
__device__ __half g_kh[B_*H_*L_*D_];
__device__ __half g_vh[B_*H_*L_*D_];
__device__ __half g_aoh[M_TOT*C_];

// ---------------- host-side stream fork (static init; no device mem) ---------
namespace {
struct AuxStream {
    cudaStream_t s = nullptr;
    cudaEvent_t fork = nullptr, join = nullptr;
    AuxStream() {
        cudaStreamCreateWithFlags(&s, cudaStreamNonBlocking);
        cudaEventCreateWithFlags(&fork, cudaEventDisableTiming);
        cudaEventCreateWithFlags(&join, cudaEventDisableTiming);
    }
};
AuxStream g_aux;
}

// ---------------- device helpers ----------------------------------------------
__device__ __forceinline__ uint32_t smem_u32(const void* p) {
    uint32_t a;
    asm("{ .reg .u64 t; cvta.to.shared.u64 t, %1; cvt.u32.u64 %0, t; }" : "=r"(a) : "l"(p));
    return a;
}
#define SW128(o) ((o) ^ (((o) >> 3) & 0x70))

#define CPA(dst, src) asm volatile("cp.async.cg.shared.global [%0], [%1], 16;" :: "r"(dst), "l"(src))
#define CPC()  asm volatile("cp.async.commit_group;")
#define CPW(n) asm volatile("cp.async.wait_group %0;" :: "n"(n))

__device__ __forceinline__ void mma_f16(float* c, const unsigned* a, const unsigned* b) {
    asm volatile("mma.sync.aligned.m16n8k16.row.col.f32.f16.f16.f32 "
        "{%0,%1,%2,%3}, {%4,%5,%6,%7}, {%8,%9}, {%0,%1,%2,%3};"
        : "+f"(c[0]), "+f"(c[1]), "+f"(c[2]), "+f"(c[3])
        : "r"(a[0]), "r"(a[1]), "r"(a[2]), "r"(a[3]), "r"(b[0]), "r"(b[1]));
}
__device__ __forceinline__ void ldm4(unsigned* r, uint32_t a) {
    asm volatile("ldmatrix.sync.aligned.m8n8.x4.shared.b16 {%0,%1,%2,%3}, [%4];"
        : "=r"(r[0]), "=r"(r[1]), "=r"(r[2]), "=r"(r[3]) : "r"(a));
}
__device__ __forceinline__ void ldm4t(unsigned* r, uint32_t a) {
    asm volatile("ldmatrix.sync.aligned.m8n8.x4.trans.shared.b16 {%0,%1,%2,%3}, [%4];"
        : "=r"(r[0]), "=r"(r[1]), "=r"(r[2]), "=r"(r[3]) : "r"(a));
}
__device__ __forceinline__ unsigned packh2(float a, float b) {
    __half2 hv = __floats2half2_rn(a, b);
    return *(unsigned*)&hv;
}
__device__ __forceinline__ unsigned h2ex2(unsigned x) {
    unsigned y;
    asm("ex2.approx.f16x2 %0, %1;" : "=r"(y) : "r"(x));
    return y;
}

// ---------------- fused k1: pack bitmasks + split_x + weight transpose --------
__global__ void prep1(const float* __restrict__ adj, const float* __restrict__ dist,
                      const float* __restrict__ x,
                      const float* __restrict__ wq, const float* __restrict__ wp) {
    unsigned bid = blockIdx.x;
    if (bid < 32768u) {
        unsigned e = bid * 256u + threadIdx.x;
        unsigned j = e & (L_ - 1u), i = (e >> 10) & (L_ - 1u);
        bool ab = (adj[e] != 0.0f) && (i != 0u) && (j != 0u);
        unsigned aw = __ballot_sync(0xffffffffu, ab);
        unsigned dw = __ballot_sync(0xffffffffu, dist[e] > 0.0f);
        if ((threadIdx.x & 31u) == 0u) { g_adjbits[e >> 5] = aw; g_distbits[e >> 5] = dw; }
    } else if (bid < 49152u) {
        unsigned i = (bid - 32768u) * 256u + threadIdx.x;
        g_xh[i] = __float2half_rn(x[i]);
    } else {
        __shared__ float tile[32][33];
        int wb = bid - 49152;
        const float* src; __half* dh; int N;
        if (wb < 768) { src = wq; dh = g_wqT; N = 1536; }
        else          { wb -= 768; src = wp; dh = g_wpT; N = 512; }
        int tn = N >> 5;
        int k0 = (wb / tn) * 32, n0 = (wb % tn) * 32;
        int c = threadIdx.x & 31, r0 = threadIdx.x >> 5;
#pragma unroll
        for (int p = 0; p < 4; p++) {
            int r = r0 + p * 8;
            tile[r][c] = src[(size_t)(k0 + r) * N + n0 + c];
        }
        __syncthreads();
#pragma unroll
        for (int p = 0; p < 4; p++) {
            int r = r0 + p * 8;
            dh[(size_t)(n0 + r) * 512 + k0 + c] = __float2half_rn(tile[c][r]);
        }
    }
}

// ---------------- k2: 5-bit mask (side stream, overlaps qkv) ------------------
__global__ void mask_kernel() {
    const int b = blockIdx.z, i0 = blockIdx.y * 32, j0 = blockIdx.x * 32;
    __shared__ unsigned Ai[32][33], Aj[32][33];
    const int t = threadIdx.x;
#pragma unroll
    for (int k = 0; k < 4; k++) {
        int pos = t + k * 256, r = pos >> 5, w = pos & 31;
        Ai[r][w] = g_adjbits[((b << 10) + i0 + r) * 32 + w];
        Aj[r][w] = g_adjbits[((b << 10) + j0 + r) * 32 + w];
    }
    __syncthreads();
    const int il = t >> 3, jb = (t & 7) << 2, ig = i0 + il;
    const unsigned di = g_distbits[((b << 10) + ig) * 32 + (j0 >> 5)];
    unsigned sbits = 0u;
    for (int w = 0; w < 32; w++) {
        unsigned ai = Ai[il][w];
#pragma unroll
        for (int jj = 0; jj < 4; jj++)
            if (ai & Aj[jb + jj][w]) sbits |= (1u << jj);
        if (sbits == 0xFu) break;
    }
    unsigned word = 0u;
#pragma unroll
    for (int jj = 0; jj < 4; jj++) {
        int jl = jb + jj;
        unsigned fwd = (Ai[il][j0 >> 5] >> jl) & 1u;
        unsigned bwd = (Aj[jl][i0 >> 5] >> il) & 1u;
        unsigned dfw = (di >> jl) & 1u;
        unsigned dbw = (g_distbits[((b << 10) + j0 + jl) * 32 + (i0 >> 5)] >> il) & 1u;
        unsigned st = (sbits >> jj) & 1u;
        word |= (fwd | (bwd << 1) | (dfw << 2) | (dbw << 3) | (st << 4)) << (8 * jj);
    }
    *reinterpret_cast<unsigned*>(g_mask + (((size_t)((b << 10) + ig)) << 10) + j0 + jb) = word;
}

// ---------------- fp16 GEMM: 128x128 CTA tile, K=512, 3-stage -----------------
#define GDYN (98304 + 1024)
__global__ void __launch_bounds__(256) mm_kernel(int mode, float* __restrict__ out) {
    extern __shared__ char raw[];
    uint32_t rb = smem_u32(raw);
    char* sm = raw + ((1024u - (rb & 1023u)) & 1023u);
    const uint32_t sb = smem_u32(sm);
    const int t = threadIdx.x, lane = t & 31, wid = t >> 5;
    const int wm = wid & 3, wn = wid >> 2;
    const int n0 = blockIdx.x * 128, m0 = blockIdx.y * 128;

    const __half *Ah, *Bh;
    if (mode == 0) { Ah = g_xh;  Bh = g_wqT; }
    else           { Ah = g_aoh; Bh = g_wpT; }

    float C[2][8][4];
#pragma unroll
    for (int m = 0; m < 2; m++)
#pragma unroll
        for (int f = 0; f < 8; f++)
#pragma unroll
            for (int c = 0; c < 4; c++) C[m][f][c] = 0.0f;

    const int a_row = wm * 32 + (lane & 15);
    const int a_k   = (lane >> 4) * 8;
    const int b_row = wn * 64 + ((lane >> 4) << 3) + (lane & 7);
    const int b_k   = ((lane >> 3) & 1) * 8;

    auto pf = [&](int kc, uint32_t stb) {
#pragma unroll
        for (int i = 0; i < 4; i++) {
            int pos = t + i * 256, row = pos >> 3, cs = pos & 7;
            unsigned off = SW128((unsigned)(row * 128 + cs * 16));
            size_t ga = (size_t)(m0 + row) * 512 + kc * 64 + cs * 8;
            size_t gb = (size_t)(n0 + row) * 512 + kc * 64 + cs * 8;
            CPA(stb + off,         Ah + ga);
            CPA(stb + 16384 + off, Bh + gb);
        }
    };
    pf(0, sb); CPC();
    pf(1, sb + 32768u); CPC();

    for (int kc = 0; kc < 8; kc++) {
        if (kc < 7) CPW(1); else CPW(0);
        __syncthreads();
        if (kc < 6) { pf(kc + 2, sb + (unsigned)((kc + 2) % 3) * 32768u); CPC(); }
        const uint32_t base = sb + (unsigned)(kc % 3) * 32768u;
#pragma unroll
        for (int ks = 0; ks < 4; ks++) {
            unsigned ah[2][4];
#pragma unroll
            for (int mf = 0; mf < 2; mf++) {
                unsigned off = SW128((unsigned)((a_row + mf * 16) * 128 + (a_k + ks * 16) * 2));
                ldm4(ah[mf], base + off);
            }
#pragma unroll
            for (int nf4 = 0; nf4 < 4; nf4++) {
                unsigned off = SW128((unsigned)((b_row + nf4 * 16) * 128 + (b_k + ks * 16) * 2));
                unsigned bh[4];
                ldm4(bh, base + 16384 + off);
#pragma unroll
                for (int mf = 0; mf < 2; mf++) {
                    mma_f16(C[mf][2 * nf4], ah[mf], bh);
                    mma_f16(C[mf][2 * nf4 + 1], ah[mf], bh + 2);
                }
            }
        }
    }

    const int rq = lane >> 2, q2 = 2 * (lane & 3);
    if (mode == 1) {
#pragma unroll
        for (int mf = 0; mf < 2; mf++)
#pragma unroll
            for (int f = 0; f < 8; f++) {
                int row = m0 + wm * 32 + mf * 16 + rq;
                int col = n0 + wn * 64 + f * 8 + q2;
                float2 v0; v0.x = C[mf][f][0]; v0.y = C[mf][f][1];
                float2 v1; v1.x = C[mf][f][2]; v1.y = C[mf][f][3];
                *(float2*)(out + (size_t)row * 512 + col) = v0;
                *(float2*)(out + (size_t)(row + 8) * 512 + col) = v1;
            }
    } else {
        int part = n0 >> 9;
        int h = ((n0 + wn * 64) >> 6) & 7;
        __half* dst = (part == 0) ? g_qh : (part == 1) ? g_kh : g_vh;
        float sc = (part == 0) ? 0.125f * 1.44269504f : 1.0f;
        int bb = m0 >> 10, lbase = (m0 & 1023) + wm * 32;
#pragma unroll
        for (int mf = 0; mf < 2; mf++)
#pragma unroll
            for (int f = 0; f < 8; f++) {
                int ll = lbase + mf * 16 + rq;
                size_t base = ((size_t)(bb * 8 + h) * 1024 + ll) * 64 + f * 8 + q2;
                *(unsigned*)(dst + base)          = packh2(C[mf][f][0] * sc, C[mf][f][1] * sc);
                *(unsigned*)(dst + base + 8 * 64) = packh2(C[mf][f][2] * sc, C[mf][f][3] * sc);
            }
    }
}

// ---------------- attention: 128 thr / 64 q-rows, 4 CTAs/SM, 2-stage ----------
// stage s at s*21504 (21*1024): Kh 0, Vh 8192, Mask 16384 (64 rows x 80B)
#define ASTG 21504
#define ADYN (2*ASTG + 1024)
__global__ void __launch_bounds__(128, 4) attn_mma(const float* __restrict__ gamma) {
    extern __shared__ char raw[];
    uint32_t rb = smem_u32(raw);
    char* sm = raw + ((1024u - (rb & 1023u)) & 1023u);
    const uint32_t sb = smem_u32(sm);
    const int t = threadIdx.x, lane = t & 31, wid = t >> 5;   // 4 warps
    const int b = blockIdx.z, h = blockIdx.y, i0 = blockIdx.x * 64;
    const int bh = b * H_ + h;
    const int rq = lane >> 2, q2 = 2 * (lane & 3);

    // per-lane bias table, base-2 domain, minus fixed softmax offset C=4
    float tv = 0.0f;
#pragma unroll
    for (int kk = 0; kk < 5; kk++)
        if ((lane >> kk) & 1) tv += gamma[h * 5 + kk];
    tv = tv * 1.44269504f - 4.0f;

    // stage Q (64x64 fp16) into stage0 KV region, build A-fragments
#pragma unroll
    for (int i = 0; i < 4; i++) {
        int pos = t + i * 128, row = pos >> 3, cs = pos & 7;
        unsigned off = SW128((unsigned)(row * 128 + cs * 16));
        size_t g = ((size_t)bh * L_ + i0 + row) * 64 + cs * 8;
        *(uint4*)(sm + off) = *(const uint4*)(g_qh + g);
    }
    __syncthreads();
    unsigned qh[4][4];
    {
        int arow = wid * 16 + (lane & 15);
        int ak = (lane >> 4) * 8;
#pragma unroll
        for (int ks = 0; ks < 4; ks++) {
            unsigned off = SW128((unsigned)(arow * 128 + (ak + ks * 16) * 2));
            ldm4(qh[ks], sb + off);
        }
    }
    __syncthreads();

    const unsigned char* mbase = g_mask + ((size_t)b << 20) + (size_t)i0 * 1024;

    auto pf = [&](int jtile, uint32_t stb) {
        int j0 = jtile * 64;
#pragma unroll
        for (int i = 0; i < 4; i++) {
            int pos = t + i * 128, row = pos >> 3, cs = pos & 7;
            unsigned off = SW128((unsigned)(row * 128 + cs * 16));
            size_t g = ((size_t)bh * L_ + j0 + row) * 64 + cs * 8;
            CPA(stb + off,        g_kh + g);
            CPA(stb + 8192 + off, g_vh + g);
            if (i < 2) {
                int mrow = pos >> 2, mcs = pos & 3;
                CPA(stb + 16384u + (unsigned)(mrow * 80 + mcs * 16),
                    mbase + (size_t)mrow * 1024 + j0 + mcs * 16);
            }
        }
    };
    pf(0, sb); CPC();

    float O[8][4];
#pragma unroll
    for (int f = 0; f < 8; f++)
#pragma unroll
        for (int c = 0; c < 4; c++) O[f][c] = 0.0f;
    float OL[4] = {0.0f, 0.0f, 0.0f, 0.0f};

    const unsigned onesb[2] = { 0x3C003C00u, 0x3C003C00u };

    const int mrow0 = (wid * 16 + rq) * 80;
    const int mrow1 = mrow0 + 8 * 80;

    const int kb_row = ((lane >> 4) << 3) + (lane & 7);
    const int kb_k   = ((lane >> 3) & 1) * 8;
    const int vb_j   = ((lane >> 3) & 1) * 8 + (lane & 7);
    const int vb_d   = (lane >> 4) * 8;

    for (int jt = 0; jt < 16; jt++) {
        CPW(0);
        __syncthreads();   // stage jt&1 ready; prior consumption of other stage done
        if (jt < 15) { pf(jt + 1, sb + (unsigned)((jt + 1) & 1) * ASTG); CPC(); }
        const uint32_t base = sb + (unsigned)(jt & 1) * ASTG;
        const char* msm = sm + (size_t)(jt & 1) * ASTG + 16384;

        // group-pipelined: S(g) -> softmax(g) -> PV step g
#pragma unroll
        for (int g = 0; g < 4; g++) {
            float S0[4] = {0.f, 0.f, 0.f, 0.f};
            float S1[4] = {0.f, 0.f, 0.f, 0.f};
#pragma unroll
            for (int ks = 0; ks < 4; ks++) {
                unsigned off = SW128((unsigned)((kb_row + g * 16) * 128 + (kb_k + ks * 16) * 2));
                unsigned bhf[4];
                ldm4(bhf, base + off);
                mma_f16(S0, qh[ks], bhf);
                mma_f16(S1, qh[ks], bhf + 2);
            }
            int cb0 = (2 * g) * 8 + q2, cb1 = cb0 + 8;
            unsigned short a0 = *(const unsigned short*)(msm + mrow0 + cb0);
            unsigned short a1 = *(const unsigned short*)(msm + mrow1 + cb0);
            unsigned short b0 = *(const unsigned short*)(msm + mrow0 + cb1);
            unsigned short b1 = *(const unsigned short*)(msm + mrow1 + cb1);
            float e0 = S0[0] + __shfl_sync(0xffffffffu, tv, a0 & 31u);
            float e1 = S0[1] + __shfl_sync(0xffffffffu, tv, (a0 >> 8) & 31u);
            float e2 = S0[2] + __shfl_sync(0xffffffffu, tv, a1 & 31u);
            float e3 = S0[3] + __shfl_sync(0xffffffffu, tv, (a1 >> 8) & 31u);
            float f0 = S1[0] + __shfl_sync(0xffffffffu, tv, b0 & 31u);
            float f1 = S1[1] + __shfl_sync(0xffffffffu, tv, (b0 >> 8) & 31u);
            float f2 = S1[2] + __shfl_sync(0xffffffffu, tv, b1 & 31u);
            float f3 = S1[3] + __shfl_sync(0xffffffffu, tv, (b1 >> 8) & 31u);
            unsigned ah[4];
            ah[0] = h2ex2(packh2(e0, e1));
            ah[1] = h2ex2(packh2(e2, e3));
            ah[2] = h2ex2(packh2(f0, f1));
            ah[3] = h2ex2(packh2(f2, f3));
            mma_f16(OL, ah, onesb);
#pragma unroll
            for (int nf4 = 0; nf4 < 4; nf4++) {
                unsigned off = SW128((unsigned)((vb_j + g * 16) * 128 + (vb_d + nf4 * 16) * 2));
                unsigned bvh[4];
                ldm4t(bvh, base + 8192 + off);
                mma_f16(O[2 * nf4], ah, bvh);
                mma_f16(O[2 * nf4 + 1], ah, bvh + 2);
            }
        }
    }

    // epilogue
    float inv0 = 1.0f / OL[0], inv1 = 1.0f / OL[2];
    const int ig0 = i0 + wid * 16 + rq;
    size_t base0 = ((size_t)(b << 10) + ig0) * 512 + h * 64;
    size_t base1 = base0 + 8 * 512;
#pragma unroll
    for (int f = 0; f < 8; f++) {
        *(unsigned*)(g_aoh + base0 + f * 8 + q2) = packh2(O[f][0] * inv0, O[f][1] * inv0);
        *(unsigned*)(g_aoh + base1 + f * 8 + q2) = packh2(O[f][2] * inv1, O[f][3] * inv1);
    }
}

// ---------------- launch --------------------------------------------------------
extern "C" void kernel_launch(void* const* d_in, const int* in_sizes, int n_in,
                              void* d_out, int out_size) {
    const float* x      = (const float*)d_in[0];
    const float* adj    = (const float*)d_in[1];
    const float* dist   = (const float*)d_in[2];
    const float* w_qkv  = (const float*)d_in[3];
    const float* w_proj = (const float*)d_in[4];
    const float* gamma  = (const float*)d_in[5];
    float* out = (float*)d_out;

    cudaFuncSetAttribute(mm_kernel, cudaFuncAttributeMaxDynamicSharedMemorySize, GDYN);
    cudaFuncSetAttribute(attn_mma, cudaFuncAttributeMaxDynamicSharedMemorySize, ADYN);

    cudaStream_t ms = cudaStreamPerThread;

    prep1<<<32768 + 16384 + 1024, 256, 0, ms>>>(adj, dist, x, w_qkv, w_proj);

    // fork: mask on side stream, overlapped with qkv GEMM
    cudaEventRecord(g_aux.fork, ms);
    cudaStreamWaitEvent(g_aux.s, g_aux.fork, 0);
    mask_kernel<<<dim3(32, 32, B_), 256, 0, g_aux.s>>>();
    cudaEventRecord(g_aux.join, g_aux.s);

    mm_kernel<<<dim3(12, 64), 256, GDYN, ms>>>(0, nullptr);   // qkv

    cudaStreamWaitEvent(ms, g_aux.join, 0);
    attn_mma<<<dim3(L_ / 64, H_, B_), 128, ADYN, ms>>>(gamma);
    mm_kernel<<<dim3(4, 64), 256, GDYN, ms>>>(1, out);        // proj
}

// round 16
// speedup vs baseline: 6.1175x; 1.0095x over previous
#include <cuda_runtime.h>
#include <cuda_fp16.h>
#include <cstdint>

#define B_ 8
#define L_ 1024
#define C_ 512
#define H_ 8
#define D_ 64
#define M_TOT (B_*L_)

// ---------------- static device scratch -------------------------------------
__device__ unsigned g_adjbits[B_*L_*(L_/32)];
__device__ unsigned g_distbits[B_*L_*(L_/32)];
__device__ unsigned char g_mask[(size_t)B_*L_*L_];

__device__ __half g_xh[M_TOT*C_];
__device__ __half g_wqT[3*C_*C_];   // [1536][512] fp16
__device__ __half g_wpT[C_*C_];     // [512][512]  fp16
__device__ __half g_qh[B_*H_*L_*D_];  // pre-scaled (1/8)*log2e
__device__ __half g_kh[B_*H_*L_*D_];
__device__ __half g_vh[B_*H_*L_*D_];
__device__ __half g_aoh[M_TOT*C_];

// ---------------- host-side stream fork (static init; no device mem) ---------
namespace {
struct AuxStream {
    cudaStream_t s = nullptr;
    cudaEvent_t fork = nullptr, join = nullptr;
    AuxStream() {
        cudaStreamCreateWithFlags(&s, cudaStreamNonBlocking);
        cudaEventCreateWithFlags(&fork, cudaEventDisableTiming);
        cudaEventCreateWithFlags(&join, cudaEventDisableTiming);
    }
};
AuxStream g_aux;
}

// ---------------- device helpers ----------------------------------------------
__device__ __forceinline__ uint32_t smem_u32(const void* p) {
    uint32_t a;
    asm("{ .reg .u64 t; cvta.to.shared.u64 t, %1; cvt.u32.u64 %0, t; }" : "=r"(a) : "l"(p));
    return a;
}
#define SW128(o) ((o) ^ (((o) >> 3) & 0x70))

#define CPA(dst, src) asm volatile("cp.async.cg.shared.global [%0], [%1], 16;" :: "r"(dst), "l"(src))
#define CPC()  asm volatile("cp.async.commit_group;")
#define CPW(n) asm volatile("cp.async.wait_group %0;" :: "n"(n))

__device__ __forceinline__ void mma_f16(float* c, const unsigned* a, const unsigned* b) {
    asm volatile("mma.sync.aligned.m16n8k16.row.col.f32.f16.f16.f32 "
        "{%0,%1,%2,%3}, {%4,%5,%6,%7}, {%8,%9}, {%0,%1,%2,%3};"
        : "+f"(c[0]), "+f"(c[1]), "+f"(c[2]), "+f"(c[3])
        : "r"(a[0]), "r"(a[1]), "r"(a[2]), "r"(a[3]), "r"(b[0]), "r"(b[1]));
}
__device__ __forceinline__ void ldm4(unsigned* r, uint32_t a) {
    asm volatile("ldmatrix.sync.aligned.m8n8.x4.shared.b16 {%0,%1,%2,%3}, [%4];"
        : "=r"(r[0]), "=r"(r[1]), "=r"(r[2]), "=r"(r[3]) : "r"(a));
}
__device__ __forceinline__ void ldm4t(unsigned* r, uint32_t a) {
    asm volatile("ldmatrix.sync.aligned.m8n8.x4.trans.shared.b16 {%0,%1,%2,%3}, [%4];"
        : "=r"(r[0]), "=r"(r[1]), "=r"(r[2]), "=r"(r[3]) : "r"(a));
}
__device__ __forceinline__ unsigned packh2(float a, float b) {
    __half2 hv = __floats2half2_rn(a, b);
    return *(unsigned*)&hv;
}
__device__ __forceinline__ unsigned h2ex2(unsigned x) {
    unsigned y;
    asm("ex2.approx.f16x2 %0, %1;" : "=r"(y) : "r"(x));
    return y;
}

// ---------------- fused k1: pack bitmasks + split_x + weight transpose --------
__global__ void prep1(const float* __restrict__ adj, const float* __restrict__ dist,
                      const float* __restrict__ x,
                      const float* __restrict__ wq, const float* __restrict__ wp) {
    unsigned bid = blockIdx.x;
    if (bid < 32768u) {
        unsigned e = bid * 256u + threadIdx.x;
        unsigned j = e & (L_ - 1u), i = (e >> 10) & (L_ - 1u);
        bool ab = (adj[e] != 0.0f) && (i != 0u) && (j != 0u);
        unsigned aw = __ballot_sync(0xffffffffu, ab);
        unsigned dw = __ballot_sync(0xffffffffu, dist[e] > 0.0f);
        if ((threadIdx.x & 31u) == 0u) { g_adjbits[e >> 5] = aw; g_distbits[e >> 5] = dw; }
    } else if (bid < 49152u) {
        unsigned i = (bid - 32768u) * 256u + threadIdx.x;
        g_xh[i] = __float2half_rn(x[i]);
    } else {
        __shared__ float tile[32][33];
        int wb = bid - 49152;
        const float* src; __half* dh; int N;
        if (wb < 768) { src = wq; dh = g_wqT; N = 1536; }
        else          { wb -= 768; src = wp; dh = g_wpT; N = 512; }
        int tn = N >> 5;
        int k0 = (wb / tn) * 32, n0 = (wb % tn) * 32;
        int c = threadIdx.x & 31, r0 = threadIdx.x >> 5;
#pragma unroll
        for (int p = 0; p < 4; p++) {
            int r = r0 + p * 8;
            tile[r][c] = src[(size_t)(k0 + r) * N + n0 + c];
        }
        __syncthreads();
#pragma unroll
        for (int p = 0; p < 4; p++) {
            int r = r0 + p * 8;
            dh[(size_t)(n0 + r) * 512 + k0 + c] = __float2half_rn(tile[c][r]);
        }
    }
}

// ---------------- k2: 5-bit mask (side stream, overlaps qkv) ------------------
__global__ void mask_kernel() {
    const int b = blockIdx.z, i0 = blockIdx.y * 32, j0 = blockIdx.x * 32;
    __shared__ unsigned Ai[32][33], Aj[32][33];
    const int t = threadIdx.x;
#pragma unroll
    for (int k = 0; k < 4; k++) {
        int pos = t + k * 256, r = pos >> 5, w = pos & 31;
        Ai[r][w] = g_adjbits[((b << 10) + i0 + r) * 32 + w];
        Aj[r][w] = g_adjbits[((b << 10) + j0 + r) * 32 + w];
    }
    __syncthreads();
    const int il = t >> 3, jb = (t & 7) << 2, ig = i0 + il;
    const unsigned di = g_distbits[((b << 10) + ig) * 32 + (j0 >> 5)];
    unsigned sbits = 0u;
    for (int w = 0; w < 32; w++) {
        unsigned ai = Ai[il][w];
#pragma unroll
        for (int jj = 0; jj < 4; jj++)
            if (ai & Aj[jb + jj][w]) sbits |= (1u << jj);
        if (sbits == 0xFu) break;
    }
    unsigned word = 0u;
#pragma unroll
    for (int jj = 0; jj < 4; jj++) {
        int jl = jb + jj;
        unsigned fwd = (Ai[il][j0 >> 5] >> jl) & 1u;
        unsigned bwd = (Aj[jl][i0 >> 5] >> il) & 1u;
        unsigned dfw = (di >> jl) & 1u;
        unsigned dbw = (g_distbits[((b << 10) + j0 + jl) * 32 + (i0 >> 5)] >> il) & 1u;
        unsigned st = (sbits >> jj) & 1u;
        word |= (fwd | (bwd << 1) | (dfw << 2) | (dbw << 3) | (st << 4)) << (8 * jj);
    }
    *reinterpret_cast<unsigned*>(g_mask + (((size_t)((b << 10) + ig)) << 10) + j0 + jb) = word;
}

// ---------------- fp16 GEMM: 128x128 CTA tile, K=512, 3-stage -----------------
#define GDYN (98304 + 1024)
__global__ void __launch_bounds__(256) mm_kernel(int mode, float* __restrict__ out) {
    extern __shared__ char raw[];
    uint32_t rb = smem_u32(raw);
    char* sm = raw + ((1024u - (rb & 1023u)) & 1023u);
    const uint32_t sb = smem_u32(sm);
    const int t = threadIdx.x, lane = t & 31, wid = t >> 5;
    const int wm = wid & 3, wn = wid >> 2;
    const int n0 = blockIdx.x * 128, m0 = blockIdx.y * 128;

    const __half *Ah, *Bh;
    if (mode == 0) { Ah = g_xh;  Bh = g_wqT; }
    else           { Ah = g_aoh; Bh = g_wpT; }

    float C[2][8][4];
#pragma unroll
    for (int m = 0; m < 2; m++)
#pragma unroll
        for (int f = 0; f < 8; f++)
#pragma unroll
            for (int c = 0; c < 4; c++) C[m][f][c] = 0.0f;

    const int a_row = wm * 32 + (lane & 15);
    const int a_k   = (lane >> 4) * 8;
    const int b_row = wn * 64 + ((lane >> 4) << 3) + (lane & 7);
    const int b_k   = ((lane >> 3) & 1) * 8;

    auto pf = [&](int kc, uint32_t stb) {
#pragma unroll
        for (int i = 0; i < 4; i++) {
            int pos = t + i * 256, row = pos >> 3, cs = pos & 7;
            unsigned off = SW128((unsigned)(row * 128 + cs * 16));
            size_t ga = (size_t)(m0 + row) * 512 + kc * 64 + cs * 8;
            size_t gb = (size_t)(n0 + row) * 512 + kc * 64 + cs * 8;
            CPA(stb + off,         Ah + ga);
            CPA(stb + 16384 + off, Bh + gb);
        }
    };
    pf(0, sb); CPC();
    pf(1, sb + 32768u); CPC();

    for (int kc = 0; kc < 8; kc++) {
        if (kc < 7) CPW(1); else CPW(0);
        __syncthreads();
        if (kc < 6) { pf(kc + 2, sb + (unsigned)((kc + 2) % 3) * 32768u); CPC(); }
        const uint32_t base = sb + (unsigned)(kc % 3) * 32768u;
#pragma unroll
        for (int ks = 0; ks < 4; ks++) {
            unsigned ah[2][4];
#pragma unroll
            for (int mf = 0; mf < 2; mf++) {
                unsigned off = SW128((unsigned)((a_row + mf * 16) * 128 + (a_k + ks * 16) * 2));
                ldm4(ah[mf], base + off);
            }
#pragma unroll
            for (int nf4 = 0; nf4 < 4; nf4++) {
                unsigned off = SW128((unsigned)((b_row + nf4 * 16) * 128 + (b_k + ks * 16) * 2));
                unsigned bh[4];
                ldm4(bh, base + 16384 + off);
#pragma unroll
                for (int mf = 0; mf < 2; mf++) {
                    mma_f16(C[mf][2 * nf4], ah[mf], bh);
                    mma_f16(C[mf][2 * nf4 + 1], ah[mf], bh + 2);
                }
            }
        }
    }

    const int rq = lane >> 2, q2 = 2 * (lane & 3);
    if (mode == 1) {
#pragma unroll
        for (int mf = 0; mf < 2; mf++)
#pragma unroll
            for (int f = 0; f < 8; f++) {
                int row = m0 + wm * 32 + mf * 16 + rq;
                int col = n0 + wn * 64 + f * 8 + q2;
                float2 v0; v0.x = C[mf][f][0]; v0.y = C[mf][f][1];
                float2 v1; v1.x = C[mf][f][2]; v1.y = C[mf][f][3];
                *(float2*)(out + (size_t)row * 512 + col) = v0;
                *(float2*)(out + (size_t)(row + 8) * 512 + col) = v1;
            }
    } else {
        int part = n0 >> 9;
        int h = ((n0 + wn * 64) >> 6) & 7;
        __half* dst = (part == 0) ? g_qh : (part == 1) ? g_kh : g_vh;
        float sc = (part == 0) ? 0.125f * 1.44269504f : 1.0f;
        int bb = m0 >> 10, lbase = (m0 & 1023) + wm * 32;
#pragma unroll
        for (int mf = 0; mf < 2; mf++)
#pragma unroll
            for (int f = 0; f < 8; f++) {
                int ll = lbase + mf * 16 + rq;
                size_t base = ((size_t)(bb * 8 + h) * 1024 + ll) * 64 + f * 8 + q2;
                *(unsigned*)(dst + base)          = packh2(C[mf][f][0] * sc, C[mf][f][1] * sc);
                *(unsigned*)(dst + base + 8 * 64) = packh2(C[mf][f][2] * sc, C[mf][f][3] * sc);
            }
    }
}

// ---------------- attention: 128 thr / 64 q-rows, 4 CTAs/SM, 2-stage ----------
// group-ahead S pipeline + hoisted SW128 offsets
// stage s at s*21504: Kh 0, Vh 8192, Mask 16384 (64 rows x 80B)
#define ASTG 21504
#define ADYN (2*ASTG + 1024)
__global__ void __launch_bounds__(128, 4) attn_mma(const float* __restrict__ gamma) {
    extern __shared__ char raw[];
    uint32_t rb = smem_u32(raw);
    char* sm = raw + ((1024u - (rb & 1023u)) & 1023u);
    const uint32_t sb = smem_u32(sm);
    const int t = threadIdx.x, lane = t & 31, wid = t >> 5;   // 4 warps
    const int b = blockIdx.z, h = blockIdx.y, i0 = blockIdx.x * 64;
    const int bh = b * H_ + h;
    const int rq = lane >> 2, q2 = 2 * (lane & 3);

    // per-lane bias table, base-2 domain, minus fixed softmax offset C=4
    float tv = 0.0f;
#pragma unroll
    for (int kk = 0; kk < 5; kk++)
        if ((lane >> kk) & 1) tv += gamma[h * 5 + kk];
    tv = tv * 1.44269504f - 4.0f;

    // stage Q (64x64 fp16) into stage0 KV region, build A-fragments
#pragma unroll
    for (int i = 0; i < 4; i++) {
        int pos = t + i * 128, row = pos >> 3, cs = pos & 7;
        unsigned off = SW128((unsigned)(row * 128 + cs * 16));
        size_t g = ((size_t)bh * L_ + i0 + row) * 64 + cs * 8;
        *(uint4*)(sm + off) = *(const uint4*)(g_qh + g);
    }
    __syncthreads();
    unsigned qh[4][4];
    {
        int arow = wid * 16 + (lane & 15);
        int ak = (lane >> 4) * 8;
#pragma unroll
        for (int ks = 0; ks < 4; ks++) {
            unsigned off = SW128((unsigned)(arow * 128 + (ak + ks * 16) * 2));
            ldm4(qh[ks], sb + off);
        }
    }
    __syncthreads();

    const unsigned char* mbase = g_mask + ((size_t)b << 20) + (size_t)i0 * 1024;

    auto pf = [&](int jtile, uint32_t stb) {
        int j0 = jtile * 64;
#pragma unroll
        for (int i = 0; i < 4; i++) {
            int pos = t + i * 128, row = pos >> 3, cs = pos & 7;
            unsigned off = SW128((unsigned)(row * 128 + cs * 16));
            size_t g = ((size_t)bh * L_ + j0 + row) * 64 + cs * 8;
            CPA(stb + off,        g_kh + g);
            CPA(stb + 8192 + off, g_vh + g);
            if (i < 2) {
                int mrow = pos >> 2, mcs = pos & 3;
                CPA(stb + 16384u + (unsigned)(mrow * 80 + mcs * 16),
                    mbase + (size_t)mrow * 1024 + j0 + mcs * 16);
            }
        }
    };
    pf(0, sb); CPC();

    float O[8][4];
#pragma unroll
    for (int f = 0; f < 8; f++)
#pragma unroll
        for (int c = 0; c < 4; c++) O[f][c] = 0.0f;
    float OL[4] = {0.0f, 0.0f, 0.0f, 0.0f};

    const unsigned onesb[2] = { 0x3C003C00u, 0x3C003C00u };

    const int mrow0 = (wid * 16 + rq) * 80;
    const int mrow1 = mrow0 + 8 * 80;

    // hoisted SW128 offsets: row steps of 16 are ≡0 mod 8 so swizzle commutes
    // K addr(g, ks) = base + koff[ks] + g*2048 ;  V addr(g, nf4) = base+8192 + voff[nf4] + g*2048
    const int kb_row = ((lane >> 4) << 3) + (lane & 7);
    const int kb_k   = ((lane >> 3) & 1) * 8;
    const int vb_j   = ((lane >> 3) & 1) * 8 + (lane & 7);
    const int vb_d   = (lane >> 4) * 8;
    unsigned koff[4], voff[4];
#pragma unroll
    for (int ks = 0; ks < 4; ks++)
        koff[ks] = SW128((unsigned)(kb_row * 128 + (kb_k + ks * 16) * 2));
#pragma unroll
    for (int nf4 = 0; nf4 < 4; nf4++)
        voff[nf4] = SW128((unsigned)(vb_j * 128 + (vb_d + nf4 * 16) * 2));

    for (int jt = 0; jt < 16; jt++) {
        CPW(0);
        __syncthreads();
        if (jt < 15) { pf(jt + 1, sb + (unsigned)((jt + 1) & 1) * ASTG); CPC(); }
        const uint32_t base = sb + (unsigned)(jt & 1) * ASTG;
        const char* msm = sm + (size_t)(jt & 1) * ASTG + 16384;

        // group-ahead pipeline: S(g+1) issued before softmax(g) so the tensor
        // pipe stays fed while the ALU/MUFU softmax chain runs.
        float Sb[2][8];
#pragma unroll
        for (int c = 0; c < 8; c++) Sb[0][c] = 0.0f;
#pragma unroll
        for (int ks = 0; ks < 4; ks++) {
            unsigned bhf[4];
            ldm4(bhf, base + koff[ks]);
            mma_f16(Sb[0], qh[ks], bhf);
            mma_f16(Sb[0] + 4, qh[ks], bhf + 2);
        }
#pragma unroll
        for (int g = 0; g < 4; g++) {
            if (g < 3) {
                float* Sn = Sb[(g + 1) & 1];
#pragma unroll
                for (int c = 0; c < 8; c++) Sn[c] = 0.0f;
                unsigned gro = (unsigned)((g + 1) << 11);
#pragma unroll
                for (int ks = 0; ks < 4; ks++) {
                    unsigned bhf[4];
                    ldm4(bhf, base + koff[ks] + gro);
                    mma_f16(Sn, qh[ks], bhf);
                    mma_f16(Sn + 4, qh[ks], bhf + 2);
                }
            }
            const float* Sc = Sb[g & 1];
            int cb0 = (2 * g) * 8 + q2, cb1 = cb0 + 8;
            unsigned short a0 = *(const unsigned short*)(msm + mrow0 + cb0);
            unsigned short a1 = *(const unsigned short*)(msm + mrow1 + cb0);
            unsigned short b0 = *(const unsigned short*)(msm + mrow0 + cb1);
            unsigned short b1 = *(const unsigned short*)(msm + mrow1 + cb1);
            float e0 = Sc[0] + __shfl_sync(0xffffffffu, tv, a0 & 31u);
            float e1 = Sc[1] + __shfl_sync(0xffffffffu, tv, (a0 >> 8) & 31u);
            float e2 = Sc[2] + __shfl_sync(0xffffffffu, tv, a1 & 31u);
            float e3 = Sc[3] + __shfl_sync(0xffffffffu, tv, (a1 >> 8) & 31u);
            float f0 = Sc[4] + __shfl_sync(0xffffffffu, tv, b0 & 31u);
            float f1 = Sc[5] + __shfl_sync(0xffffffffu, tv, (b0 >> 8) & 31u);
            float f2 = Sc[6] + __shfl_sync(0xffffffffu, tv, b1 & 31u);
            float f3 = Sc[7] + __shfl_sync(0xffffffffu, tv, (b1 >> 8) & 31u);
            unsigned ah[4];
            ah[0] = h2ex2(packh2(e0, e1));
            ah[1] = h2ex2(packh2(e2, e3));
            ah[2] = h2ex2(packh2(f0, f1));
            ah[3] = h2ex2(packh2(f2, f3));
            mma_f16(OL, ah, onesb);
            unsigned gro = (unsigned)(g << 11);
#pragma unroll
            for (int nf4 = 0; nf4 < 4; nf4++) {
                unsigned bvh[4];
                ldm4t(bvh, base + 8192u + voff[nf4] + gro);
                mma_f16(O[2 * nf4], ah, bvh);
                mma_f16(O[2 * nf4 + 1], ah, bvh + 2);
            }
        }
    }

    // epilogue
    float inv0 = 1.0f / OL[0], inv1 = 1.0f / OL[2];
    const int ig0 = i0 + wid * 16 + rq;
    size_t base0 = ((size_t)(b << 10) + ig0) * 512 + h * 64;
    size_t base1 = base0 + 8 * 512;
#pragma unroll
    for (int f = 0; f < 8; f++) {
        *(unsigned*)(g_aoh + base0 + f * 8 + q2) = packh2(O[f][0] * inv0, O[f][1] * inv0);
        *(unsigned*)(g_aoh + base1 + f * 8 + q2) = packh2(O[f][2] * inv1, O[f][3] * inv1);
    }
}

// ---------------- launch --------------------------------------------------------
extern "C" void kernel_launch(void* const* d_in, const int* in_sizes, int n_in,
                              void* d_out, int out_size) {
    const float* x      = (const float*)d_in[0];
    const float* adj    = (const float*)d_in[1];
    const float* dist   = (const float*)d_in[2];
    const float* w_qkv  = (const float*)d_in[3];
    const float* w_proj = (const float*)d_in[4];
    const float* gamma  = (const float*)d_in[5];
    float* out = (float*)d_out;

    cudaFuncSetAttribute(mm_kernel, cudaFuncAttributeMaxDynamicSharedMemorySize, GDYN);
    cudaFuncSetAttribute(attn_mma, cudaFuncAttributeMaxDynamicSharedMemorySize, ADYN);

    cudaStream_t ms = cudaStreamPerThread;

    prep1<<<32768 + 16384 + 1024, 256, 0, ms>>>(adj, dist, x, w_qkv, w_proj);

    // fork: mask on side stream, overlapped with qkv GEMM
    cudaEventRecord(g_aux.fork, ms);
    cudaStreamWaitEvent(g_aux.s, g_aux.fork, 0);
    mask_kernel<<<dim3(32, 32, B_), 256, 0, g_aux.s>>>();
    cudaEventRecord(g_aux.join, g_aux.s);

    mm_kernel<<<dim3(12, 64), 256, GDYN, ms>>>(0, nullptr);   // qkv

    cudaStreamWaitEvent(ms, g_aux.join, 0);
    attn_mma<<<dim3(L_ / 64, H_, B_), 128, ADYN, ms>>>(gamma);
    mm_kernel<<<dim3(4, 64), 256, GDYN, ms>>>(1, out);        // proj
}

// round 17
// speedup vs baseline: 6.9494x; 1.1360x over previous
#include <cuda_runtime.h>
#include <cuda_fp16.h>
#include <cstdint>

#define B_ 8
#define L_ 1024
#define C_ 512
#define H_ 8
#define D_ 64
#define M_TOT (B_*L_)

// ---------------- static device scratch -------------------------------------
__device__ unsigned g_adjbits[B_*L_*(L_/32)];
__device__ unsigned g_distbits[B_*L_*(L_/32)];
// permuted 5-bit mask: [b][iblk64][jt64] -> 4096B tile of 8B units
// unit (wid,g,rq,q2p): {a0,b0,a1,b1} ushorts (rows rq/rq+8, col pairs q2/q2+8)
__device__ unsigned char g_maskP[(size_t)B_*16*16*4096];

__device__ __half g_xh[M_TOT*C_];
__device__ __half g_wqT[3*C_*C_];   // [1536][512] fp16
__device__ __half g_wpT[C_*C_];     // [512][512]  fp16
__device__ __half g_qh[B_*H_*L_*D_];  // pre-scaled (1/8)*log2e
__device__ __half g_kh[B_*H_*L_*D_];
__device__ __half g_vh[B_*H_*L_*D_];
__device__ __half g_aoh[M_TOT*C_];

// ---------------- host-side stream fork (static init; no device mem) ---------
namespace {
struct AuxStream {
    cudaStream_t s = nullptr;
    cudaEvent_t fork = nullptr, join = nullptr;
    AuxStream() {
        cudaStreamCreateWithFlags(&s, cudaStreamNonBlocking);
        cudaEventCreateWithFlags(&fork, cudaEventDisableTiming);
        cudaEventCreateWithFlags(&join, cudaEventDisableTiming);
    }
};
AuxStream g_aux;
}

// ---------------- device helpers ----------------------------------------------
__device__ __forceinline__ uint32_t smem_u32(const void* p) {
    uint32_t a;
    asm("{ .reg .u64 t; cvta.to.shared.u64 t, %1; cvt.u32.u64 %0, t; }" : "=r"(a) : "l"(p));
    return a;
}
#define SW128(o) ((o) ^ (((o) >> 3) & 0x70))

#define CPA(dst, src) asm volatile("cp.async.cg.shared.global [%0], [%1], 16;" :: "r"(dst), "l"(src))
#define CPC()  asm volatile("cp.async.commit_group;")
#define CPW(n) asm volatile("cp.async.wait_group %0;" :: "n"(n))

__device__ __forceinline__ void mma_f16(float* c, const unsigned* a, const unsigned* b) {
    asm volatile("mma.sync.aligned.m16n8k16.row.col.f32.f16.f16.f32 "
        "{%0,%1,%2,%3}, {%4,%5,%6,%7}, {%8,%9}, {%0,%1,%2,%3};"
        : "+f"(c[0]), "+f"(c[1]), "+f"(c[2]), "+f"(c[3])
        : "r"(a[0]), "r"(a[1]), "r"(a[2]), "r"(a[3]), "r"(b[0]), "r"(b[1]));
}
__device__ __forceinline__ void ldm4(unsigned* r, uint32_t a) {
    asm volatile("ldmatrix.sync.aligned.m8n8.x4.shared.b16 {%0,%1,%2,%3}, [%4];"
        : "=r"(r[0]), "=r"(r[1]), "=r"(r[2]), "=r"(r[3]) : "r"(a));
}
__device__ __forceinline__ void ldm4t(unsigned* r, uint32_t a) {
    asm volatile("ldmatrix.sync.aligned.m8n8.x4.trans.shared.b16 {%0,%1,%2,%3}, [%4];"
        : "=r"(r[0]), "=r"(r[1]), "=r"(r[2]), "=r"(r[3]) : "r"(a));
}
__device__ __forceinline__ unsigned packh2(float a, float b) {
    __half2 hv = __floats2half2_rn(a, b);
    return *(unsigned*)&hv;
}
__device__ __forceinline__ unsigned h2ex2(unsigned x) {
    unsigned y;
    asm("ex2.approx.f16x2 %0, %1;" : "=r"(y) : "r"(x));
    return y;
}

// ---------------- fused k1: pack (vectorized) + split_x (vec) + w transpose ---
__global__ void prep1(const float* __restrict__ adj, const float* __restrict__ dist,
                      const float* __restrict__ x,
                      const float* __restrict__ wq, const float* __restrict__ wp) {
    unsigned bid = blockIdx.x;
    const int t = threadIdx.x, lane = t & 31, w = t >> 5;
    if (bid < 4096u) {
        // pack: block covers 2048 elements; warp covers 256 (2 passes of 128)
        size_t ebase = (size_t)bid * 2048 + (size_t)w * 256 + (size_t)(lane * 4);
#pragma unroll
        for (int pass = 0; pass < 2; pass++) {
            size_t e = ebase + pass * 128;
            float4 a4 = *(const float4*)(adj + e);
            float4 d4 = *(const float4*)(dist + e);
            unsigned i = ((unsigned)(e >> 10)) & 1023u;
            unsigned j = ((unsigned)e) & 1023u;
            bool rz = (i != 0u);
            unsigned na = 0u, nd = 0u;
            if (a4.x != 0.0f && rz && j != 0u) na |= 1u;
            if (a4.y != 0.0f && rz) na |= 2u;
            if (a4.z != 0.0f && rz) na |= 4u;
            if (a4.w != 0.0f && rz) na |= 8u;
            if (d4.x > 0.0f) nd |= 1u;
            if (d4.y > 0.0f) nd |= 2u;
            if (d4.z > 0.0f) nd |= 4u;
            if (d4.w > 0.0f) nd |= 8u;
            unsigned sh = 4u * (unsigned)(lane & 7);
            unsigned va = na << sh, vd = nd << sh;
#pragma unroll
            for (int o = 1; o < 8; o <<= 1) {
                va |= __shfl_xor_sync(0xffffffffu, va, o);
                vd |= __shfl_xor_sync(0xffffffffu, vd, o);
            }
            if ((lane & 7) == 0) {
                g_adjbits[e >> 5] = va;
                g_distbits[e >> 5] = vd;
            }
        }
    } else if (bid < 8192u) {
        size_t i = (size_t)(bid - 4096u) * 1024 + (size_t)(t * 4);
        float4 v = *(const float4*)(x + i);
        uint2 st;
        st.x = packh2(v.x, v.y);
        st.y = packh2(v.z, v.w);
        *(uint2*)(g_xh + i) = st;
    } else {
        __shared__ float tile[32][33];
        int wb = bid - 8192;
        const float* src; __half* dh; int N;
        if (wb < 768) { src = wq; dh = g_wqT; N = 1536; }
        else          { wb -= 768; src = wp; dh = g_wpT; N = 512; }
        int tn = N >> 5;
        int k0 = (wb / tn) * 32, n0 = (wb % tn) * 32;
        int c = t & 31, r0 = t >> 5;
#pragma unroll
        for (int p = 0; p < 4; p++) {
            int r = r0 + p * 8;
            tile[r][c] = src[(size_t)(k0 + r) * N + n0 + c];
        }
        __syncthreads();
#pragma unroll
        for (int p = 0; p < 4; p++) {
            int r = r0 + p * 8;
            dh[(size_t)(n0 + r) * 512 + k0 + c] = __float2half_rn(tile[c][r]);
        }
    }
}

// ---------------- k2: 5-bit mask -> permuted layout (side stream) -------------
__global__ void mask_kernel() {
    const int b = blockIdx.z, i0 = blockIdx.y * 32, j0 = blockIdx.x * 32;
    __shared__ unsigned Ai[32][33], Aj[32][33];
    const int t = threadIdx.x;
#pragma unroll
    for (int k = 0; k < 4; k++) {
        int pos = t + k * 256, r = pos >> 5, w = pos & 31;
        Ai[r][w] = g_adjbits[((b << 10) + i0 + r) * 32 + w];
        Aj[r][w] = g_adjbits[((b << 10) + j0 + r) * 32 + w];
    }
    __syncthreads();
    const int il = t >> 3, jb = (t & 7) << 2, ig = i0 + il;
    const unsigned di = g_distbits[((b << 10) + ig) * 32 + (j0 >> 5)];
    unsigned sbits = 0u;
    for (int w = 0; w < 32; w++) {
        unsigned ai = Ai[il][w];
#pragma unroll
        for (int jj = 0; jj < 4; jj++)
            if (ai & Aj[jb + jj][w]) sbits |= (1u << jj);
        if (sbits == 0xFu) break;
    }
    unsigned word = 0u;
#pragma unroll
    for (int jj = 0; jj < 4; jj++) {
        int jl = jb + jj;
        unsigned fwd = (Ai[il][j0 >> 5] >> jl) & 1u;
        unsigned bwd = (Aj[jl][i0 >> 5] >> il) & 1u;
        unsigned dfw = (di >> jl) & 1u;
        unsigned dbw = (g_distbits[((b << 10) + j0 + jl) * 32 + (i0 >> 5)] >> il) & 1u;
        unsigned st = (sbits >> jj) & 1u;
        word |= (fwd | (bwd << 1) | (dfw << 2) | (dbw << 3) | (st << 4)) << (8 * jj);
    }
    // permuted store: unit = 8B {a0,b0,a1,b1} for (rowpair, colquad)
    unsigned jc0 = (unsigned)(j0 + jb);
    unsigned iblk = (unsigned)ig >> 6, wid = ((unsigned)ig >> 4) & 3u;
    unsigned half_r = ((unsigned)ig >> 3) & 1u, rqv = (unsigned)ig & 7u;
    unsigned jt = jc0 >> 6, gg = (jc0 >> 4) & 3u, half_c = (jc0 >> 3) & 1u;
    unsigned q2p = (jc0 >> 1) & 3u;
    size_t ubase = ((((size_t)b * 16 + iblk) * 16 + jt) << 12)
                 + (size_t)(((wid * 4 + gg) * 8 + rqv) * 32 + half_r * 4 + half_c * 2);
    *(unsigned short*)(g_maskP + ubase + q2p * 8)       = (unsigned short)(word & 0xFFFFu);
    *(unsigned short*)(g_maskP + ubase + (q2p + 1) * 8) = (unsigned short)(word >> 16);
}

// ---------------- fp16 GEMM: 128x128 CTA tile, K=512, 3-stage -----------------
#define GDYN (98304 + 1024)
__global__ void __launch_bounds__(256) mm_kernel(int mode, float* __restrict__ out) {
    extern __shared__ char raw[];
    uint32_t rb = smem_u32(raw);
    char* sm = raw + ((1024u - (rb & 1023u)) & 1023u);
    const uint32_t sb = smem_u32(sm);
    const int t = threadIdx.x, lane = t & 31, wid = t >> 5;
    const int wm = wid & 3, wn = wid >> 2;
    const int n0 = blockIdx.x * 128, m0 = blockIdx.y * 128;

    const __half *Ah, *Bh;
    if (mode == 0) { Ah = g_xh;  Bh = g_wqT; }
    else           { Ah = g_aoh; Bh = g_wpT; }

    float C[2][8][4];
#pragma unroll
    for (int m = 0; m < 2; m++)
#pragma unroll
        for (int f = 0; f < 8; f++)
#pragma unroll
            for (int c = 0; c < 4; c++) C[m][f][c] = 0.0f;

    const int a_row = wm * 32 + (lane & 15);
    const int a_k   = (lane >> 4) * 8;
    const int b_row = wn * 64 + ((lane >> 4) << 3) + (lane & 7);
    const int b_k   = ((lane >> 3) & 1) * 8;

    auto pf = [&](int kc, uint32_t stb) {
#pragma unroll
        for (int i = 0; i < 4; i++) {
            int pos = t + i * 256, row = pos >> 3, cs = pos & 7;
            unsigned off = SW128((unsigned)(row * 128 + cs * 16));
            size_t ga = (size_t)(m0 + row) * 512 + kc * 64 + cs * 8;
            size_t gb = (size_t)(n0 + row) * 512 + kc * 64 + cs * 8;
            CPA(stb + off,         Ah + ga);
            CPA(stb + 16384 + off, Bh + gb);
        }
    };
    pf(0, sb); CPC();
    pf(1, sb + 32768u); CPC();

    for (int kc = 0; kc < 8; kc++) {
        if (kc < 7) CPW(1); else CPW(0);
        __syncthreads();
        if (kc < 6) { pf(kc + 2, sb + (unsigned)((kc + 2) % 3) * 32768u); CPC(); }
        const uint32_t base = sb + (unsigned)(kc % 3) * 32768u;
#pragma unroll
        for (int ks = 0; ks < 4; ks++) {
            unsigned ah[2][4];
#pragma unroll
            for (int mf = 0; mf < 2; mf++) {
                unsigned off = SW128((unsigned)((a_row + mf * 16) * 128 + (a_k + ks * 16) * 2));
                ldm4(ah[mf], base + off);
            }
#pragma unroll
            for (int nf4 = 0; nf4 < 4; nf4++) {
                unsigned off = SW128((unsigned)((b_row + nf4 * 16) * 128 + (b_k + ks * 16) * 2));
                unsigned bh[4];
                ldm4(bh, base + 16384 + off);
#pragma unroll
                for (int mf = 0; mf < 2; mf++) {
                    mma_f16(C[mf][2 * nf4], ah[mf], bh);
                    mma_f16(C[mf][2 * nf4 + 1], ah[mf], bh + 2);
                }
            }
        }
    }

    const int rq = lane >> 2, q2 = 2 * (lane & 3);
    if (mode == 1) {
#pragma unroll
        for (int mf = 0; mf < 2; mf++)
#pragma unroll
            for (int f = 0; f < 8; f++) {
                int row = m0 + wm * 32 + mf * 16 + rq;
                int col = n0 + wn * 64 + f * 8 + q2;
                float2 v0; v0.x = C[mf][f][0]; v0.y = C[mf][f][1];
                float2 v1; v1.x = C[mf][f][2]; v1.y = C[mf][f][3];
                *(float2*)(out + (size_t)row * 512 + col) = v0;
                *(float2*)(out + (size_t)(row + 8) * 512 + col) = v1;
            }
    } else {
        int part = n0 >> 9;
        int h = ((n0 + wn * 64) >> 6) & 7;
        __half* dst = (part == 0) ? g_qh : (part == 1) ? g_kh : g_vh;
        float sc = (part == 0) ? 0.125f * 1.44269504f : 1.0f;
        int bb = m0 >> 10, lbase = (m0 & 1023) + wm * 32;
#pragma unroll
        for (int mf = 0; mf < 2; mf++)
#pragma unroll
            for (int f = 0; f < 8; f++) {
                int ll = lbase + mf * 16 + rq;
                size_t base = ((size_t)(bb * 8 + h) * 1024 + ll) * 64 + f * 8 + q2;
                *(unsigned*)(dst + base)          = packh2(C[mf][f][0] * sc, C[mf][f][1] * sc);
                *(unsigned*)(dst + base + 8 * 64) = packh2(C[mf][f][2] * sc, C[mf][f][3] * sc);
            }
    }
}

// ---------------- attention: 128 thr / 64 q-rows, 4 CTAs/SM, 2-stage ----------
// stage s at s*20480: Kh 0, Vh 8192, MaskP 16384 (4096B permuted tile)
#define ASTG 20480
#define ADYN (2*ASTG + 1024)
__global__ void __launch_bounds__(128, 4) attn_mma(const float* __restrict__ gamma) {
    extern __shared__ char raw[];
    uint32_t rb = smem_u32(raw);
    char* sm = raw + ((1024u - (rb & 1023u)) & 1023u);
    const uint32_t sb = smem_u32(sm);
    const int t = threadIdx.x, lane = t & 31, wid = t >> 5;   // 4 warps
    const int b = blockIdx.z, h = blockIdx.y, i0 = blockIdx.x * 64;
    const int bh = b * H_ + h;
    const int rq = lane >> 2, q2 = 2 * (lane & 3);

    float tv = 0.0f;
#pragma unroll
    for (int kk = 0; kk < 5; kk++)
        if ((lane >> kk) & 1) tv += gamma[h * 5 + kk];
    tv = tv * 1.44269504f - 4.0f;   // base-2 domain, fixed offset C=4

    // stage Q (64x64 fp16) into stage0 KV region, build A-fragments
#pragma unroll
    for (int i = 0; i < 4; i++) {
        int pos = t + i * 128, row = pos >> 3, cs = pos & 7;
        unsigned off = SW128((unsigned)(row * 128 + cs * 16));
        size_t g = ((size_t)bh * L_ + i0 + row) * 64 + cs * 8;
        *(uint4*)(sm + off) = *(const uint4*)(g_qh + g);
    }
    __syncthreads();
    unsigned qh[4][4];
    {
        int arow = wid * 16 + (lane & 15);
        int ak = (lane >> 4) * 8;
#pragma unroll
        for (int ks = 0; ks < 4; ks++) {
            unsigned off = SW128((unsigned)(arow * 128 + (ak + ks * 16) * 2));
            ldm4(qh[ks], sb + off);
        }
    }
    __syncthreads();

    const unsigned char* mPbase = g_maskP + ((((size_t)b * 16 + blockIdx.x) * 16) << 12);

    auto pf = [&](int jtile, uint32_t stb) {
        int j0 = jtile * 64;
        const unsigned char* mP = mPbase + ((size_t)jtile << 12);
#pragma unroll
        for (int i = 0; i < 4; i++) {
            int pos = t + i * 128, row = pos >> 3, cs = pos & 7;
            unsigned off = SW128((unsigned)(row * 128 + cs * 16));
            size_t g = ((size_t)bh * L_ + j0 + row) * 64 + cs * 8;
            CPA(stb + off,        g_kh + g);
            CPA(stb + 8192 + off, g_vh + g);
            if (i < 2) {
                int pm = t + i * 128;           // 0..255 chunks of 16B
                CPA(stb + 16384u + (unsigned)(pm * 16), mP + pm * 16);
            }
        }
    };
    pf(0, sb); CPC();

    float O[8][4];
#pragma unroll
    for (int f = 0; f < 8; f++)
#pragma unroll
        for (int c = 0; c < 4; c++) O[f][c] = 0.0f;
    float OL[4] = {0.0f, 0.0f, 0.0f, 0.0f};

    const unsigned onesb[2] = { 0x3C003C00u, 0x3C003C00u };

    // permuted mask: one LDS.64 per group; lanes read linearly (conflict-free)
    const unsigned moff = (unsigned)(wid * 1024 + rq * 32 + (lane & 3) * 8);

    const int kb_row = ((lane >> 4) << 3) + (lane & 7);
    const int kb_k   = ((lane >> 3) & 1) * 8;
    const int vb_j   = ((lane >> 3) & 1) * 8 + (lane & 7);
    const int vb_d   = (lane >> 4) * 8;
    unsigned koff[4], voff[4];
#pragma unroll
    for (int ks = 0; ks < 4; ks++)
        koff[ks] = SW128((unsigned)(kb_row * 128 + (kb_k + ks * 16) * 2));
#pragma unroll
    for (int nf4 = 0; nf4 < 4; nf4++)
        voff[nf4] = SW128((unsigned)(vb_j * 128 + (vb_d + nf4 * 16) * 2));

    for (int jt = 0; jt < 16; jt++) {
        CPW(0);
        __syncthreads();
        if (jt < 15) { pf(jt + 1, sb + (unsigned)((jt + 1) & 1) * ASTG); CPC(); }
        const uint32_t base = sb + (unsigned)(jt & 1) * ASTG;
        const char* msm = sm + (size_t)(jt & 1) * ASTG + 16384;

        // group-ahead pipeline: S(g+1) issued before softmax(g)
        float Sb[2][8];
#pragma unroll
        for (int c = 0; c < 8; c++) Sb[0][c] = 0.0f;
#pragma unroll
        for (int ks = 0; ks < 4; ks++) {
            unsigned bhf[4];
            ldm4(bhf, base + koff[ks]);
            mma_f16(Sb[0], qh[ks], bhf);
            mma_f16(Sb[0] + 4, qh[ks], bhf + 2);
        }
#pragma unroll
        for (int g = 0; g < 4; g++) {
            if (g < 3) {
                float* Sn = Sb[(g + 1) & 1];
#pragma unroll
                for (int c = 0; c < 8; c++) Sn[c] = 0.0f;
                unsigned gro = (unsigned)((g + 1) << 11);
#pragma unroll
                for (int ks = 0; ks < 4; ks++) {
                    unsigned bhf[4];
                    ldm4(bhf, base + koff[ks] + gro);
                    mma_f16(Sn, qh[ks], bhf);
                    mma_f16(Sn + 4, qh[ks], bhf + 2);
                }
            }
            const float* Sc = Sb[g & 1];
            uint2 mv = *(const uint2*)(msm + moff + (unsigned)(g << 8));
            float e0 = Sc[0] + __shfl_sync(0xffffffffu, tv, mv.x & 31u);
            float e1 = Sc[1] + __shfl_sync(0xffffffffu, tv, (mv.x >> 8) & 31u);
            float f0 = Sc[4] + __shfl_sync(0xffffffffu, tv, (mv.x >> 16) & 31u);
            float f1 = Sc[5] + __shfl_sync(0xffffffffu, tv, (mv.x >> 24) & 31u);
            float e2 = Sc[2] + __shfl_sync(0xffffffffu, tv, mv.y & 31u);
            float e3 = Sc[3] + __shfl_sync(0xffffffffu, tv, (mv.y >> 8) & 31u);
            float f2 = Sc[6] + __shfl_sync(0xffffffffu, tv, (mv.y >> 16) & 31u);
            float f3 = Sc[7] + __shfl_sync(0xffffffffu, tv, (mv.y >> 24) & 31u);
            unsigned ah[4];
            ah[0] = h2ex2(packh2(e0, e1));
            ah[1] = h2ex2(packh2(e2, e3));
            ah[2] = h2ex2(packh2(f0, f1));
            ah[3] = h2ex2(packh2(f2, f3));
            mma_f16(OL, ah, onesb);
            unsigned gro = (unsigned)(g << 11);
#pragma unroll
            for (int nf4 = 0; nf4 < 4; nf4++) {
                unsigned bvh[4];
                ldm4t(bvh, base + 8192u + voff[nf4] + gro);
                mma_f16(O[2 * nf4], ah, bvh);
                mma_f16(O[2 * nf4 + 1], ah, bvh + 2);
            }
        }
    }

    // epilogue
    float inv0 = 1.0f / OL[0], inv1 = 1.0f / OL[2];
    const int ig0 = i0 + wid * 16 + rq;
    size_t base0 = ((size_t)(b << 10) + ig0) * 512 + h * 64;
    size_t base1 = base0 + 8 * 512;
#pragma unroll
    for (int f = 0; f < 8; f++) {
        *(unsigned*)(g_aoh + base0 + f * 8 + q2) = packh2(O[f][0] * inv0, O[f][1] * inv0);
        *(unsigned*)(g_aoh + base1 + f * 8 + q2) = packh2(O[f][2] * inv1, O[f][3] * inv1);
    }
}

// ---------------- launch --------------------------------------------------------
extern "C" void kernel_launch(void* const* d_in, const int* in_sizes, int n_in,
                              void* d_out, int out_size) {
    const float* x      = (const float*)d_in[0];
    const float* adj    = (const float*)d_in[1];
    const float* dist   = (const float*)d_in[2];
    const float* w_qkv  = (const float*)d_in[3];
    const float* w_proj = (const float*)d_in[4];
    const float* gamma  = (const float*)d_in[5];
    float* out = (float*)d_out;

    cudaFuncSetAttribute(mm_kernel, cudaFuncAttributeMaxDynamicSharedMemorySize, GDYN);
    cudaFuncSetAttribute(attn_mma, cudaFuncAttributeMaxDynamicSharedMemorySize, ADYN);

    cudaStream_t ms = cudaStreamPerThread;

    prep1<<<4096 + 4096 + 1024, 256, 0, ms>>>(adj, dist, x, w_qkv, w_proj);

    // fork: mask on side stream, overlapped with qkv GEMM
    cudaEventRecord(g_aux.fork, ms);
    cudaStreamWaitEvent(g_aux.s, g_aux.fork, 0);
    mask_kernel<<<dim3(32, 32, B_), 256, 0, g_aux.s>>>();
    cudaEventRecord(g_aux.join, g_aux.s);

    mm_kernel<<<dim3(12, 64), 256, GDYN, ms>>>(0, nullptr);   // qkv

    cudaStreamWaitEvent(ms, g_aux.join, 0);
    attn_mma<<<dim3(L_ / 64, H_, B_), 128, ADYN, ms>>>(gamma);
    mm_kernel<<<dim3(4, 64), 256, GDYN, ms>>>(1, out);        // proj
}